// round 11
// baseline (speedup 1.0000x reference)
#include <cuda_runtime.h>
#include <cuda_bf16.h>
#include <cuda_fp16.h>
#include <math.h>
#include <stdint.h>

// ---------------- problem constants ----------------
#define BB 2
#define SS 1024
#define UU 1024
#define HH 16
#define DD 64
#define NT 32000
#define MEMLEN 576
#define FFD 4096
#define KLEN 1600   // MEM + S
#define VOCAB 1024

typedef __nv_bfloat16 bf16;

// ---------------- scratch (device globals; no allocation allowed) ----------------
__device__ float g_ac  [(size_t)BB*HH*SS*KLEN];
__device__ float g_ar  [(size_t)BB*HH*SS*KLEN];
__device__ float g_x   [(size_t)BB*SS*UU];
__device__ float g_tmp [(size_t)BB*SS*UU];
__device__ float g_h1  [(size_t)BB*SS*UU];

// fp16 A-side splits
__device__ __half g_xh   [(size_t)BB*SS*UU],   g_xl   [(size_t)BB*SS*UU];
__device__ __half g_fullh[(size_t)BB*KLEN*UU], g_fulll[(size_t)BB*KLEN*UU];
__device__ __half g_relh [(size_t)KLEN*UU],    g_rell [(size_t)KLEN*UU];
__device__ __half g_ctxh [(size_t)BB*SS*UU],   g_ctxl [(size_t)BB*SS*UU];
__device__ __half g_h1hh [(size_t)BB*SS*UU],   g_h1lh [(size_t)BB*SS*UU];
__device__ __half g_ffhh [(size_t)BB*SS*FFD],  g_fflh [(size_t)BB*SS*FFD];
__device__ __half g_h2hh [(size_t)BB*SS*UU],   g_h2lh [(size_t)BB*SS*UU];
// bf16 splits (attention internal path)
__device__ bf16 g_qch  [(size_t)BB*SS*UU],   g_qcl  [(size_t)BB*SS*UU];
__device__ bf16 g_qrh  [(size_t)BB*SS*UU],   g_qrl  [(size_t)BB*SS*UU];
__device__ bf16 g_kvh  [(size_t)BB*KLEN*2*UU], g_kvl [(size_t)BB*KLEN*2*UU];
__device__ bf16 g_rh   [(size_t)KLEN*UU],    g_rl   [(size_t)KLEN*UU];
__device__ bf16 g_ph   [(size_t)BB*HH*SS*KLEN], g_pl [(size_t)BB*HH*SS*KLEN];
__device__ bf16 g_vth  [(size_t)BB*HH*DD*KLEN], g_vtl[(size_t)BB*HH*DD*KLEN];
// single-fp16 transposed weights [N,K]
__device__ __half g_WqH [(size_t)UU*UU];
__device__ __half g_WkvH[(size_t)2*UU*UU];
__device__ __half g_WrH [(size_t)UU*UU];
__device__ __half g_WoH [(size_t)UU*UU];
__device__ __half g_W1H [(size_t)FFD*UU];
__device__ __half g_W2H [(size_t)UU*FFD];
__device__ __half g_WoutH[(size_t)NT*UU];

// ---------------- helpers ----------------
__device__ __forceinline__ uint32_t smem_u32(const void* p) {
    uint32_t a;
    asm("{ .reg .u64 t; cvta.to.shared.u64 t, %1; cvt.u32.u64 %0, t; }" : "=r"(a) : "l"(p));
    return a;
}
__device__ __forceinline__ void split_to(float v, bf16& h, bf16& l) {
    h = __float2bfloat16(v);
    l = __float2bfloat16(v - __bfloat162float(h));
}
__device__ __forceinline__ void split_to(float v, __half& h, __half& l) {
    h = __float2half(v);
    l = __float2half(v - __half2float(h));
}
template<typename T>
__device__ __forceinline__ uint32_t pack2(T a, T b) {
    unsigned short x = *(unsigned short*)&a, y = *(unsigned short*)&b;
    return (uint32_t)x | ((uint32_t)y << 16);
}
__device__ __forceinline__ void cp16(uint32_t dst, const void* src) {
    asm volatile("cp.async.cg.shared.global [%0], [%1], 16;" :: "r"(dst), "l"(src));
}
__device__ __forceinline__ void ldx4(uint32_t* r, uint32_t addr) {
    asm volatile("ldmatrix.sync.aligned.m8n8.x4.shared.b16 {%0,%1,%2,%3}, [%4];"
                 : "=r"(r[0]), "=r"(r[1]), "=r"(r[2]), "=r"(r[3]) : "r"(addr));
}
__device__ __forceinline__ void mma_bf(float* c, const uint32_t* a, const uint32_t* b) {
    asm volatile("mma.sync.aligned.m16n8k16.row.col.f32.bf16.bf16.f32 "
                 "{%0,%1,%2,%3}, {%4,%5,%6,%7}, {%8,%9}, {%0,%1,%2,%3};"
                 : "+f"(c[0]), "+f"(c[1]), "+f"(c[2]), "+f"(c[3])
                 : "r"(a[0]), "r"(a[1]), "r"(a[2]), "r"(a[3]), "r"(b[0]), "r"(b[1]));
}
__device__ __forceinline__ void mma_fp(float* c, const uint32_t* a, const uint32_t* b) {
    asm volatile("mma.sync.aligned.m16n8k16.row.col.f32.f16.f16.f32 "
                 "{%0,%1,%2,%3}, {%4,%5,%6,%7}, {%8,%9}, {%0,%1,%2,%3};"
                 : "+f"(c[0]), "+f"(c[1]), "+f"(c[2]), "+f"(c[3])
                 : "r"(a[0]), "r"(a[1]), "r"(a[2]), "r"(a[3]), "r"(b[0]), "r"(b[1]));
}

// shared epilogue writer
template<int OUT, typename ET>
__device__ __forceinline__ void epi_store(
    float v0, float v1, float v2, float v3,
    int gm0, int gn, int M, int ldc, long long cbase,
    float* C, ET* Ch, ET* Cl, ET* Dh, ET* Dl,
    const float* bias2, const float* bias3)
{
    if (OUT == 0) {
        if (gm0 < M) {
            float2 w; w.x = v0; w.y = v1;
            *(float2*)(C + cbase + (long long)gm0 * ldc + gn) = w;
        }
        if (gm0 + 8 < M) {
            float2 w; w.x = v2; w.y = v3;
            *(float2*)(C + cbase + (long long)(gm0 + 8) * ldc + gn) = w;
        }
    } else if (OUT == 3) {
        float2 b2 = *(const float2*)(bias2 + gn);
        float2 b3 = *(const float2*)(bias3 + gn);
        ET h0, l0, h1, l1;
        if (gm0 < M) {
            long long o = cbase + (long long)gm0 * ldc + gn;
            split_to(v0 + b2.x, h0, l0); split_to(v1 + b2.y, h1, l1);
            *(uint32_t*)(Ch + o) = pack2(h0, h1); *(uint32_t*)(Cl + o) = pack2(l0, l1);
            split_to(v0 + b3.x, h0, l0); split_to(v1 + b3.y, h1, l1);
            *(uint32_t*)(Dh + o) = pack2(h0, h1); *(uint32_t*)(Dl + o) = pack2(l0, l1);
        }
        if (gm0 + 8 < M) {
            long long o = cbase + (long long)(gm0 + 8) * ldc + gn;
            split_to(v2 + b2.x, h0, l0); split_to(v3 + b2.y, h1, l1);
            *(uint32_t*)(Ch + o) = pack2(h0, h1); *(uint32_t*)(Cl + o) = pack2(l0, l1);
            split_to(v2 + b3.x, h0, l0); split_to(v3 + b3.y, h1, l1);
            *(uint32_t*)(Dh + o) = pack2(h0, h1); *(uint32_t*)(Dl + o) = pack2(l0, l1);
        }
    } else {
        if (OUT == 2) {
            v0 = fmaxf(v0, 0.f); v1 = fmaxf(v1, 0.f);
            v2 = fmaxf(v2, 0.f); v3 = fmaxf(v3, 0.f);
        }
        ET h0, l0, h1, l1;
        if (gm0 < M) {
            long long o = cbase + (long long)gm0 * ldc + gn;
            split_to(v0, h0, l0); split_to(v1, h1, l1);
            *(uint32_t*)(Ch + o) = pack2(h0, h1); *(uint32_t*)(Cl + o) = pack2(l0, l1);
        }
        if (gm0 + 8 < M) {
            long long o = cbase + (long long)(gm0 + 8) * ldc + gn;
            split_to(v2, h0, l0); split_to(v3, h1, l1);
            *(uint32_t*)(Ch + o) = pack2(h0, h1); *(uint32_t*)(Cl + o) = pack2(l0, l1);
        }
    }
}

// ---------------- hgemm2: 128x256 tile, fp16 2-pass (weights single fp16) ------
// C[M,N] = (Ah+Al)[M,K] @ Bh[N,K]^T (+bias). 8 warps of 64x64. 6-stage pipeline.
// ET = epilogue split type (bf16 or __half).
template<int OUT, typename ET>
__global__ __launch_bounds__(256)
void hgemm2(const __half* __restrict__ Ah, const __half* __restrict__ Al,
            const __half* __restrict__ Bh,
            float* __restrict__ C, ET* __restrict__ Ch, ET* __restrict__ Cl,
            ET* __restrict__ Dh, ET* __restrict__ Dl,
            const float* __restrict__ bias,
            const float* __restrict__ bias2, const float* __restrict__ bias3,
            int M, int N, int K, int lda, int ldb, int ldc)
{
    constexpr int STAGE = 16384;   // A-hi 4K, A-lo 4K, B 8K
    extern __shared__ __align__(128) char sm[];
    const uint32_t smb = smem_u32(sm);
    const int tid = threadIdx.x, wid = tid >> 5, lane = tid & 31;
    const int m0 = blockIdx.x * 128, n0 = blockIdx.y * 256;
    const int m_w = (wid & 1) * 64, n_w = (wid >> 1) * 64;

    const int lr = tid >> 1, lc = tid & 1;
    const uint32_t soA = (uint32_t)(lr * 32 + ((lc ^ ((lr >> 2) & 1)) << 4));
    const int ga = min(m0 + lr, M - 1);
    const long long aoff = (long long)ga * lda + lc * 8;
    const int gb = min(n0 + tid, N - 1);
    const long long boff = (long long)gb * ldb;
    const uint32_t soB0 = (uint32_t)(tid * 32 + ((0 ^ ((tid >> 2) & 1)) << 4));
    const uint32_t soB1 = (uint32_t)(tid * 32 + ((1 ^ ((tid >> 2) & 1)) << 4));

    float acc[4][8][4];
    #pragma unroll
    for (int i = 0; i < 4; i++)
        #pragma unroll
        for (int j = 0; j < 8; j++)
            #pragma unroll
            for (int k = 0; k < 4; k++) acc[i][j][k] = 0.f;

    const int NC = K / 16;
    const int NP = NC / 2;

    #pragma unroll
    for (int g = 0; g < 2; g++) {
        #pragma unroll
        for (int s = 0; s < 2; s++) {
            const int ck = 2 * g + s;
            const uint32_t st = smb + (2 * g + s) * STAGE;
            cp16(st + soA,        Ah + aoff + ck * 16);
            cp16(st + 4096 + soA, Al + aoff + ck * 16);
            cp16(st + 8192 + soB0, Bh + boff + ck * 16);
            cp16(st + 8192 + soB1, Bh + boff + ck * 16 + 8);
        }
        asm volatile("cp.async.commit_group;");
    }

    const int rr = lane & 15, ccq = lane >> 4;
    const int rbq = (lane & 7) | ((lane & 16) >> 1);
    const int cbq = (lane >> 3) & 1;

    for (int p = 0; p < NP; p++) {
        asm volatile("cp.async.wait_group 1;");
        __syncthreads();
        {
            const int gidx = p + 2;
            const int sb = (gidx % 3) * 2;
            #pragma unroll
            for (int s = 0; s < 2; s++) {
                const int ck = 2 * gidx + s;
                if (ck < NC) {
                    const uint32_t st = smb + (sb + s) * STAGE;
                    cp16(st + soA,        Ah + aoff + ck * 16);
                    cp16(st + 4096 + soA, Al + aoff + ck * 16);
                    cp16(st + 8192 + soB0, Bh + boff + ck * 16);
                    cp16(st + 8192 + soB1, Bh + boff + ck * 16 + 8);
                }
            }
            asm volatile("cp.async.commit_group;");
        }
        const int cb2 = (p % 3) * 2;
        #pragma unroll
        for (int s = 0; s < 2; s++) {
            const uint32_t st = smb + (cb2 + s) * STAGE;
            uint32_t ah[4][4], al[4][4], bh[4][4];
            #pragma unroll
            for (int mt = 0; mt < 4; mt++) {
                int R = m_w + mt * 16 + rr;
                uint32_t ad = st + R * 32 + ((ccq ^ ((R >> 2) & 1)) << 4);
                ldx4(ah[mt], ad);
                ldx4(al[mt], ad + 4096);
            }
            #pragma unroll
            for (int np = 0; np < 4; np++) {
                int Nr = n_w + np * 16 + rbq;
                uint32_t bd = st + 8192 + Nr * 32 + ((cbq ^ ((Nr >> 2) & 1)) << 4);
                ldx4(bh[np], bd);
            }
            #pragma unroll
            for (int mt = 0; mt < 4; mt++)
                #pragma unroll
                for (int nt = 0; nt < 8; nt++) {
                    const uint32_t* bp = &bh[nt >> 1][(nt & 1) * 2];
                    mma_fp(acc[mt][nt], ah[mt], bp);
                    mma_fp(acc[mt][nt], al[mt], bp);
                }
        }
    }

    #pragma unroll
    for (int mt = 0; mt < 4; mt++) {
        int gm0 = m0 + m_w + mt * 16 + (lane >> 2);
        #pragma unroll
        for (int nt = 0; nt < 8; nt++) {
            int gn = n0 + n_w + nt * 8 + (lane & 3) * 2;
            if (gn >= N) continue;
            float bx = 0.f, by = 0.f;
            if (bias) { float2 bv = *(const float2*)(bias + gn); bx = bv.x; by = bv.y; }
            epi_store<OUT, ET>(acc[mt][nt][0] + bx, acc[mt][nt][1] + by,
                               acc[mt][nt][2] + bx, acc[mt][nt][3] + by,
                               gm0, gn, M, ldc, 0, C, Ch, Cl, Dh, Dl, bias2, bias3);
        }
    }
}

// ---------------- hgemm: 128xBN tile, bf16 3-pass (attention path) -------------
// maskA/maskB dead-tile skips; kclamp for causal K truncation.
template<int BN, int OUT, typename ET>
__global__ __launch_bounds__(256)
void hgemm(const bf16* __restrict__ Ah, const bf16* __restrict__ Al,
           const bf16* __restrict__ Bh, const bf16* __restrict__ Bl,
           float* __restrict__ C, ET* __restrict__ Ch, ET* __restrict__ Cl,
           const float* __restrict__ bias,
           int M, int N, int K, int lda, int ldb, int ldc, int Z2,
           long long sA1, long long sA2, long long sB1, long long sB2,
           long long sC1, long long sC2,
           int maskA, int maskB, int kclamp)
{
    constexpr int BSTR = BN * 32;
    constexpr int STAGE = 8192 + 2 * BSTR;
    constexpr int MT = (BN == 128) ? 4 : 2;
    extern __shared__ __align__(128) char sm[];
    const uint32_t smb = smem_u32(sm);
    const int tid = threadIdx.x, wid = tid >> 5, lane = tid & 31;
    const int m0 = blockIdx.x * 128, n0 = blockIdx.y * BN;
    if (maskA >= 0 && n0 > m0 + maskA) return;
    if (maskB >= 0 && m0 + n0 < maskB) return;
    const int Keff = (kclamp >= 0) ? min(K, m0 + kclamp) : K;

    const int m_w = (BN == 128) ? (wid & 1) * 64 : (wid & 3) * 32;
    const int n_w = (BN == 128) ? (wid >> 1) * 32 : (wid >> 2) * 32;

    const int z = blockIdx.z;
    const int z1 = z / Z2, z2 = z - z1 * Z2;
    Ah += z1 * sA1 + z2 * sA2;  Al += z1 * sA1 + z2 * sA2;
    Bh += z1 * sB1 + z2 * sB2;  Bl += z1 * sB1 + z2 * sB2;
    const long long cbase = z1 * sC1 + z2 * sC2;

    const int lr = tid >> 1, lc = tid & 1;
    const uint32_t so = (uint32_t)(lr * 32 + ((lc ^ ((lr >> 2) & 1)) << 4));
    const int ga = min(m0 + lr, M - 1);
    const long long aoff = (long long)ga * lda + lc * 8;
    const bool bdo = (BN == 128) || (tid < 128);
    const int gb = min(n0 + lr, N - 1);
    const long long boff = (long long)gb * ldb + lc * 8;

    float acc[MT][4][4];
    #pragma unroll
    for (int i = 0; i < MT; i++)
        #pragma unroll
        for (int j = 0; j < 4; j++)
            #pragma unroll
            for (int k = 0; k < 4; k++) acc[i][j][k] = 0.f;

    const int NC = Keff / 16;
    const int NP = NC / 2;

    #pragma unroll
    for (int g = 0; g < 2; g++) {
        #pragma unroll
        for (int s = 0; s < 2; s++) {
            const int ck = 2 * g + s;
            const uint32_t st = smb + (2 * g + s) * STAGE;
            cp16(st + so,        Ah + aoff + ck * 16);
            cp16(st + 4096 + so, Al + aoff + ck * 16);
            if (bdo) {
                cp16(st + 8192 + so, Bh + boff + ck * 16);
                cp16(st + 8192 + BSTR + so, Bl + boff + ck * 16);
            }
        }
        asm volatile("cp.async.commit_group;");
    }

    const int rr = lane & 15, ccq = lane >> 4;
    const int rbq = (lane & 7) | ((lane & 16) >> 1);
    const int cbq = (lane >> 3) & 1;

    for (int p = 0; p < NP; p++) {
        asm volatile("cp.async.wait_group 1;");
        __syncthreads();
        {
            const int gidx = p + 2;
            const int sb = (gidx % 3) * 2;
            #pragma unroll
            for (int s = 0; s < 2; s++) {
                const int ck = 2 * gidx + s;
                if (ck < NC) {
                    const uint32_t st = smb + (sb + s) * STAGE;
                    cp16(st + so,        Ah + aoff + ck * 16);
                    cp16(st + 4096 + so, Al + aoff + ck * 16);
                    if (bdo) {
                        cp16(st + 8192 + so, Bh + boff + ck * 16);
                        cp16(st + 8192 + BSTR + so, Bl + boff + ck * 16);
                    }
                }
            }
            asm volatile("cp.async.commit_group;");
        }
        const int cb2 = (p % 3) * 2;
        #pragma unroll
        for (int s = 0; s < 2; s++) {
            const uint32_t st = smb + (cb2 + s) * STAGE;
            uint32_t ah[MT][4], al[MT][4], bh[2][4], bl[2][4];
            #pragma unroll
            for (int mt = 0; mt < MT; mt++) {
                int R = m_w + mt * 16 + rr;
                uint32_t ad = st + R * 32 + ((ccq ^ ((R >> 2) & 1)) << 4);
                ldx4(ah[mt], ad);
                ldx4(al[mt], ad + 4096);
            }
            #pragma unroll
            for (int np = 0; np < 2; np++) {
                int Nr = n_w + np * 16 + rbq;
                uint32_t bd = st + 8192 + Nr * 32 + ((cbq ^ ((Nr >> 2) & 1)) << 4);
                ldx4(bh[np], bd);
                ldx4(bl[np], bd + BSTR);
            }
            #pragma unroll
            for (int mt = 0; mt < MT; mt++)
                #pragma unroll
                for (int nt = 0; nt < 4; nt++) {
                    const uint32_t* bhp = &bh[nt >> 1][(nt & 1) * 2];
                    const uint32_t* blp = &bl[nt >> 1][(nt & 1) * 2];
                    mma_bf(acc[mt][nt], ah[mt], bhp);
                    mma_bf(acc[mt][nt], ah[mt], blp);
                    mma_bf(acc[mt][nt], al[mt], bhp);
                }
        }
    }

    #pragma unroll
    for (int mt = 0; mt < MT; mt++) {
        int gm0 = m0 + m_w + mt * 16 + (lane >> 2);
        #pragma unroll
        for (int nt = 0; nt < 4; nt++) {
            int gn = n0 + n_w + nt * 8 + (lane & 3) * 2;
            if (gn >= N) continue;
            float bx = 0.f, by = 0.f;
            if (bias) { float2 bv = *(const float2*)(bias + gn); bx = bv.x; by = bv.y; }
            epi_store<OUT, ET>(acc[mt][nt][0] + bx, acc[mt][nt][1] + by,
                               acc[mt][nt][2] + bx, acc[mt][nt][3] + by,
                               gm0, gn, M, ldc, cbase, C, Ch, Cl,
                               (ET*)nullptr, (ET*)nullptr, nullptr, nullptr);
        }
    }
}

// ---------------- reductions ----------------
__device__ __forceinline__ float block_reduce_sum(float v) {
    __shared__ float sm[16];
    __syncthreads();
    #pragma unroll
    for (int o = 16; o > 0; o >>= 1) v += __shfl_xor_sync(0xffffffffu, v, o);
    if ((threadIdx.x & 31) == 0) sm[threadIdx.x >> 5] = v;
    __syncthreads();
    if (threadIdx.x < 32) {
        float x = (threadIdx.x < (blockDim.x >> 5)) ? sm[threadIdx.x] : 0.f;
        #pragma unroll
        for (int o = 8; o > 0; o >>= 1) x += __shfl_xor_sync(0xffffffffu, x, o);
        if (threadIdx.x == 0) sm[0] = x;
    }
    __syncthreads();
    return sm[0];
}
__device__ __forceinline__ float block_reduce_max(float v) {
    __shared__ float sm[16];
    __syncthreads();
    #pragma unroll
    for (int o = 16; o > 0; o >>= 1) v = fmaxf(v, __shfl_xor_sync(0xffffffffu, v, o));
    if ((threadIdx.x & 31) == 0) sm[threadIdx.x >> 5] = v;
    __syncthreads();
    if (threadIdx.x < 32) {
        float x = (threadIdx.x < (blockDim.x >> 5)) ? sm[threadIdx.x] : -3.4e38f;
        #pragma unroll
        for (int o = 8; o > 0; o >>= 1) x = fmaxf(x, __shfl_xor_sync(0xffffffffu, x, o));
        if (threadIdx.x == 0) sm[0] = x;
    }
    __syncthreads();
    return sm[0];
}

// ---------------- small kernels ----------------
__global__ void build_full(const int* __restrict__ tokens,
                           const float* __restrict__ memory,
                           const float* __restrict__ embed,
                           float* __restrict__ x,
                           __half* __restrict__ xh, __half* __restrict__ xl,
                           __half* __restrict__ fullh, __half* __restrict__ fulll)
{
    long long idx = (long long)blockIdx.x * 256 + threadIdx.x;
    const long long tot = (long long)BB * KLEN * UU;
    if (idx >= tot) return;
    int u = (int)(idx % UU);
    long long t = idx / UU;
    int j = (int)(t % KLEN);
    int b = (int)(t / KLEN);
    float v;
    if (j < MEMLEN) {
        v = memory[((long long)b * MEMLEN + j) * UU + u];
    } else {
        int s = j - MEMLEN;
        int tok = tokens[b * SS + s];
        v = embed[(long long)tok * UU + u] * 32.0f;  // sqrt(1024)
        long long xo = ((long long)b * SS + s) * UU + u;
        x[xo] = v;
        __half h, l; split_to(v, h, l);
        xh[xo] = h; xl[xo] = l;
    }
    __half h, l; split_to(v, h, l);
    fullh[idx] = h; fulll[idx] = l;
}

__global__ void pos_embed(__half* __restrict__ relh, __half* __restrict__ rell)
{
    long long idx = (long long)blockIdx.x * 256 + threadIdx.x;
    if (idx >= (long long)KLEN * UU) return;
    int u = (int)(idx % UU);
    int jj = (int)(idx / UU);
    float pos = (float)(KLEN - 1 - jj);
    int i2 = (u < UU / 2) ? u : (u - UU / 2);
    float expo = ((float)(2 * i2)) / (float)UU;
    float invf = expf(-expo * 9.210340371976184f);  // ln(10000)
    float ang = pos * invf;
    float v = (u < UU / 2) ? sinf(ang) : cosf(ang);
    __half h, l; split_to(v, h, l);
    relh[idx] = h; rell[idx] = l;
}

// transpose: W[K,N] fp32 -> single fp16 [N,K]
__global__ void split_T_h(const float* __restrict__ W, __half* __restrict__ hi,
                          int K, int N)
{
    __shared__ float t[32][33];
    int n0 = blockIdx.x * 32, k0 = blockIdx.y * 32;
    #pragma unroll
    for (int i = 0; i < 32; i += 8)
        t[threadIdx.y + i][threadIdx.x] =
            W[(long long)(k0 + threadIdx.y + i) * N + n0 + threadIdx.x];
    __syncthreads();
    #pragma unroll
    for (int i = 0; i < 32; i += 8) {
        float v = t[threadIdx.x][threadIdx.y + i];
        long long o = (long long)(n0 + threadIdx.y + i) * K + k0 + threadIdx.x;
        hi[o] = __float2half(v);
    }
}

// V^T per head (bit-level, bf16): vt[(b*H+h), d, j] = kv[b, j, U + h*64 + d]
__global__ void transpose_v(const bf16* __restrict__ kvh, const bf16* __restrict__ kvl,
                            bf16* __restrict__ vth, bf16* __restrict__ vtl)
{
    __shared__ bf16 th[32][33], tl[32][33];
    int z = blockIdx.z;
    int b = z / HH, h = z % HH;
    int j0 = blockIdx.x * 32, d0 = blockIdx.y * 32;
    int tx = threadIdx.x, ty = threadIdx.y;
    #pragma unroll
    for (int i = 0; i < 32; i += 8) {
        long long src = ((long long)b * KLEN + j0 + ty + i) * (2 * UU) + UU + h * 64 + d0 + tx;
        th[ty + i][tx] = kvh[src];
        tl[ty + i][tx] = kvl[src];
    }
    __syncthreads();
    #pragma unroll
    for (int i = 0; i < 32; i += 8) {
        long long dst = ((long long)z * DD + d0 + ty + i) * KLEN + j0 + tx;
        vth[dst] = th[tx][ty + i];
        vtl[dst] = tl[tx][ty + i];
    }
}

// mask + rel-shift + softmax; writes P as split bf16 (zero tail)
__global__ __launch_bounds__(256)
void attn_softmax(const float* __restrict__ ac, const float* __restrict__ ar,
                  bf16* __restrict__ ph, bf16* __restrict__ pl)
{
    int i = blockIdx.x;
    long long z = blockIdx.y;
    const float* arow = ac + (z * SS + i) * (long long)KLEN;
    const float* rrow = ar + (z * SS + i) * (long long)KLEN;
    bf16* phr = ph + (z * SS + i) * (long long)KLEN;
    bf16* plr = pl + (z * SS + i) * (long long)KLEN;
    int lim = i + MEMLEN;
    int shift = SS - 1 - i;
    int tid = threadIdx.x;

    float vals[7];
    int cnt = 0;
    float lmax = -3.4e38f;
    for (int j = tid; j <= lim; j += 256) {
        float v = (arow[j] + rrow[j + shift]) * 0.125f;
        vals[cnt++] = v;
        lmax = fmaxf(lmax, v);
    }
    float m = block_reduce_max(lmax);
    float lsum = 0.f;
    for (int t = 0; t < cnt; t++) {
        float e = expf(vals[t] - m);
        vals[t] = e;
        lsum += e;
    }
    float s = block_reduce_sum(lsum);
    float inv = 1.f / s;
    cnt = 0;
    for (int j = tid; j <= lim; j += 256) {
        float p = vals[cnt++] * inv;
        bf16 h, l; split_to(p, h, l);
        phr[j] = h; plr[j] = l;
    }
    bf16 z0 = __float2bfloat16(0.f);
    for (int j = lim + 1 + tid; j < KLEN; j += 256) { phr[j] = z0; plr[j] = z0; }
}

// add + LayerNorm; emits fp32 (optional) plus fp16 split pair
__global__ __launch_bounds__(256)
void add_ln(const float* __restrict__ a, const float* __restrict__ b,
            const float* __restrict__ g, const float* __restrict__ beta,
            float* __restrict__ out, __half* __restrict__ oh, __half* __restrict__ ol)
{
    long long row = blockIdx.x;
    const float* pa = a + row * UU;
    const float* pb = b + row * UU;
    int tid = threadIdx.x;
    float vals[4];
    float s = 0.f, ss = 0.f;
    #pragma unroll
    for (int t = 0; t < 4; t++) {
        int idx = tid * 4 + t;
        float v = pa[idx] + pb[idx];
        vals[t] = v;
        s += v;
        ss += v * v;
    }
    s = block_reduce_sum(s);
    ss = block_reduce_sum(ss);
    float mean = s * (1.f / UU);
    float var = fmaxf(ss * (1.f / UU) - mean * mean, 0.f);
    float rstd = rsqrtf(var + 1e-5f);
    #pragma unroll
    for (int t = 0; t < 4; t++) {
        int idx = tid * 4 + t;
        float v = (vals[t] - mean) * rstd * g[idx] + beta[idx];
        if (out) out[row * UU + idx] = v;
        __half h, l; split_to(v, h, l);
        oh[row * UU + idx] = h; ol[row * UU + idx] = l;
    }
}

// online-softmax over vocab rows, in place
__global__ __launch_bounds__(512)
void softmax_rows(float* __restrict__ x, int N)
{
    __shared__ float smm[16], sms[16];
    long long row = blockIdx.x;
    float* p = x + row * (long long)N;
    int tid = threadIdx.x;
    float m = -3.4e38f, s = 0.f;
    for (int j = tid; j < N; j += 512) {
        float v = p[j];
        if (v > m) { s = s * expf(m - v) + 1.f; m = v; }
        else       { s += expf(v - m); }
    }
    #pragma unroll
    for (int o = 16; o > 0; o >>= 1) {
        float m2 = __shfl_xor_sync(0xffffffffu, m, o);
        float s2 = __shfl_xor_sync(0xffffffffu, s, o);
        float M = fmaxf(m, m2);
        s = s * expf(m - M) + s2 * expf(m2 - M);
        m = M;
    }
    if ((tid & 31) == 0) { smm[tid >> 5] = m; sms[tid >> 5] = s; }
    __syncthreads();
    if (tid < 32) {
        float mm = (tid < 16) ? smm[tid] : -3.4e38f;
        float ssv = (tid < 16) ? sms[tid] : 0.f;
        #pragma unroll
        for (int o = 8; o > 0; o >>= 1) {
            float m2 = __shfl_xor_sync(0xffffffffu, mm, o);
            float s2 = __shfl_xor_sync(0xffffffffu, ssv, o);
            float M = fmaxf(mm, m2);
            ssv = ssv * expf(mm - M) + s2 * expf(m2 - M);
            mm = M;
        }
        if (tid == 0) { smm[0] = mm; sms[0] = ssv; }
    }
    __syncthreads();
    float M = smm[0];
    float inv = 1.f / sms[0];
    for (int j = tid; j < N; j += 512) p[j] = expf(p[j] - M) * inv;
}

// ---------------- host ----------------
#define SMEM_G2 (6 * 16384)
#define SMEM_G(BN) (6 * (8192 + 2 * (BN) * 32))

extern "C" void kernel_launch(void* const* d_in, const int* in_sizes, int n_in,
                              void* d_out, int out_size)
{
    const int*   tokens  = (const int*)  d_in[0];
    const float* memory  = (const float*)d_in[1];
    const float* embed   = (const float*)d_in[2];
    const float* Wq      = (const float*)d_in[3];
    const float* Wkv     = (const float*)d_in[4];
    const float* Wr      = (const float*)d_in[5];
    const float* Wo      = (const float*)d_in[6];
    const float* bq      = (const float*)d_in[7];
    const float* bkv     = (const float*)d_in[8];
    const float* br      = (const float*)d_in[9];
    const float* bo      = (const float*)d_in[10];
    const float* bias_c  = (const float*)d_in[11];
    const float* bias_r  = (const float*)d_in[12];
    const float* ln1_g   = (const float*)d_in[13];
    const float* ln1_b   = (const float*)d_in[14];
    const float* W1      = (const float*)d_in[15];
    const float* b1      = (const float*)d_in[16];
    const float* W2      = (const float*)d_in[17];
    const float* b2      = (const float*)d_in[18];
    const float* ln2_g   = (const float*)d_in[19];
    const float* ln2_b   = (const float*)d_in[20];
    const float* Wout    = (const float*)d_in[21];
    const float* bout    = (const float*)d_in[22];
    float* out = (float*)d_out;

    static bool s_attr = false;
    if (!s_attr) {
        cudaFuncSetAttribute(hgemm2<0, __half>, cudaFuncAttributeMaxDynamicSharedMemorySize, SMEM_G2);
        cudaFuncSetAttribute(hgemm2<1, bf16>,   cudaFuncAttributeMaxDynamicSharedMemorySize, SMEM_G2);
        cudaFuncSetAttribute(hgemm2<2, __half>, cudaFuncAttributeMaxDynamicSharedMemorySize, SMEM_G2);
        cudaFuncSetAttribute(hgemm2<3, bf16>,   cudaFuncAttributeMaxDynamicSharedMemorySize, SMEM_G2);
        cudaFuncSetAttribute(hgemm<128,0,bf16>, cudaFuncAttributeMaxDynamicSharedMemorySize, SMEM_G(128));
        cudaFuncSetAttribute(hgemm<64,1,__half>, cudaFuncAttributeMaxDynamicSharedMemorySize, SMEM_G(64));
        s_attr = true;
    }

    float *x, *ac, *ar, *tmp, *h1;
    cudaGetSymbolAddress((void**)&x,   g_x);
    cudaGetSymbolAddress((void**)&ac,  g_ac);
    cudaGetSymbolAddress((void**)&ar,  g_ar);
    cudaGetSymbolAddress((void**)&tmp, g_tmp);
    cudaGetSymbolAddress((void**)&h1,  g_h1);

    __half *xh,*xl,*fullh,*fulll,*relh,*rell,*ctxh,*ctxl,*h1hh,*h1lh,*ffhh,*fflh,*h2hh,*h2lh;
    bf16 *qch,*qcl,*qrh,*qrl,*kvh,*kvl,*rh,*rl,*ph,*pl,*vth,*vtl;
    __half *WqH,*WkvH,*WrH,*WoH,*W1H,*W2H,*WoutH;
    cudaGetSymbolAddress((void**)&xh, g_xh);       cudaGetSymbolAddress((void**)&xl, g_xl);
    cudaGetSymbolAddress((void**)&fullh, g_fullh); cudaGetSymbolAddress((void**)&fulll, g_fulll);
    cudaGetSymbolAddress((void**)&relh, g_relh);   cudaGetSymbolAddress((void**)&rell, g_rell);
    cudaGetSymbolAddress((void**)&ctxh, g_ctxh);   cudaGetSymbolAddress((void**)&ctxl, g_ctxl);
    cudaGetSymbolAddress((void**)&h1hh, g_h1hh);   cudaGetSymbolAddress((void**)&h1lh, g_h1lh);
    cudaGetSymbolAddress((void**)&ffhh, g_ffhh);   cudaGetSymbolAddress((void**)&fflh, g_fflh);
    cudaGetSymbolAddress((void**)&h2hh, g_h2hh);   cudaGetSymbolAddress((void**)&h2lh, g_h2lh);
    cudaGetSymbolAddress((void**)&qch, g_qch);     cudaGetSymbolAddress((void**)&qcl, g_qcl);
    cudaGetSymbolAddress((void**)&qrh, g_qrh);     cudaGetSymbolAddress((void**)&qrl, g_qrl);
    cudaGetSymbolAddress((void**)&kvh, g_kvh);     cudaGetSymbolAddress((void**)&kvl, g_kvl);
    cudaGetSymbolAddress((void**)&rh, g_rh);       cudaGetSymbolAddress((void**)&rl, g_rl);
    cudaGetSymbolAddress((void**)&ph, g_ph);       cudaGetSymbolAddress((void**)&pl, g_pl);
    cudaGetSymbolAddress((void**)&vth, g_vth);     cudaGetSymbolAddress((void**)&vtl, g_vtl);
    cudaGetSymbolAddress((void**)&WqH, g_WqH);     cudaGetSymbolAddress((void**)&WkvH, g_WkvH);
    cudaGetSymbolAddress((void**)&WrH, g_WrH);     cudaGetSymbolAddress((void**)&WoH, g_WoH);
    cudaGetSymbolAddress((void**)&W1H, g_W1H);     cudaGetSymbolAddress((void**)&W2H, g_W2H);
    cudaGetSymbolAddress((void**)&WoutH, g_WoutH);

    const int M_TOK = BB * SS;      // 2048
    const int M_FULL = BB * KLEN;   // 3200
    dim3 tb(32, 8);

    // 1) embedding + concat + fp16 splits
    {
        long long tot = (long long)BB * KLEN * UU;
        build_full<<<(unsigned)((tot + 255) / 256), 256>>>(tokens, memory, embed,
                                                           x, xh, xl, fullh, fulll);
    }
    // 2) Wkv -> fp16
    split_T_h<<<dim3(2*UU/32, UU/32), tb>>>(Wkv, WkvH, UU, 2*UU);
    // 3) positional embedding
    {
        long long tot = (long long)KLEN * UU;
        pos_embed<<<(unsigned)((tot + 255) / 256), 256>>>(relh, rell);
    }
    // 4) kv projection (hgemm2)  <-- ncu capture target (4th launch)
    hgemm2<1, bf16><<<dim3(M_FULL/128, 2*UU/256), 256, SMEM_G2>>>(
        fullh, fulll, WkvH, nullptr, kvh, kvl, nullptr, nullptr,
        bkv, nullptr, nullptr, M_FULL, 2*UU, UU, UU, UU, 2*UU);
    // remaining weight conversions
    split_T_h<<<dim3(UU/32,  UU/32),  tb>>>(Wq,   WqH,   UU,  UU);
    split_T_h<<<dim3(UU/32,  UU/32),  tb>>>(Wr,   WrH,   UU,  UU);
    split_T_h<<<dim3(UU/32,  UU/32),  tb>>>(Wo,   WoH,   UU,  UU);
    split_T_h<<<dim3(FFD/32, UU/32),  tb>>>(W1,   W1H,   UU,  FFD);
    split_T_h<<<dim3(UU/32,  FFD/32), tb>>>(W2,   W2H,   FFD, UU);
    split_T_h<<<dim3(NT/32,  UU/32),  tb>>>(Wout, WoutH, UU,  NT);
    // q projection fused with (q+u)/(q+v) bf16 splits
    hgemm2<3, bf16><<<dim3(M_TOK/128, UU/256), 256, SMEM_G2>>>(
        xh, xl, WqH, nullptr, qch, qcl, qrh, qrl,
        bq, bias_c, bias_r, M_TOK, UU, UU, UU, UU, UU);
    // r projection
    hgemm2<1, bf16><<<dim3((KLEN+127)/128, UU/256), 256, SMEM_G2>>>(
        relh, rell, WrH, nullptr, rh, rl, nullptr, nullptr,
        br, nullptr, nullptr, KLEN, UU, UU, UU, UU, UU);
    // scores (bf16 3-pass, batched over b,h), dead-tile skips
    {
        dim3 grid(SS / 128, (KLEN + 127) / 128, BB * HH);
        hgemm<128,0,bf16><<<grid, 256, SMEM_G(128)>>>(qch, qcl, kvh, kvl, ac,
            (bf16*)nullptr, (bf16*)nullptr, nullptr,
            SS, KLEN, DD, UU, 2*UU, KLEN, HH,
            (long long)SS*UU, 64,
            (long long)KLEN*2*UU, 64,
            (long long)HH*SS*KLEN, (long long)SS*KLEN,
            MEMLEN + 127, -1, -1);
        hgemm<128,0,bf16><<<grid, 256, SMEM_G(128)>>>(qrh, qrl, rh, rl, ar,
            (bf16*)nullptr, (bf16*)nullptr, nullptr,
            SS, KLEN, DD, UU, UU, KLEN, HH,
            (long long)SS*UU, 64,
            0, 64,
            (long long)HH*SS*KLEN, (long long)SS*KLEN,
            -1, SS - 255, -1);
    }
    // fused rel-shift + mask + softmax -> split P (bf16)
    {
        dim3 grid(SS, BB * HH);
        attn_softmax<<<grid, 256>>>(ac, ar, ph, pl);
    }
    // V^T per head
    {
        dim3 grid(KLEN / 32, DD / 32, BB * HH);
        transpose_v<<<grid, tb>>>(kvh, kvl, vth, vtl);
    }
    // ctx = P @ V^T (bf16 3-pass, K clamp), fp16 split output
    {
        dim3 grid(SS / 128, 1, BB * HH);
        hgemm<64,1,__half><<<grid, 256, SMEM_G(64)>>>(ph, pl, vth, vtl, nullptr,
            ctxh, ctxl, nullptr,
            SS, DD, KLEN, KLEN, KLEN, UU, HH,
            (long long)HH*SS*KLEN, (long long)SS*KLEN,
            (long long)HH*DD*KLEN, (long long)DD*KLEN,
            (long long)SS*UU, 64,
            -1, -1, MEMLEN + 128);
    }
    // attention out projection + LN1
    hgemm2<0, __half><<<dim3(M_TOK/128, UU/256), 256, SMEM_G2>>>(
        ctxh, ctxl, WoH, tmp, nullptr, nullptr, nullptr, nullptr,
        bo, nullptr, nullptr, M_TOK, UU, UU, UU, UU, UU);
    add_ln<<<M_TOK, 256>>>(x, tmp, ln1_g, ln1_b, h1, h1hh, h1lh);
    // FF
    hgemm2<2, __half><<<dim3(M_TOK/128, FFD/256), 256, SMEM_G2>>>(
        h1hh, h1lh, W1H, nullptr, ffhh, fflh, nullptr, nullptr,
        b1, nullptr, nullptr, M_TOK, FFD, UU, UU, UU, FFD);
    hgemm2<0, __half><<<dim3(M_TOK/128, UU/256), 256, SMEM_G2>>>(
        ffhh, fflh, W2H, tmp, nullptr, nullptr, nullptr, nullptr,
        b2, nullptr, nullptr, M_TOK, UU, FFD, FFD, FFD, UU);
    add_ln<<<M_TOK, 256>>>(h1, tmp, ln2_g, ln2_b, nullptr, h2hh, h2lh);
    // logits + softmax
    hgemm2<0, __half><<<dim3(M_TOK/128, NT/256), 256, SMEM_G2>>>(
        h2hh, h2lh, WoutH, out, nullptr, nullptr, nullptr, nullptr,
        bout, nullptr, nullptr, M_TOK, NT, UU, UU, UU, NT);
    softmax_rows<<<M_TOK, 512>>>(out, NT);
}

// round 12
// speedup vs baseline: 1.0002x; 1.0002x over previous
#include <cuda_runtime.h>
#include <cuda_bf16.h>
#include <cuda_fp16.h>
#include <math.h>
#include <stdint.h>

// ---------------- problem constants ----------------
#define BB 2
#define SS 1024
#define UU 1024
#define HH 16
#define DD 64
#define NT 32000
#define MEMLEN 576
#define FFD 4096
#define KLEN 1600   // MEM + S
#define VOCAB 1024

typedef __nv_bfloat16 bf16;

// ---------------- scratch (device globals; no allocation allowed) ----------------
__device__ float g_ac  [(size_t)BB*HH*SS*KLEN];
__device__ float g_ar  [(size_t)BB*HH*SS*KLEN];
__device__ float g_x   [(size_t)BB*SS*UU];
__device__ float g_tmp [(size_t)BB*SS*UU];
__device__ float g_h1  [(size_t)BB*SS*UU];

// fp16 A-side splits
__device__ __half g_xh   [(size_t)BB*SS*UU],   g_xl   [(size_t)BB*SS*UU];
__device__ __half g_fullh[(size_t)BB*KLEN*UU], g_fulll[(size_t)BB*KLEN*UU];
__device__ __half g_relh [(size_t)KLEN*UU],    g_rell [(size_t)KLEN*UU];
__device__ __half g_ctxh [(size_t)BB*SS*UU],   g_ctxl [(size_t)BB*SS*UU];
__device__ __half g_h1hh [(size_t)BB*SS*UU],   g_h1lh [(size_t)BB*SS*UU];
__device__ __half g_ffhh [(size_t)BB*SS*FFD],  g_fflh [(size_t)BB*SS*FFD];
__device__ __half g_h2hh [(size_t)BB*SS*UU],   g_h2lh [(size_t)BB*SS*UU];
// bf16 splits (attention internal path)
__device__ bf16 g_qch  [(size_t)BB*SS*UU],   g_qcl  [(size_t)BB*SS*UU];
__device__ bf16 g_qrh  [(size_t)BB*SS*UU],   g_qrl  [(size_t)BB*SS*UU];
__device__ bf16 g_kvh  [(size_t)BB*KLEN*2*UU], g_kvl [(size_t)BB*KLEN*2*UU];
__device__ bf16 g_rh   [(size_t)KLEN*UU],    g_rl   [(size_t)KLEN*UU];
__device__ bf16 g_ph   [(size_t)BB*HH*SS*KLEN], g_pl [(size_t)BB*HH*SS*KLEN];
__device__ bf16 g_vth  [(size_t)BB*HH*DD*KLEN], g_vtl[(size_t)BB*HH*DD*KLEN];
// single-fp16 transposed weights [N,K]
__device__ __half g_WqH [(size_t)UU*UU];
__device__ __half g_WkvH[(size_t)2*UU*UU];
__device__ __half g_WrH [(size_t)UU*UU];
__device__ __half g_WoH [(size_t)UU*UU];
__device__ __half g_W1H [(size_t)FFD*UU];
__device__ __half g_W2H [(size_t)UU*FFD];
__device__ __half g_WoutH[(size_t)NT*UU];

// ---------------- helpers ----------------
__device__ __forceinline__ uint32_t smem_u32(const void* p) {
    uint32_t a;
    asm("{ .reg .u64 t; cvta.to.shared.u64 t, %1; cvt.u32.u64 %0, t; }" : "=r"(a) : "l"(p));
    return a;
}
__device__ __forceinline__ void split_to(float v, bf16& h, bf16& l) {
    h = __float2bfloat16(v);
    l = __float2bfloat16(v - __bfloat162float(h));
}
__device__ __forceinline__ void split_to(float v, __half& h, __half& l) {
    h = __float2half(v);
    l = __float2half(v - __half2float(h));
}
template<typename T>
__device__ __forceinline__ uint32_t pack2(T a, T b) {
    unsigned short x = *(unsigned short*)&a, y = *(unsigned short*)&b;
    return (uint32_t)x | ((uint32_t)y << 16);
}
__device__ __forceinline__ void cp16(uint32_t dst, const void* src) {
    asm volatile("cp.async.cg.shared.global [%0], [%1], 16;" :: "r"(dst), "l"(src));
}
__device__ __forceinline__ void ldx4(uint32_t* r, uint32_t addr) {
    asm volatile("ldmatrix.sync.aligned.m8n8.x4.shared.b16 {%0,%1,%2,%3}, [%4];"
                 : "=r"(r[0]), "=r"(r[1]), "=r"(r[2]), "=r"(r[3]) : "r"(addr));
}
__device__ __forceinline__ void mma_bf(float* c, const uint32_t* a, const uint32_t* b) {
    asm volatile("mma.sync.aligned.m16n8k16.row.col.f32.bf16.bf16.f32 "
                 "{%0,%1,%2,%3}, {%4,%5,%6,%7}, {%8,%9}, {%0,%1,%2,%3};"
                 : "+f"(c[0]), "+f"(c[1]), "+f"(c[2]), "+f"(c[3])
                 : "r"(a[0]), "r"(a[1]), "r"(a[2]), "r"(a[3]), "r"(b[0]), "r"(b[1]));
}
__device__ __forceinline__ void mma_fp(float* c, const uint32_t* a, const uint32_t* b) {
    asm volatile("mma.sync.aligned.m16n8k16.row.col.f32.f16.f16.f32 "
                 "{%0,%1,%2,%3}, {%4,%5,%6,%7}, {%8,%9}, {%0,%1,%2,%3};"
                 : "+f"(c[0]), "+f"(c[1]), "+f"(c[2]), "+f"(c[3])
                 : "r"(a[0]), "r"(a[1]), "r"(a[2]), "r"(a[3]), "r"(b[0]), "r"(b[1]));
}

// shared epilogue writer
template<int OUT, typename ET>
__device__ __forceinline__ void epi_store(
    float v0, float v1, float v2, float v3,
    int gm0, int gn, int M, int ldc, long long cbase,
    float* C, ET* Ch, ET* Cl, ET* Dh, ET* Dl,
    const float* bias2, const float* bias3)
{
    if (OUT == 0) {
        if (gm0 < M) {
            float2 w; w.x = v0; w.y = v1;
            *(float2*)(C + cbase + (long long)gm0 * ldc + gn) = w;
        }
        if (gm0 + 8 < M) {
            float2 w; w.x = v2; w.y = v3;
            *(float2*)(C + cbase + (long long)(gm0 + 8) * ldc + gn) = w;
        }
    } else if (OUT == 3) {
        float2 b2 = *(const float2*)(bias2 + gn);
        float2 b3 = *(const float2*)(bias3 + gn);
        ET h0, l0, h1, l1;
        if (gm0 < M) {
            long long o = cbase + (long long)gm0 * ldc + gn;
            split_to(v0 + b2.x, h0, l0); split_to(v1 + b2.y, h1, l1);
            *(uint32_t*)(Ch + o) = pack2(h0, h1); *(uint32_t*)(Cl + o) = pack2(l0, l1);
            split_to(v0 + b3.x, h0, l0); split_to(v1 + b3.y, h1, l1);
            *(uint32_t*)(Dh + o) = pack2(h0, h1); *(uint32_t*)(Dl + o) = pack2(l0, l1);
        }
        if (gm0 + 8 < M) {
            long long o = cbase + (long long)(gm0 + 8) * ldc + gn;
            split_to(v2 + b2.x, h0, l0); split_to(v3 + b2.y, h1, l1);
            *(uint32_t*)(Ch + o) = pack2(h0, h1); *(uint32_t*)(Cl + o) = pack2(l0, l1);
            split_to(v2 + b3.x, h0, l0); split_to(v3 + b3.y, h1, l1);
            *(uint32_t*)(Dh + o) = pack2(h0, h1); *(uint32_t*)(Dl + o) = pack2(l0, l1);
        }
    } else {
        if (OUT == 2) {
            v0 = fmaxf(v0, 0.f); v1 = fmaxf(v1, 0.f);
            v2 = fmaxf(v2, 0.f); v3 = fmaxf(v3, 0.f);
        }
        ET h0, l0, h1, l1;
        if (gm0 < M) {
            long long o = cbase + (long long)gm0 * ldc + gn;
            split_to(v0, h0, l0); split_to(v1, h1, l1);
            *(uint32_t*)(Ch + o) = pack2(h0, h1); *(uint32_t*)(Cl + o) = pack2(l0, l1);
        }
        if (gm0 + 8 < M) {
            long long o = cbase + (long long)(gm0 + 8) * ldc + gn;
            split_to(v2, h0, l0); split_to(v3, h1, l1);
            *(uint32_t*)(Ch + o) = pack2(h0, h1); *(uint32_t*)(Cl + o) = pack2(l0, l1);
        }
    }
}

// ---------------- hgemm2: 128x256 tile, fp16 2-pass (weights single fp16) ------
// C[M,N] = (Ah+Al)[M,K] @ Bh[N,K]^T (+bias). 8 warps of 64x64. 6-stage pipeline.
// ET = epilogue split type (bf16 or __half).
template<int OUT, typename ET>
__global__ __launch_bounds__(256)
void hgemm2(const __half* __restrict__ Ah, const __half* __restrict__ Al,
            const __half* __restrict__ Bh,
            float* __restrict__ C, ET* __restrict__ Ch, ET* __restrict__ Cl,
            ET* __restrict__ Dh, ET* __restrict__ Dl,
            const float* __restrict__ bias,
            const float* __restrict__ bias2, const float* __restrict__ bias3,
            int M, int N, int K, int lda, int ldb, int ldc)
{
    constexpr int STAGE = 16384;   // A-hi 4K, A-lo 4K, B 8K
    extern __shared__ __align__(128) char sm[];
    const uint32_t smb = smem_u32(sm);
    const int tid = threadIdx.x, wid = tid >> 5, lane = tid & 31;
    const int m0 = blockIdx.x * 128, n0 = blockIdx.y * 256;
    const int m_w = (wid & 1) * 64, n_w = (wid >> 1) * 64;

    const int lr = tid >> 1, lc = tid & 1;
    const uint32_t soA = (uint32_t)(lr * 32 + ((lc ^ ((lr >> 2) & 1)) << 4));
    const int ga = min(m0 + lr, M - 1);
    const long long aoff = (long long)ga * lda + lc * 8;
    const int gb = min(n0 + tid, N - 1);
    const long long boff = (long long)gb * ldb;
    const uint32_t soB0 = (uint32_t)(tid * 32 + ((0 ^ ((tid >> 2) & 1)) << 4));
    const uint32_t soB1 = (uint32_t)(tid * 32 + ((1 ^ ((tid >> 2) & 1)) << 4));

    float acc[4][8][4];
    #pragma unroll
    for (int i = 0; i < 4; i++)
        #pragma unroll
        for (int j = 0; j < 8; j++)
            #pragma unroll
            for (int k = 0; k < 4; k++) acc[i][j][k] = 0.f;

    const int NC = K / 16;
    const int NP = NC / 2;

    #pragma unroll
    for (int g = 0; g < 2; g++) {
        #pragma unroll
        for (int s = 0; s < 2; s++) {
            const int ck = 2 * g + s;
            const uint32_t st = smb + (2 * g + s) * STAGE;
            cp16(st + soA,        Ah + aoff + ck * 16);
            cp16(st + 4096 + soA, Al + aoff + ck * 16);
            cp16(st + 8192 + soB0, Bh + boff + ck * 16);
            cp16(st + 8192 + soB1, Bh + boff + ck * 16 + 8);
        }
        asm volatile("cp.async.commit_group;");
    }

    const int rr = lane & 15, ccq = lane >> 4;
    const int rbq = (lane & 7) | ((lane & 16) >> 1);
    const int cbq = (lane >> 3) & 1;

    for (int p = 0; p < NP; p++) {
        asm volatile("cp.async.wait_group 1;");
        __syncthreads();
        {
            const int gidx = p + 2;
            const int sb = (gidx % 3) * 2;
            #pragma unroll
            for (int s = 0; s < 2; s++) {
                const int ck = 2 * gidx + s;
                if (ck < NC) {
                    const uint32_t st = smb + (sb + s) * STAGE;
                    cp16(st + soA,        Ah + aoff + ck * 16);
                    cp16(st + 4096 + soA, Al + aoff + ck * 16);
                    cp16(st + 8192 + soB0, Bh + boff + ck * 16);
                    cp16(st + 8192 + soB1, Bh + boff + ck * 16 + 8);
                }
            }
            asm volatile("cp.async.commit_group;");
        }
        const int cb2 = (p % 3) * 2;
        #pragma unroll
        for (int s = 0; s < 2; s++) {
            const uint32_t st = smb + (cb2 + s) * STAGE;
            uint32_t ah[4][4], al[4][4], bh[4][4];
            #pragma unroll
            for (int mt = 0; mt < 4; mt++) {
                int R = m_w + mt * 16 + rr;
                uint32_t ad = st + R * 32 + ((ccq ^ ((R >> 2) & 1)) << 4);
                ldx4(ah[mt], ad);
                ldx4(al[mt], ad + 4096);
            }
            #pragma unroll
            for (int np = 0; np < 4; np++) {
                int Nr = n_w + np * 16 + rbq;
                uint32_t bd = st + 8192 + Nr * 32 + ((cbq ^ ((Nr >> 2) & 1)) << 4);
                ldx4(bh[np], bd);
            }
            #pragma unroll
            for (int mt = 0; mt < 4; mt++)
                #pragma unroll
                for (int nt = 0; nt < 8; nt++) {
                    const uint32_t* bp = &bh[nt >> 1][(nt & 1) * 2];
                    mma_fp(acc[mt][nt], ah[mt], bp);
                    mma_fp(acc[mt][nt], al[mt], bp);
                }
        }
    }

    #pragma unroll
    for (int mt = 0; mt < 4; mt++) {
        int gm0 = m0 + m_w + mt * 16 + (lane >> 2);
        #pragma unroll
        for (int nt = 0; nt < 8; nt++) {
            int gn = n0 + n_w + nt * 8 + (lane & 3) * 2;
            if (gn >= N) continue;
            float bx = 0.f, by = 0.f;
            if (bias) { float2 bv = *(const float2*)(bias + gn); bx = bv.x; by = bv.y; }
            epi_store<OUT, ET>(acc[mt][nt][0] + bx, acc[mt][nt][1] + by,
                               acc[mt][nt][2] + bx, acc[mt][nt][3] + by,
                               gm0, gn, M, ldc, 0, C, Ch, Cl, Dh, Dl, bias2, bias3);
        }
    }
}

// ---------------- hgemm: 128xBN tile, bf16 3-pass (attention path) -------------
// maskA/maskB dead-tile skips; kclamp for causal K truncation.
template<int BN, int OUT, typename ET>
__global__ __launch_bounds__(256)
void hgemm(const bf16* __restrict__ Ah, const bf16* __restrict__ Al,
           const bf16* __restrict__ Bh, const bf16* __restrict__ Bl,
           float* __restrict__ C, ET* __restrict__ Ch, ET* __restrict__ Cl,
           const float* __restrict__ bias,
           int M, int N, int K, int lda, int ldb, int ldc, int Z2,
           long long sA1, long long sA2, long long sB1, long long sB2,
           long long sC1, long long sC2,
           int maskA, int maskB, int kclamp)
{
    constexpr int BSTR = BN * 32;
    constexpr int STAGE = 8192 + 2 * BSTR;
    constexpr int MT = (BN == 128) ? 4 : 2;
    extern __shared__ __align__(128) char sm[];
    const uint32_t smb = smem_u32(sm);
    const int tid = threadIdx.x, wid = tid >> 5, lane = tid & 31;
    const int m0 = blockIdx.x * 128, n0 = blockIdx.y * BN;
    if (maskA >= 0 && n0 > m0 + maskA) return;
    if (maskB >= 0 && m0 + n0 < maskB) return;
    const int Keff = (kclamp >= 0) ? min(K, m0 + kclamp) : K;

    const int m_w = (BN == 128) ? (wid & 1) * 64 : (wid & 3) * 32;
    const int n_w = (BN == 128) ? (wid >> 1) * 32 : (wid >> 2) * 32;

    const int z = blockIdx.z;
    const int z1 = z / Z2, z2 = z - z1 * Z2;
    Ah += z1 * sA1 + z2 * sA2;  Al += z1 * sA1 + z2 * sA2;
    Bh += z1 * sB1 + z2 * sB2;  Bl += z1 * sB1 + z2 * sB2;
    const long long cbase = z1 * sC1 + z2 * sC2;

    const int lr = tid >> 1, lc = tid & 1;
    const uint32_t so = (uint32_t)(lr * 32 + ((lc ^ ((lr >> 2) & 1)) << 4));
    const int ga = min(m0 + lr, M - 1);
    const long long aoff = (long long)ga * lda + lc * 8;
    const bool bdo = (BN == 128) || (tid < 128);
    const int gb = min(n0 + lr, N - 1);
    const long long boff = (long long)gb * ldb + lc * 8;

    float acc[MT][4][4];
    #pragma unroll
    for (int i = 0; i < MT; i++)
        #pragma unroll
        for (int j = 0; j < 4; j++)
            #pragma unroll
            for (int k = 0; k < 4; k++) acc[i][j][k] = 0.f;

    const int NC = Keff / 16;
    const int NP = NC / 2;

    #pragma unroll
    for (int g = 0; g < 2; g++) {
        #pragma unroll
        for (int s = 0; s < 2; s++) {
            const int ck = 2 * g + s;
            const uint32_t st = smb + (2 * g + s) * STAGE;
            cp16(st + so,        Ah + aoff + ck * 16);
            cp16(st + 4096 + so, Al + aoff + ck * 16);
            if (bdo) {
                cp16(st + 8192 + so, Bh + boff + ck * 16);
                cp16(st + 8192 + BSTR + so, Bl + boff + ck * 16);
            }
        }
        asm volatile("cp.async.commit_group;");
    }

    const int rr = lane & 15, ccq = lane >> 4;
    const int rbq = (lane & 7) | ((lane & 16) >> 1);
    const int cbq = (lane >> 3) & 1;

    for (int p = 0; p < NP; p++) {
        asm volatile("cp.async.wait_group 1;");
        __syncthreads();
        {
            const int gidx = p + 2;
            const int sb = (gidx % 3) * 2;
            #pragma unroll
            for (int s = 0; s < 2; s++) {
                const int ck = 2 * gidx + s;
                if (ck < NC) {
                    const uint32_t st = smb + (sb + s) * STAGE;
                    cp16(st + so,        Ah + aoff + ck * 16);
                    cp16(st + 4096 + so, Al + aoff + ck * 16);
                    if (bdo) {
                        cp16(st + 8192 + so, Bh + boff + ck * 16);
                        cp16(st + 8192 + BSTR + so, Bl + boff + ck * 16);
                    }
                }
            }
            asm volatile("cp.async.commit_group;");
        }
        const int cb2 = (p % 3) * 2;
        #pragma unroll
        for (int s = 0; s < 2; s++) {
            const uint32_t st = smb + (cb2 + s) * STAGE;
            uint32_t ah[MT][4], al[MT][4], bh[2][4], bl[2][4];
            #pragma unroll
            for (int mt = 0; mt < MT; mt++) {
                int R = m_w + mt * 16 + rr;
                uint32_t ad = st + R * 32 + ((ccq ^ ((R >> 2) & 1)) << 4);
                ldx4(ah[mt], ad);
                ldx4(al[mt], ad + 4096);
            }
            #pragma unroll
            for (int np = 0; np < 2; np++) {
                int Nr = n_w + np * 16 + rbq;
                uint32_t bd = st + 8192 + Nr * 32 + ((cbq ^ ((Nr >> 2) & 1)) << 4);
                ldx4(bh[np], bd);
                ldx4(bl[np], bd + BSTR);
            }
            #pragma unroll
            for (int mt = 0; mt < MT; mt++)
                #pragma unroll
                for (int nt = 0; nt < 4; nt++) {
                    const uint32_t* bhp = &bh[nt >> 1][(nt & 1) * 2];
                    const uint32_t* blp = &bl[nt >> 1][(nt & 1) * 2];
                    mma_bf(acc[mt][nt], ah[mt], bhp);
                    mma_bf(acc[mt][nt], ah[mt], blp);
                    mma_bf(acc[mt][nt], al[mt], bhp);
                }
        }
    }

    #pragma unroll
    for (int mt = 0; mt < MT; mt++) {
        int gm0 = m0 + m_w + mt * 16 + (lane >> 2);
        #pragma unroll
        for (int nt = 0; nt < 4; nt++) {
            int gn = n0 + n_w + nt * 8 + (lane & 3) * 2;
            if (gn >= N) continue;
            float bx = 0.f, by = 0.f;
            if (bias) { float2 bv = *(const float2*)(bias + gn); bx = bv.x; by = bv.y; }
            epi_store<OUT, ET>(acc[mt][nt][0] + bx, acc[mt][nt][1] + by,
                               acc[mt][nt][2] + bx, acc[mt][nt][3] + by,
                               gm0, gn, M, ldc, cbase, C, Ch, Cl,
                               (ET*)nullptr, (ET*)nullptr, nullptr, nullptr);
        }
    }
}

// ---------------- reductions ----------------
__device__ __forceinline__ float block_reduce_sum(float v) {
    __shared__ float sm[16];
    __syncthreads();
    #pragma unroll
    for (int o = 16; o > 0; o >>= 1) v += __shfl_xor_sync(0xffffffffu, v, o);
    if ((threadIdx.x & 31) == 0) sm[threadIdx.x >> 5] = v;
    __syncthreads();
    if (threadIdx.x < 32) {
        float x = (threadIdx.x < (blockDim.x >> 5)) ? sm[threadIdx.x] : 0.f;
        #pragma unroll
        for (int o = 8; o > 0; o >>= 1) x += __shfl_xor_sync(0xffffffffu, x, o);
        if (threadIdx.x == 0) sm[0] = x;
    }
    __syncthreads();
    return sm[0];
}
__device__ __forceinline__ float block_reduce_max(float v) {
    __shared__ float sm[16];
    __syncthreads();
    #pragma unroll
    for (int o = 16; o > 0; o >>= 1) v = fmaxf(v, __shfl_xor_sync(0xffffffffu, v, o));
    if ((threadIdx.x & 31) == 0) sm[threadIdx.x >> 5] = v;
    __syncthreads();
    if (threadIdx.x < 32) {
        float x = (threadIdx.x < (blockDim.x >> 5)) ? sm[threadIdx.x] : -3.4e38f;
        #pragma unroll
        for (int o = 8; o > 0; o >>= 1) x = fmaxf(x, __shfl_xor_sync(0xffffffffu, x, o));
        if (threadIdx.x == 0) sm[0] = x;
    }
    __syncthreads();
    return sm[0];
}

// ---------------- small kernels ----------------
__global__ void build_full(const int* __restrict__ tokens,
                           const float* __restrict__ memory,
                           const float* __restrict__ embed,
                           float* __restrict__ x,
                           __half* __restrict__ xh, __half* __restrict__ xl,
                           __half* __restrict__ fullh, __half* __restrict__ fulll)
{
    long long idx = (long long)blockIdx.x * 256 + threadIdx.x;
    const long long tot = (long long)BB * KLEN * UU;
    if (idx >= tot) return;
    int u = (int)(idx % UU);
    long long t = idx / UU;
    int j = (int)(t % KLEN);
    int b = (int)(t / KLEN);
    float v;
    if (j < MEMLEN) {
        v = memory[((long long)b * MEMLEN + j) * UU + u];
    } else {
        int s = j - MEMLEN;
        int tok = tokens[b * SS + s];
        v = embed[(long long)tok * UU + u] * 32.0f;  // sqrt(1024)
        long long xo = ((long long)b * SS + s) * UU + u;
        x[xo] = v;
        __half h, l; split_to(v, h, l);
        xh[xo] = h; xl[xo] = l;
    }
    __half h, l; split_to(v, h, l);
    fullh[idx] = h; fulll[idx] = l;
}

__global__ void pos_embed(__half* __restrict__ relh, __half* __restrict__ rell)
{
    long long idx = (long long)blockIdx.x * 256 + threadIdx.x;
    if (idx >= (long long)KLEN * UU) return;
    int u = (int)(idx % UU);
    int jj = (int)(idx / UU);
    float pos = (float)(KLEN - 1 - jj);
    int i2 = (u < UU / 2) ? u : (u - UU / 2);
    float expo = ((float)(2 * i2)) / (float)UU;
    float invf = expf(-expo * 9.210340371976184f);  // ln(10000)
    float ang = pos * invf;
    float v = (u < UU / 2) ? sinf(ang) : cosf(ang);
    __half h, l; split_to(v, h, l);
    relh[idx] = h; rell[idx] = l;
}

// transpose: W[K,N] fp32 -> single fp16 [N,K]
__global__ void split_T_h(const float* __restrict__ W, __half* __restrict__ hi,
                          int K, int N)
{
    __shared__ float t[32][33];
    int n0 = blockIdx.x * 32, k0 = blockIdx.y * 32;
    #pragma unroll
    for (int i = 0; i < 32; i += 8)
        t[threadIdx.y + i][threadIdx.x] =
            W[(long long)(k0 + threadIdx.y + i) * N + n0 + threadIdx.x];
    __syncthreads();
    #pragma unroll
    for (int i = 0; i < 32; i += 8) {
        float v = t[threadIdx.x][threadIdx.y + i];
        long long o = (long long)(n0 + threadIdx.y + i) * K + k0 + threadIdx.x;
        hi[o] = __float2half(v);
    }
}

// V^T per head (bit-level, bf16): vt[(b*H+h), d, j] = kv[b, j, U + h*64 + d]
__global__ void transpose_v(const bf16* __restrict__ kvh, const bf16* __restrict__ kvl,
                            bf16* __restrict__ vth, bf16* __restrict__ vtl)
{
    __shared__ bf16 th[32][33], tl[32][33];
    int z = blockIdx.z;
    int b = z / HH, h = z % HH;
    int j0 = blockIdx.x * 32, d0 = blockIdx.y * 32;
    int tx = threadIdx.x, ty = threadIdx.y;
    #pragma unroll
    for (int i = 0; i < 32; i += 8) {
        long long src = ((long long)b * KLEN + j0 + ty + i) * (2 * UU) + UU + h * 64 + d0 + tx;
        th[ty + i][tx] = kvh[src];
        tl[ty + i][tx] = kvl[src];
    }
    __syncthreads();
    #pragma unroll
    for (int i = 0; i < 32; i += 8) {
        long long dst = ((long long)z * DD + d0 + ty + i) * KLEN + j0 + tx;
        vth[dst] = th[tx][ty + i];
        vtl[dst] = tl[tx][ty + i];
    }
}

// mask + rel-shift + softmax; writes P as split bf16 (zero tail)
__global__ __launch_bounds__(256)
void attn_softmax(const float* __restrict__ ac, const float* __restrict__ ar,
                  bf16* __restrict__ ph, bf16* __restrict__ pl)
{
    int i = blockIdx.x;
    long long z = blockIdx.y;
    const float* arow = ac + (z * SS + i) * (long long)KLEN;
    const float* rrow = ar + (z * SS + i) * (long long)KLEN;
    bf16* phr = ph + (z * SS + i) * (long long)KLEN;
    bf16* plr = pl + (z * SS + i) * (long long)KLEN;
    int lim = i + MEMLEN;
    int shift = SS - 1 - i;
    int tid = threadIdx.x;

    float vals[7];
    int cnt = 0;
    float lmax = -3.4e38f;
    for (int j = tid; j <= lim; j += 256) {
        float v = (arow[j] + rrow[j + shift]) * 0.125f;
        vals[cnt++] = v;
        lmax = fmaxf(lmax, v);
    }
    float m = block_reduce_max(lmax);
    float lsum = 0.f;
    for (int t = 0; t < cnt; t++) {
        float e = expf(vals[t] - m);
        vals[t] = e;
        lsum += e;
    }
    float s = block_reduce_sum(lsum);
    float inv = 1.f / s;
    cnt = 0;
    for (int j = tid; j <= lim; j += 256) {
        float p = vals[cnt++] * inv;
        bf16 h, l; split_to(p, h, l);
        phr[j] = h; plr[j] = l;
    }
    bf16 z0 = __float2bfloat16(0.f);
    for (int j = lim + 1 + tid; j < KLEN; j += 256) { phr[j] = z0; plr[j] = z0; }
}

// add + LayerNorm; emits fp32 (optional) plus fp16 split pair
__global__ __launch_bounds__(256)
void add_ln(const float* __restrict__ a, const float* __restrict__ b,
            const float* __restrict__ g, const float* __restrict__ beta,
            float* __restrict__ out, __half* __restrict__ oh, __half* __restrict__ ol)
{
    long long row = blockIdx.x;
    const float* pa = a + row * UU;
    const float* pb = b + row * UU;
    int tid = threadIdx.x;
    float vals[4];
    float s = 0.f, ss = 0.f;
    #pragma unroll
    for (int t = 0; t < 4; t++) {
        int idx = tid * 4 + t;
        float v = pa[idx] + pb[idx];
        vals[t] = v;
        s += v;
        ss += v * v;
    }
    s = block_reduce_sum(s);
    ss = block_reduce_sum(ss);
    float mean = s * (1.f / UU);
    float var = fmaxf(ss * (1.f / UU) - mean * mean, 0.f);
    float rstd = rsqrtf(var + 1e-5f);
    #pragma unroll
    for (int t = 0; t < 4; t++) {
        int idx = tid * 4 + t;
        float v = (vals[t] - mean) * rstd * g[idx] + beta[idx];
        if (out) out[row * UU + idx] = v;
        __half h, l; split_to(v, h, l);
        oh[row * UU + idx] = h; ol[row * UU + idx] = l;
    }
}

// online-softmax over vocab rows, in place
__global__ __launch_bounds__(512)
void softmax_rows(float* __restrict__ x, int N)
{
    __shared__ float smm[16], sms[16];
    long long row = blockIdx.x;
    float* p = x + row * (long long)N;
    int tid = threadIdx.x;
    float m = -3.4e38f, s = 0.f;
    for (int j = tid; j < N; j += 512) {
        float v = p[j];
        if (v > m) { s = s * expf(m - v) + 1.f; m = v; }
        else       { s += expf(v - m); }
    }
    #pragma unroll
    for (int o = 16; o > 0; o >>= 1) {
        float m2 = __shfl_xor_sync(0xffffffffu, m, o);
        float s2 = __shfl_xor_sync(0xffffffffu, s, o);
        float M = fmaxf(m, m2);
        s = s * expf(m - M) + s2 * expf(m2 - M);
        m = M;
    }
    if ((tid & 31) == 0) { smm[tid >> 5] = m; sms[tid >> 5] = s; }
    __syncthreads();
    if (tid < 32) {
        float mm = (tid < 16) ? smm[tid] : -3.4e38f;
        float ssv = (tid < 16) ? sms[tid] : 0.f;
        #pragma unroll
        for (int o = 8; o > 0; o >>= 1) {
            float m2 = __shfl_xor_sync(0xffffffffu, mm, o);
            float s2 = __shfl_xor_sync(0xffffffffu, ssv, o);
            float M = fmaxf(mm, m2);
            ssv = ssv * expf(mm - M) + s2 * expf(m2 - M);
            mm = M;
        }
        if (tid == 0) { smm[0] = mm; sms[0] = ssv; }
    }
    __syncthreads();
    float M = smm[0];
    float inv = 1.f / sms[0];
    for (int j = tid; j < N; j += 512) p[j] = expf(p[j] - M) * inv;
}

// ---------------- host ----------------
#define SMEM_G2 (6 * 16384)
#define SMEM_G(BN) (6 * (8192 + 2 * (BN) * 32))

extern "C" void kernel_launch(void* const* d_in, const int* in_sizes, int n_in,
                              void* d_out, int out_size)
{
    const int*   tokens  = (const int*)  d_in[0];
    const float* memory  = (const float*)d_in[1];
    const float* embed   = (const float*)d_in[2];
    const float* Wq      = (const float*)d_in[3];
    const float* Wkv     = (const float*)d_in[4];
    const float* Wr      = (const float*)d_in[5];
    const float* Wo      = (const float*)d_in[6];
    const float* bq      = (const float*)d_in[7];
    const float* bkv     = (const float*)d_in[8];
    const float* br      = (const float*)d_in[9];
    const float* bo      = (const float*)d_in[10];
    const float* bias_c  = (const float*)d_in[11];
    const float* bias_r  = (const float*)d_in[12];
    const float* ln1_g   = (const float*)d_in[13];
    const float* ln1_b   = (const float*)d_in[14];
    const float* W1      = (const float*)d_in[15];
    const float* b1      = (const float*)d_in[16];
    const float* W2      = (const float*)d_in[17];
    const float* b2      = (const float*)d_in[18];
    const float* ln2_g   = (const float*)d_in[19];
    const float* ln2_b   = (const float*)d_in[20];
    const float* Wout    = (const float*)d_in[21];
    const float* bout    = (const float*)d_in[22];
    float* out = (float*)d_out;

    static bool s_attr = false;
    if (!s_attr) {
        cudaFuncSetAttribute(hgemm2<0, __half>, cudaFuncAttributeMaxDynamicSharedMemorySize, SMEM_G2);
        cudaFuncSetAttribute(hgemm2<1, bf16>,   cudaFuncAttributeMaxDynamicSharedMemorySize, SMEM_G2);
        cudaFuncSetAttribute(hgemm2<2, __half>, cudaFuncAttributeMaxDynamicSharedMemorySize, SMEM_G2);
        cudaFuncSetAttribute(hgemm2<3, bf16>,   cudaFuncAttributeMaxDynamicSharedMemorySize, SMEM_G2);
        cudaFuncSetAttribute(hgemm<128,0,bf16>, cudaFuncAttributeMaxDynamicSharedMemorySize, SMEM_G(128));
        cudaFuncSetAttribute(hgemm<64,1,__half>, cudaFuncAttributeMaxDynamicSharedMemorySize, SMEM_G(64));
        s_attr = true;
    }

    float *x, *ac, *ar, *tmp, *h1;
    cudaGetSymbolAddress((void**)&x,   g_x);
    cudaGetSymbolAddress((void**)&ac,  g_ac);
    cudaGetSymbolAddress((void**)&ar,  g_ar);
    cudaGetSymbolAddress((void**)&tmp, g_tmp);
    cudaGetSymbolAddress((void**)&h1,  g_h1);

    __half *xh,*xl,*fullh,*fulll,*relh,*rell,*ctxh,*ctxl,*h1hh,*h1lh,*ffhh,*fflh,*h2hh,*h2lh;
    bf16 *qch,*qcl,*qrh,*qrl,*kvh,*kvl,*rh,*rl,*ph,*pl,*vth,*vtl;
    __half *WqH,*WkvH,*WrH,*WoH,*W1H,*W2H,*WoutH;
    cudaGetSymbolAddress((void**)&xh, g_xh);       cudaGetSymbolAddress((void**)&xl, g_xl);
    cudaGetSymbolAddress((void**)&fullh, g_fullh); cudaGetSymbolAddress((void**)&fulll, g_fulll);
    cudaGetSymbolAddress((void**)&relh, g_relh);   cudaGetSymbolAddress((void**)&rell, g_rell);
    cudaGetSymbolAddress((void**)&ctxh, g_ctxh);   cudaGetSymbolAddress((void**)&ctxl, g_ctxl);
    cudaGetSymbolAddress((void**)&h1hh, g_h1hh);   cudaGetSymbolAddress((void**)&h1lh, g_h1lh);
    cudaGetSymbolAddress((void**)&ffhh, g_ffhh);   cudaGetSymbolAddress((void**)&fflh, g_fflh);
    cudaGetSymbolAddress((void**)&h2hh, g_h2hh);   cudaGetSymbolAddress((void**)&h2lh, g_h2lh);
    cudaGetSymbolAddress((void**)&qch, g_qch);     cudaGetSymbolAddress((void**)&qcl, g_qcl);
    cudaGetSymbolAddress((void**)&qrh, g_qrh);     cudaGetSymbolAddress((void**)&qrl, g_qrl);
    cudaGetSymbolAddress((void**)&kvh, g_kvh);     cudaGetSymbolAddress((void**)&kvl, g_kvl);
    cudaGetSymbolAddress((void**)&rh, g_rh);       cudaGetSymbolAddress((void**)&rl, g_rl);
    cudaGetSymbolAddress((void**)&ph, g_ph);       cudaGetSymbolAddress((void**)&pl, g_pl);
    cudaGetSymbolAddress((void**)&vth, g_vth);     cudaGetSymbolAddress((void**)&vtl, g_vtl);
    cudaGetSymbolAddress((void**)&WqH, g_WqH);     cudaGetSymbolAddress((void**)&WkvH, g_WkvH);
    cudaGetSymbolAddress((void**)&WrH, g_WrH);     cudaGetSymbolAddress((void**)&WoH, g_WoH);
    cudaGetSymbolAddress((void**)&W1H, g_W1H);     cudaGetSymbolAddress((void**)&W2H, g_W2H);
    cudaGetSymbolAddress((void**)&WoutH, g_WoutH);

    const int M_TOK = BB * SS;      // 2048
    const int M_FULL = BB * KLEN;   // 3200
    dim3 tb(32, 8);

    // 1) embedding + concat + fp16 splits
    {
        long long tot = (long long)BB * KLEN * UU;
        build_full<<<(unsigned)((tot + 255) / 256), 256>>>(tokens, memory, embed,
                                                           x, xh, xl, fullh, fulll);
    }
    // 2) Wkv -> fp16
    split_T_h<<<dim3(2*UU/32, UU/32), tb>>>(Wkv, WkvH, UU, 2*UU);
    // 3) positional embedding
    {
        long long tot = (long long)KLEN * UU;
        pos_embed<<<(unsigned)((tot + 255) / 256), 256>>>(relh, rell);
    }
    // 4) kv projection (hgemm2)  <-- ncu capture target (4th launch)
    hgemm2<1, bf16><<<dim3(M_FULL/128, 2*UU/256), 256, SMEM_G2>>>(
        fullh, fulll, WkvH, nullptr, kvh, kvl, nullptr, nullptr,
        bkv, nullptr, nullptr, M_FULL, 2*UU, UU, UU, UU, 2*UU);
    // remaining weight conversions
    split_T_h<<<dim3(UU/32,  UU/32),  tb>>>(Wq,   WqH,   UU,  UU);
    split_T_h<<<dim3(UU/32,  UU/32),  tb>>>(Wr,   WrH,   UU,  UU);
    split_T_h<<<dim3(UU/32,  UU/32),  tb>>>(Wo,   WoH,   UU,  UU);
    split_T_h<<<dim3(FFD/32, UU/32),  tb>>>(W1,   W1H,   UU,  FFD);
    split_T_h<<<dim3(UU/32,  FFD/32), tb>>>(W2,   W2H,   FFD, UU);
    split_T_h<<<dim3(NT/32,  UU/32),  tb>>>(Wout, WoutH, UU,  NT);
    // q projection fused with (q+u)/(q+v) bf16 splits
    hgemm2<3, bf16><<<dim3(M_TOK/128, UU/256), 256, SMEM_G2>>>(
        xh, xl, WqH, nullptr, qch, qcl, qrh, qrl,
        bq, bias_c, bias_r, M_TOK, UU, UU, UU, UU, UU);
    // r projection
    hgemm2<1, bf16><<<dim3((KLEN+127)/128, UU/256), 256, SMEM_G2>>>(
        relh, rell, WrH, nullptr, rh, rl, nullptr, nullptr,
        br, nullptr, nullptr, KLEN, UU, UU, UU, UU, UU);
    // scores (bf16 3-pass, batched over b,h), dead-tile skips
    {
        dim3 grid(SS / 128, (KLEN + 127) / 128, BB * HH);
        hgemm<128,0,bf16><<<grid, 256, SMEM_G(128)>>>(qch, qcl, kvh, kvl, ac,
            (bf16*)nullptr, (bf16*)nullptr, nullptr,
            SS, KLEN, DD, UU, 2*UU, KLEN, HH,
            (long long)SS*UU, 64,
            (long long)KLEN*2*UU, 64,
            (long long)HH*SS*KLEN, (long long)SS*KLEN,
            MEMLEN + 127, -1, -1);
        hgemm<128,0,bf16><<<grid, 256, SMEM_G(128)>>>(qrh, qrl, rh, rl, ar,
            (bf16*)nullptr, (bf16*)nullptr, nullptr,
            SS, KLEN, DD, UU, UU, KLEN, HH,
            (long long)SS*UU, 64,
            0, 64,
            (long long)HH*SS*KLEN, (long long)SS*KLEN,
            -1, SS - 255, -1);
    }
    // fused rel-shift + mask + softmax -> split P (bf16)
    {
        dim3 grid(SS, BB * HH);
        attn_softmax<<<grid, 256>>>(ac, ar, ph, pl);
    }
    // V^T per head
    {
        dim3 grid(KLEN / 32, DD / 32, BB * HH);
        transpose_v<<<grid, tb>>>(kvh, kvl, vth, vtl);
    }
    // ctx = P @ V^T (bf16 3-pass, K clamp), fp16 split output
    {
        dim3 grid(SS / 128, 1, BB * HH);
        hgemm<64,1,__half><<<grid, 256, SMEM_G(64)>>>(ph, pl, vth, vtl, nullptr,
            ctxh, ctxl, nullptr,
            SS, DD, KLEN, KLEN, KLEN, UU, HH,
            (long long)HH*SS*KLEN, (long long)SS*KLEN,
            (long long)HH*DD*KLEN, (long long)DD*KLEN,
            (long long)SS*UU, 64,
            -1, -1, MEMLEN + 128);
    }
    // attention out projection + LN1
    hgemm2<0, __half><<<dim3(M_TOK/128, UU/256), 256, SMEM_G2>>>(
        ctxh, ctxl, WoH, tmp, nullptr, nullptr, nullptr, nullptr,
        bo, nullptr, nullptr, M_TOK, UU, UU, UU, UU, UU);
    add_ln<<<M_TOK, 256>>>(x, tmp, ln1_g, ln1_b, h1, h1hh, h1lh);
    // FF
    hgemm2<2, __half><<<dim3(M_TOK/128, FFD/256), 256, SMEM_G2>>>(
        h1hh, h1lh, W1H, nullptr, ffhh, fflh, nullptr, nullptr,
        b1, nullptr, nullptr, M_TOK, FFD, UU, UU, UU, FFD);
    hgemm2<0, __half><<<dim3(M_TOK/128, UU/256), 256, SMEM_G2>>>(
        ffhh, fflh, W2H, tmp, nullptr, nullptr, nullptr, nullptr,
        b2, nullptr, nullptr, M_TOK, UU, FFD, FFD, FFD, UU);
    add_ln<<<M_TOK, 256>>>(h1, tmp, ln2_g, ln2_b, nullptr, h2hh, h2lh);
    // logits + softmax
    hgemm2<0, __half><<<dim3(M_TOK/128, NT/256), 256, SMEM_G2>>>(
        h2hh, h2lh, WoutH, out, nullptr, nullptr, nullptr, nullptr,
        bout, nullptr, nullptr, M_TOK, NT, UU, UU, UU, NT);
    softmax_rows<<<M_TOK, 512>>>(out, NT);
}

// round 13
// speedup vs baseline: 1.3665x; 1.3663x over previous
#include <cuda_runtime.h>
#include <cuda_bf16.h>
#include <cuda_fp16.h>
#include <math.h>
#include <stdint.h>

// ---------------- problem constants ----------------
#define BB 2
#define SS 1024
#define UU 1024
#define HH 16
#define DD 64
#define NT 32000
#define MEMLEN 576
#define FFD 4096
#define KLEN 1600   // MEM + S
#define VOCAB 1024

typedef __nv_bfloat16 bf16;

// ---------------- scratch (device globals; no allocation allowed) ----------------
__device__ float g_ac  [(size_t)BB*HH*SS*KLEN];
__device__ float g_ar  [(size_t)BB*HH*SS*KLEN];
__device__ float g_x   [(size_t)BB*SS*UU];
__device__ float g_tmp [(size_t)BB*SS*UU];
__device__ float g_h1  [(size_t)BB*SS*UU];

// fp16 A-side splits
__device__ __half g_xh   [(size_t)BB*SS*UU],   g_xl   [(size_t)BB*SS*UU];
__device__ __half g_fullh[(size_t)BB*KLEN*UU], g_fulll[(size_t)BB*KLEN*UU];
__device__ __half g_relh [(size_t)KLEN*UU],    g_rell [(size_t)KLEN*UU];
__device__ __half g_ctxh [(size_t)BB*SS*UU],   g_ctxl [(size_t)BB*SS*UU];
__device__ __half g_h1hh [(size_t)BB*SS*UU],   g_h1lh [(size_t)BB*SS*UU];
__device__ __half g_ffhh [(size_t)BB*SS*FFD],  g_fflh [(size_t)BB*SS*FFD];
__device__ __half g_h2hh [(size_t)BB*SS*UU],   g_h2lh [(size_t)BB*SS*UU];
// bf16 splits (attention internal path)
__device__ bf16 g_qch  [(size_t)BB*SS*UU],   g_qcl  [(size_t)BB*SS*UU];
__device__ bf16 g_qrh  [(size_t)BB*SS*UU],   g_qrl  [(size_t)BB*SS*UU];
__device__ bf16 g_kvh  [(size_t)BB*KLEN*2*UU], g_kvl [(size_t)BB*KLEN*2*UU];
__device__ bf16 g_rh   [(size_t)KLEN*UU],    g_rl   [(size_t)KLEN*UU];
__device__ bf16 g_ph   [(size_t)BB*HH*SS*KLEN], g_pl [(size_t)BB*HH*SS*KLEN];
__device__ bf16 g_vth  [(size_t)BB*HH*DD*KLEN], g_vtl[(size_t)BB*HH*DD*KLEN];
// single-fp16 transposed weights [N,K]
__device__ __half g_WqH [(size_t)UU*UU];
__device__ __half g_WkvH[(size_t)2*UU*UU];
__device__ __half g_WrH [(size_t)UU*UU];
__device__ __half g_WoH [(size_t)UU*UU];
__device__ __half g_W1H [(size_t)FFD*UU];
__device__ __half g_W2H [(size_t)UU*FFD];
__device__ __half g_WoutH[(size_t)NT*UU];

// ---------------- helpers ----------------
__device__ __forceinline__ uint32_t smem_u32(const void* p) {
    uint32_t a;
    asm("{ .reg .u64 t; cvta.to.shared.u64 t, %1; cvt.u32.u64 %0, t; }" : "=r"(a) : "l"(p));
    return a;
}
__device__ __forceinline__ void split_to(float v, bf16& h, bf16& l) {
    h = __float2bfloat16(v);
    l = __float2bfloat16(v - __bfloat162float(h));
}
__device__ __forceinline__ void split_to(float v, __half& h, __half& l) {
    h = __float2half(v);
    l = __float2half(v - __half2float(h));
}
template<typename T>
__device__ __forceinline__ uint32_t pack2(T a, T b) {
    unsigned short x = *(unsigned short*)&a, y = *(unsigned short*)&b;
    return (uint32_t)x | ((uint32_t)y << 16);
}
__device__ __forceinline__ void cp16(uint32_t dst, const void* src) {
    asm volatile("cp.async.cg.shared.global [%0], [%1], 16;" :: "r"(dst), "l"(src));
}
__device__ __forceinline__ void ldx4(uint32_t* r, uint32_t addr) {
    asm volatile("ldmatrix.sync.aligned.m8n8.x4.shared.b16 {%0,%1,%2,%3}, [%4];"
                 : "=r"(r[0]), "=r"(r[1]), "=r"(r[2]), "=r"(r[3]) : "r"(addr));
}
__device__ __forceinline__ void mma_bf(float* c, const uint32_t* a, const uint32_t* b) {
    asm volatile("mma.sync.aligned.m16n8k16.row.col.f32.bf16.bf16.f32 "
                 "{%0,%1,%2,%3}, {%4,%5,%6,%7}, {%8,%9}, {%0,%1,%2,%3};"
                 : "+f"(c[0]), "+f"(c[1]), "+f"(c[2]), "+f"(c[3])
                 : "r"(a[0]), "r"(a[1]), "r"(a[2]), "r"(a[3]), "r"(b[0]), "r"(b[1]));
}
__device__ __forceinline__ void mma_fp(float* c, const uint32_t* a, const uint32_t* b) {
    asm volatile("mma.sync.aligned.m16n8k16.row.col.f32.f16.f16.f32 "
                 "{%0,%1,%2,%3}, {%4,%5,%6,%7}, {%8,%9}, {%0,%1,%2,%3};"
                 : "+f"(c[0]), "+f"(c[1]), "+f"(c[2]), "+f"(c[3])
                 : "r"(a[0]), "r"(a[1]), "r"(a[2]), "r"(a[3]), "r"(b[0]), "r"(b[1]));
}

// shared epilogue writer
template<int OUT, typename ET>
__device__ __forceinline__ void epi_store(
    float v0, float v1, float v2, float v3,
    int gm0, int gn, int M, int ldc, long long cbase,
    float* C, ET* Ch, ET* Cl, ET* Dh, ET* Dl,
    const float* bias2, const float* bias3)
{
    if (OUT == 0) {
        if (gm0 < M) {
            float2 w; w.x = v0; w.y = v1;
            *(float2*)(C + cbase + (long long)gm0 * ldc + gn) = w;
        }
        if (gm0 + 8 < M) {
            float2 w; w.x = v2; w.y = v3;
            *(float2*)(C + cbase + (long long)(gm0 + 8) * ldc + gn) = w;
        }
    } else if (OUT == 3) {
        float2 b2 = *(const float2*)(bias2 + gn);
        float2 b3 = *(const float2*)(bias3 + gn);
        ET h0, l0, h1, l1;
        if (gm0 < M) {
            long long o = cbase + (long long)gm0 * ldc + gn;
            split_to(v0 + b2.x, h0, l0); split_to(v1 + b2.y, h1, l1);
            *(uint32_t*)(Ch + o) = pack2(h0, h1); *(uint32_t*)(Cl + o) = pack2(l0, l1);
            split_to(v0 + b3.x, h0, l0); split_to(v1 + b3.y, h1, l1);
            *(uint32_t*)(Dh + o) = pack2(h0, h1); *(uint32_t*)(Dl + o) = pack2(l0, l1);
        }
        if (gm0 + 8 < M) {
            long long o = cbase + (long long)(gm0 + 8) * ldc + gn;
            split_to(v2 + b2.x, h0, l0); split_to(v3 + b2.y, h1, l1);
            *(uint32_t*)(Ch + o) = pack2(h0, h1); *(uint32_t*)(Cl + o) = pack2(l0, l1);
            split_to(v2 + b3.x, h0, l0); split_to(v3 + b3.y, h1, l1);
            *(uint32_t*)(Dh + o) = pack2(h0, h1); *(uint32_t*)(Dl + o) = pack2(l0, l1);
        }
    } else {
        if (OUT == 2) {
            v0 = fmaxf(v0, 0.f); v1 = fmaxf(v1, 0.f);
            v2 = fmaxf(v2, 0.f); v3 = fmaxf(v3, 0.f);
        }
        ET h0, l0, h1, l1;
        if (gm0 < M) {
            long long o = cbase + (long long)gm0 * ldc + gn;
            split_to(v0, h0, l0); split_to(v1, h1, l1);
            *(uint32_t*)(Ch + o) = pack2(h0, h1); *(uint32_t*)(Cl + o) = pack2(l0, l1);
        }
        if (gm0 + 8 < M) {
            long long o = cbase + (long long)(gm0 + 8) * ldc + gn;
            split_to(v2, h0, l0); split_to(v3, h1, l1);
            *(uint32_t*)(Ch + o) = pack2(h0, h1); *(uint32_t*)(Cl + o) = pack2(l0, l1);
        }
    }
}

// ---------------- generalized HMMA split GEMM (R8 mainloop) ----------------
// PASS=3 (bf16): C = (Ah+Al) @ (Bh+Bl)^T via hh + hl + lh  (A,B bf16 hi/lo).
// PASS=2 (fp16): C = (Ah+Al) @ Bh^T via hh + lh            (A fp16 hi/lo, B single fp16).
// 4-stage cp.async pipeline, ONE barrier per K16 chunk (best measured config).
// maskA/maskB: dead-tile skips. kclamp: effective K = min(K, m0+kclamp).
// OUT: 0 = fp32 C (+bias); 1 = split ET; 2 = relu + split ET; 3 = dual-bias split ET.
// Element pointers are declared bf16; for PASS=2 they carry fp16 bits (MMA decides type).
template<int BN, int OUT, int PASS, typename ET>
__global__ __launch_bounds__(256)
void hgemm(const bf16* __restrict__ Ah, const bf16* __restrict__ Al,
           const bf16* __restrict__ Bh, const bf16* __restrict__ Bl,
           float* __restrict__ C, ET* __restrict__ Ch, ET* __restrict__ Cl,
           ET* __restrict__ Dh, ET* __restrict__ Dl,
           const float* __restrict__ bias,
           const float* __restrict__ bias2, const float* __restrict__ bias3,
           int M, int N, int K, int lda, int ldb, int ldc, int Z2,
           long long sA1, long long sA2, long long sB1, long long sB2,
           long long sC1, long long sC2,
           int maskA, int maskB, int kclamp)
{
    constexpr int BSTR = BN * 32;
    constexpr int STAGE = 8192 + (PASS == 3 ? 2 : 1) * BSTR;
    constexpr int MT = (BN == 128) ? 4 : 2;
    extern __shared__ __align__(128) char sm[];
    const uint32_t smb = smem_u32(sm);
    const int tid = threadIdx.x, wid = tid >> 5, lane = tid & 31;
    const int m0 = blockIdx.x * 128, n0 = blockIdx.y * BN;
    if (maskA >= 0 && n0 > m0 + maskA) return;
    if (maskB >= 0 && m0 + n0 < maskB) return;
    const int Keff = (kclamp >= 0) ? min(K, m0 + kclamp) : K;

    const int m_w = (BN == 128) ? (wid & 1) * 64 : (wid & 3) * 32;
    const int n_w = (BN == 128) ? (wid >> 1) * 32 : (wid >> 2) * 32;

    const int z = blockIdx.z;
    const int z1 = z / Z2, z2 = z - z1 * Z2;
    Ah += z1 * sA1 + z2 * sA2;  Al += z1 * sA1 + z2 * sA2;
    Bh += z1 * sB1 + z2 * sB2;
    if (PASS == 3) Bl += z1 * sB1 + z2 * sB2;
    const long long cbase = z1 * sC1 + z2 * sC2;

    const int lr = tid >> 1, lc = tid & 1;
    const uint32_t so = (uint32_t)(lr * 32 + ((lc ^ ((lr >> 2) & 1)) << 4));
    const int ga = min(m0 + lr, M - 1);
    const long long aoff = (long long)ga * lda + lc * 8;
    const bool bdo = (BN == 128) || (tid < 128);
    const int gb = min(n0 + lr, N - 1);
    const long long boff = (long long)gb * ldb + lc * 8;

    float acc[MT][4][4];
    #pragma unroll
    for (int i = 0; i < MT; i++)
        #pragma unroll
        for (int j = 0; j < 4; j++)
            #pragma unroll
            for (int k = 0; k < 4; k++) acc[i][j][k] = 0.f;

    const int NC = Keff / 16;

    // prologue: stages 0,1,2
    #pragma unroll
    for (int pc = 0; pc < 3; pc++) {
        const uint32_t st = smb + pc * STAGE;
        cp16(st + so,        Ah + aoff + pc * 16);
        cp16(st + 4096 + so, Al + aoff + pc * 16);
        if (bdo) {
            cp16(st + 8192 + so, Bh + boff + pc * 16);
            if (PASS == 3) cp16(st + 8192 + BSTR + so, Bl + boff + pc * 16);
        }
        asm volatile("cp.async.commit_group;");
    }

    const int rr = lane & 15, ccq = lane >> 4;
    const int rbq = (lane & 7) | ((lane & 16) >> 1);
    const int cbq = (lane >> 3) & 1;

    for (int c = 0; c < NC; c++) {
        asm volatile("cp.async.wait_group 2;");
        __syncthreads();
        if (c + 3 < NC) {
            const uint32_t st = smb + ((c + 3) & 3) * STAGE;
            const long long k0 = (long long)(c + 3) * 16;
            cp16(st + so,        Ah + aoff + k0);
            cp16(st + 4096 + so, Al + aoff + k0);
            if (bdo) {
                cp16(st + 8192 + so, Bh + boff + k0);
                if (PASS == 3) cp16(st + 8192 + BSTR + so, Bl + boff + k0);
            }
        }
        asm volatile("cp.async.commit_group;");

        const uint32_t st = smb + (c & 3) * STAGE;
        uint32_t ah[MT][4], al[MT][4], bh[2][4], bl[2][4];
        #pragma unroll
        for (int mt = 0; mt < MT; mt++) {
            int R = m_w + mt * 16 + rr;
            uint32_t ad = st + R * 32 + ((ccq ^ ((R >> 2) & 1)) << 4);
            ldx4(ah[mt], ad);
            ldx4(al[mt], ad + 4096);
        }
        #pragma unroll
        for (int np = 0; np < 2; np++) {
            int Nr = n_w + np * 16 + rbq;
            uint32_t bd = st + 8192 + Nr * 32 + ((cbq ^ ((Nr >> 2) & 1)) << 4);
            ldx4(bh[np], bd);
            if (PASS == 3) ldx4(bl[np], bd + BSTR);
        }
        #pragma unroll
        for (int mt = 0; mt < MT; mt++)
            #pragma unroll
            for (int nt = 0; nt < 4; nt++) {
                const uint32_t* bhp = &bh[nt >> 1][(nt & 1) * 2];
                if (PASS == 3) {
                    const uint32_t* blp = &bl[nt >> 1][(nt & 1) * 2];
                    mma_bf(acc[mt][nt], ah[mt], bhp);
                    mma_bf(acc[mt][nt], ah[mt], blp);
                    mma_bf(acc[mt][nt], al[mt], bhp);
                } else {
                    mma_fp(acc[mt][nt], ah[mt], bhp);
                    mma_fp(acc[mt][nt], al[mt], bhp);
                }
            }
    }

    // ---- epilogue ----
    #pragma unroll
    for (int mt = 0; mt < MT; mt++) {
        int gm0 = m0 + m_w + mt * 16 + (lane >> 2);
        #pragma unroll
        for (int nt = 0; nt < 4; nt++) {
            int gn = n0 + n_w + nt * 8 + (lane & 3) * 2;
            if (gn >= N) continue;
            float bx = 0.f, by = 0.f;
            if (bias) { float2 bv = *(const float2*)(bias + gn); bx = bv.x; by = bv.y; }
            epi_store<OUT, ET>(acc[mt][nt][0] + bx, acc[mt][nt][1] + by,
                               acc[mt][nt][2] + bx, acc[mt][nt][3] + by,
                               gm0, gn, M, ldc, cbase, C, Ch, Cl, Dh, Dl, bias2, bias3);
        }
    }
}

// ---------------- reductions ----------------
__device__ __forceinline__ float block_reduce_sum(float v) {
    __shared__ float sm[16];
    __syncthreads();
    #pragma unroll
    for (int o = 16; o > 0; o >>= 1) v += __shfl_xor_sync(0xffffffffu, v, o);
    if ((threadIdx.x & 31) == 0) sm[threadIdx.x >> 5] = v;
    __syncthreads();
    if (threadIdx.x < 32) {
        float x = (threadIdx.x < (blockDim.x >> 5)) ? sm[threadIdx.x] : 0.f;
        #pragma unroll
        for (int o = 8; o > 0; o >>= 1) x += __shfl_xor_sync(0xffffffffu, x, o);
        if (threadIdx.x == 0) sm[0] = x;
    }
    __syncthreads();
    return sm[0];
}
__device__ __forceinline__ float block_reduce_max(float v) {
    __shared__ float sm[16];
    __syncthreads();
    #pragma unroll
    for (int o = 16; o > 0; o >>= 1) v = fmaxf(v, __shfl_xor_sync(0xffffffffu, v, o));
    if ((threadIdx.x & 31) == 0) sm[threadIdx.x >> 5] = v;
    __syncthreads();
    if (threadIdx.x < 32) {
        float x = (threadIdx.x < (blockDim.x >> 5)) ? sm[threadIdx.x] : -3.4e38f;
        #pragma unroll
        for (int o = 8; o > 0; o >>= 1) x = fmaxf(x, __shfl_xor_sync(0xffffffffu, x, o));
        if (threadIdx.x == 0) sm[0] = x;
    }
    __syncthreads();
    return sm[0];
}

// ---------------- small kernels ----------------
__global__ void build_full(const int* __restrict__ tokens,
                           const float* __restrict__ memory,
                           const float* __restrict__ embed,
                           float* __restrict__ x,
                           __half* __restrict__ xh, __half* __restrict__ xl,
                           __half* __restrict__ fullh, __half* __restrict__ fulll)
{
    long long idx = (long long)blockIdx.x * 256 + threadIdx.x;
    const long long tot = (long long)BB * KLEN * UU;
    if (idx >= tot) return;
    int u = (int)(idx % UU);
    long long t = idx / UU;
    int j = (int)(t % KLEN);
    int b = (int)(t / KLEN);
    float v;
    if (j < MEMLEN) {
        v = memory[((long long)b * MEMLEN + j) * UU + u];
    } else {
        int s = j - MEMLEN;
        int tok = tokens[b * SS + s];
        v = embed[(long long)tok * UU + u] * 32.0f;  // sqrt(1024)
        long long xo = ((long long)b * SS + s) * UU + u;
        x[xo] = v;
        __half h, l; split_to(v, h, l);
        xh[xo] = h; xl[xo] = l;
    }
    __half h, l; split_to(v, h, l);
    fullh[idx] = h; fulll[idx] = l;
}

__global__ void pos_embed(__half* __restrict__ relh, __half* __restrict__ rell)
{
    long long idx = (long long)blockIdx.x * 256 + threadIdx.x;
    if (idx >= (long long)KLEN * UU) return;
    int u = (int)(idx % UU);
    int jj = (int)(idx / UU);
    float pos = (float)(KLEN - 1 - jj);
    int i2 = (u < UU / 2) ? u : (u - UU / 2);
    float expo = ((float)(2 * i2)) / (float)UU;
    float invf = expf(-expo * 9.210340371976184f);  // ln(10000)
    float ang = pos * invf;
    float v = (u < UU / 2) ? sinf(ang) : cosf(ang);
    __half h, l; split_to(v, h, l);
    relh[idx] = h; rell[idx] = l;
}

// transpose: W[K,N] fp32 -> single fp16 [N,K]
__global__ void split_T_h(const float* __restrict__ W, __half* __restrict__ hi,
                          int K, int N)
{
    __shared__ float t[32][33];
    int n0 = blockIdx.x * 32, k0 = blockIdx.y * 32;
    #pragma unroll
    for (int i = 0; i < 32; i += 8)
        t[threadIdx.y + i][threadIdx.x] =
            W[(long long)(k0 + threadIdx.y + i) * N + n0 + threadIdx.x];
    __syncthreads();
    #pragma unroll
    for (int i = 0; i < 32; i += 8) {
        float v = t[threadIdx.x][threadIdx.y + i];
        long long o = (long long)(n0 + threadIdx.y + i) * K + k0 + threadIdx.x;
        hi[o] = __float2half(v);
    }
}

// V^T per head (bf16): vt[(b*H+h), d, j] = kv[b, j, U + h*64 + d]
__global__ void transpose_v(const bf16* __restrict__ kvh, const bf16* __restrict__ kvl,
                            bf16* __restrict__ vth, bf16* __restrict__ vtl)
{
    __shared__ bf16 th[32][33], tl[32][33];
    int z = blockIdx.z;
    int b = z / HH, h = z % HH;
    int j0 = blockIdx.x * 32, d0 = blockIdx.y * 32;
    int tx = threadIdx.x, ty = threadIdx.y;
    #pragma unroll
    for (int i = 0; i < 32; i += 8) {
        long long src = ((long long)b * KLEN + j0 + ty + i) * (2 * UU) + UU + h * 64 + d0 + tx;
        th[ty + i][tx] = kvh[src];
        tl[ty + i][tx] = kvl[src];
    }
    __syncthreads();
    #pragma unroll
    for (int i = 0; i < 32; i += 8) {
        long long dst = ((long long)z * DD + d0 + ty + i) * KLEN + j0 + tx;
        vth[dst] = th[tx][ty + i];
        vtl[dst] = tl[tx][ty + i];
    }
}

// mask + rel-shift + softmax; writes P as split bf16 (zero tail)
__global__ __launch_bounds__(256)
void attn_softmax(const float* __restrict__ ac, const float* __restrict__ ar,
                  bf16* __restrict__ ph, bf16* __restrict__ pl)
{
    int i = blockIdx.x;
    long long z = blockIdx.y;
    const float* arow = ac + (z * SS + i) * (long long)KLEN;
    const float* rrow = ar + (z * SS + i) * (long long)KLEN;
    bf16* phr = ph + (z * SS + i) * (long long)KLEN;
    bf16* plr = pl + (z * SS + i) * (long long)KLEN;
    int lim = i + MEMLEN;
    int shift = SS - 1 - i;
    int tid = threadIdx.x;

    float vals[7];
    int cnt = 0;
    float lmax = -3.4e38f;
    for (int j = tid; j <= lim; j += 256) {
        float v = (arow[j] + rrow[j + shift]) * 0.125f;
        vals[cnt++] = v;
        lmax = fmaxf(lmax, v);
    }
    float m = block_reduce_max(lmax);
    float lsum = 0.f;
    for (int t = 0; t < cnt; t++) {
        float e = expf(vals[t] - m);
        vals[t] = e;
        lsum += e;
    }
    float s = block_reduce_sum(lsum);
    float inv = 1.f / s;
    cnt = 0;
    for (int j = tid; j <= lim; j += 256) {
        float p = vals[cnt++] * inv;
        bf16 h, l; split_to(p, h, l);
        phr[j] = h; plr[j] = l;
    }
    bf16 z0 = __float2bfloat16(0.f);
    for (int j = lim + 1 + tid; j < KLEN; j += 256) { phr[j] = z0; plr[j] = z0; }
}

// add + LayerNorm; emits fp32 (optional) plus fp16 split pair
__global__ __launch_bounds__(256)
void add_ln(const float* __restrict__ a, const float* __restrict__ b,
            const float* __restrict__ g, const float* __restrict__ beta,
            float* __restrict__ out, __half* __restrict__ oh, __half* __restrict__ ol)
{
    long long row = blockIdx.x;
    const float* pa = a + row * UU;
    const float* pb = b + row * UU;
    int tid = threadIdx.x;
    float vals[4];
    float s = 0.f, ss = 0.f;
    #pragma unroll
    for (int t = 0; t < 4; t++) {
        int idx = tid * 4 + t;
        float v = pa[idx] + pb[idx];
        vals[t] = v;
        s += v;
        ss += v * v;
    }
    s = block_reduce_sum(s);
    ss = block_reduce_sum(ss);
    float mean = s * (1.f / UU);
    float var = fmaxf(ss * (1.f / UU) - mean * mean, 0.f);
    float rstd = rsqrtf(var + 1e-5f);
    #pragma unroll
    for (int t = 0; t < 4; t++) {
        int idx = tid * 4 + t;
        float v = (vals[t] - mean) * rstd * g[idx] + beta[idx];
        if (out) out[row * UU + idx] = v;
        __half h, l; split_to(v, h, l);
        oh[row * UU + idx] = h; ol[row * UU + idx] = l;
    }
}

// online-softmax over vocab rows, in place
__global__ __launch_bounds__(512)
void softmax_rows(float* __restrict__ x, int N)
{
    __shared__ float smm[16], sms[16];
    long long row = blockIdx.x;
    float* p = x + row * (long long)N;
    int tid = threadIdx.x;
    float m = -3.4e38f, s = 0.f;
    for (int j = tid; j < N; j += 512) {
        float v = p[j];
        if (v > m) { s = s * expf(m - v) + 1.f; m = v; }
        else       { s += expf(v - m); }
    }
    #pragma unroll
    for (int o = 16; o > 0; o >>= 1) {
        float m2 = __shfl_xor_sync(0xffffffffu, m, o);
        float s2 = __shfl_xor_sync(0xffffffffu, s, o);
        float M = fmaxf(m, m2);
        s = s * expf(m - M) + s2 * expf(m2 - M);
        m = M;
    }
    if ((tid & 31) == 0) { smm[tid >> 5] = m; sms[tid >> 5] = s; }
    __syncthreads();
    if (tid < 32) {
        float mm = (tid < 16) ? smm[tid] : -3.4e38f;
        float ssv = (tid < 16) ? sms[tid] : 0.f;
        #pragma unroll
        for (int o = 8; o > 0; o >>= 1) {
            float m2 = __shfl_xor_sync(0xffffffffu, mm, o);
            float s2 = __shfl_xor_sync(0xffffffffu, ssv, o);
            float M = fmaxf(mm, m2);
            ssv = ssv * expf(mm - M) + s2 * expf(m2 - M);
            mm = M;
        }
        if (tid == 0) { smm[0] = mm; sms[0] = ssv; }
    }
    __syncthreads();
    float M = smm[0];
    float inv = 1.f / sms[0];
    for (int j = tid; j < N; j += 512) p[j] = expf(p[j] - M) * inv;
}

// ---------------- host ----------------
#define SMEM4(BN, PASS) (4 * (8192 + ((PASS) == 3 ? 2 : 1) * (BN) * 32))

extern "C" void kernel_launch(void* const* d_in, const int* in_sizes, int n_in,
                              void* d_out, int out_size)
{
    const int*   tokens  = (const int*)  d_in[0];
    const float* memory  = (const float*)d_in[1];
    const float* embed   = (const float*)d_in[2];
    const float* Wq      = (const float*)d_in[3];
    const float* Wkv     = (const float*)d_in[4];
    const float* Wr      = (const float*)d_in[5];
    const float* Wo      = (const float*)d_in[6];
    const float* bq      = (const float*)d_in[7];
    const float* bkv     = (const float*)d_in[8];
    const float* br      = (const float*)d_in[9];
    const float* bo      = (const float*)d_in[10];
    const float* bias_c  = (const float*)d_in[11];
    const float* bias_r  = (const float*)d_in[12];
    const float* ln1_g   = (const float*)d_in[13];
    const float* ln1_b   = (const float*)d_in[14];
    const float* W1      = (const float*)d_in[15];
    const float* b1      = (const float*)d_in[16];
    const float* W2      = (const float*)d_in[17];
    const float* b2      = (const float*)d_in[18];
    const float* ln2_g   = (const float*)d_in[19];
    const float* ln2_b   = (const float*)d_in[20];
    const float* Wout    = (const float*)d_in[21];
    const float* bout    = (const float*)d_in[22];
    float* out = (float*)d_out;

    static bool s_attr = false;
    if (!s_attr) {
        cudaFuncSetAttribute(hgemm<128,0,3,bf16>,   cudaFuncAttributeMaxDynamicSharedMemorySize, SMEM4(128,3));
        cudaFuncSetAttribute(hgemm<64,1,3,__half>,  cudaFuncAttributeMaxDynamicSharedMemorySize, SMEM4(64,3));
        cudaFuncSetAttribute(hgemm<128,0,2,__half>, cudaFuncAttributeMaxDynamicSharedMemorySize, SMEM4(128,2));
        cudaFuncSetAttribute(hgemm<128,1,2,bf16>,   cudaFuncAttributeMaxDynamicSharedMemorySize, SMEM4(128,2));
        cudaFuncSetAttribute(hgemm<128,2,2,__half>, cudaFuncAttributeMaxDynamicSharedMemorySize, SMEM4(128,2));
        cudaFuncSetAttribute(hgemm<128,3,2,bf16>,   cudaFuncAttributeMaxDynamicSharedMemorySize, SMEM4(128,2));
        s_attr = true;
    }

    float *x, *ac, *ar, *tmp, *h1;
    cudaGetSymbolAddress((void**)&x,   g_x);
    cudaGetSymbolAddress((void**)&ac,  g_ac);
    cudaGetSymbolAddress((void**)&ar,  g_ar);
    cudaGetSymbolAddress((void**)&tmp, g_tmp);
    cudaGetSymbolAddress((void**)&h1,  g_h1);

    __half *xh,*xl,*fullh,*fulll,*relh,*rell,*ctxh,*ctxl,*h1hh,*h1lh,*ffhh,*fflh,*h2hh,*h2lh;
    bf16 *qch,*qcl,*qrh,*qrl,*kvh,*kvl,*rh,*rl,*ph,*pl,*vth,*vtl;
    __half *WqH,*WkvH,*WrH,*WoH,*W1H,*W2H,*WoutH;
    cudaGetSymbolAddress((void**)&xh, g_xh);       cudaGetSymbolAddress((void**)&xl, g_xl);
    cudaGetSymbolAddress((void**)&fullh, g_fullh); cudaGetSymbolAddress((void**)&fulll, g_fulll);
    cudaGetSymbolAddress((void**)&relh, g_relh);   cudaGetSymbolAddress((void**)&rell, g_rell);
    cudaGetSymbolAddress((void**)&ctxh, g_ctxh);   cudaGetSymbolAddress((void**)&ctxl, g_ctxl);
    cudaGetSymbolAddress((void**)&h1hh, g_h1hh);   cudaGetSymbolAddress((void**)&h1lh, g_h1lh);
    cudaGetSymbolAddress((void**)&ffhh, g_ffhh);   cudaGetSymbolAddress((void**)&fflh, g_fflh);
    cudaGetSymbolAddress((void**)&h2hh, g_h2hh);   cudaGetSymbolAddress((void**)&h2lh, g_h2lh);
    cudaGetSymbolAddress((void**)&qch, g_qch);     cudaGetSymbolAddress((void**)&qcl, g_qcl);
    cudaGetSymbolAddress((void**)&qrh, g_qrh);     cudaGetSymbolAddress((void**)&qrl, g_qrl);
    cudaGetSymbolAddress((void**)&kvh, g_kvh);     cudaGetSymbolAddress((void**)&kvl, g_kvl);
    cudaGetSymbolAddress((void**)&rh, g_rh);       cudaGetSymbolAddress((void**)&rl, g_rl);
    cudaGetSymbolAddress((void**)&ph, g_ph);       cudaGetSymbolAddress((void**)&pl, g_pl);
    cudaGetSymbolAddress((void**)&vth, g_vth);     cudaGetSymbolAddress((void**)&vtl, g_vtl);
    cudaGetSymbolAddress((void**)&WqH, g_WqH);     cudaGetSymbolAddress((void**)&WkvH, g_WkvH);
    cudaGetSymbolAddress((void**)&WrH, g_WrH);     cudaGetSymbolAddress((void**)&WoH, g_WoH);
    cudaGetSymbolAddress((void**)&W1H, g_W1H);     cudaGetSymbolAddress((void**)&W2H, g_W2H);
    cudaGetSymbolAddress((void**)&WoutH, g_WoutH);

    const int M_TOK = BB * SS;      // 2048
    const int M_FULL = BB * KLEN;   // 3200
    dim3 tb(32, 8);

    // 1) embedding + concat + fp16 splits
    {
        long long tot = (long long)BB * KLEN * UU;
        build_full<<<(unsigned)((tot + 255) / 256), 256>>>(tokens, memory, embed,
                                                           x, xh, xl, fullh, fulll);
    }
    // 2) Wkv -> fp16
    split_T_h<<<dim3(2*UU/32, UU/32), tb>>>(Wkv, WkvH, UU, 2*UU);
    // 3) positional embedding
    {
        long long tot = (long long)KLEN * UU;
        pos_embed<<<(unsigned)((tot + 255) / 256), 256>>>(relh, rell);
    }
    // 4) kv projection (fp16 2-pass)  <-- ncu capture target (4th launch)
    hgemm<128,1,2,bf16><<<dim3(M_FULL/128, 2*UU/128, 1), 256, SMEM4(128,2)>>>(
        (const bf16*)fullh, (const bf16*)fulll, (const bf16*)WkvH, nullptr,
        nullptr, kvh, kvl, nullptr, nullptr, bkv, nullptr, nullptr,
        M_FULL, 2*UU, UU, UU, UU, 2*UU, 1, 0,0,0,0,0,0, -1,-1,-1);
    // remaining weight conversions
    split_T_h<<<dim3(UU/32,  UU/32),  tb>>>(Wq,   WqH,   UU,  UU);
    split_T_h<<<dim3(UU/32,  UU/32),  tb>>>(Wr,   WrH,   UU,  UU);
    split_T_h<<<dim3(UU/32,  UU/32),  tb>>>(Wo,   WoH,   UU,  UU);
    split_T_h<<<dim3(FFD/32, UU/32),  tb>>>(W1,   W1H,   UU,  FFD);
    split_T_h<<<dim3(UU/32,  FFD/32), tb>>>(W2,   W2H,   FFD, UU);
    split_T_h<<<dim3(NT/32,  UU/32),  tb>>>(Wout, WoutH, UU,  NT);
    // q projection fused with (q+u)/(q+v) bf16 splits (fp16 2-pass)
    hgemm<128,3,2,bf16><<<dim3(M_TOK/128, UU/128, 1), 256, SMEM4(128,2)>>>(
        (const bf16*)xh, (const bf16*)xl, (const bf16*)WqH, nullptr,
        nullptr, qch, qcl, qrh, qrl, bq, bias_c, bias_r,
        M_TOK, UU, UU, UU, UU, UU, 1, 0,0,0,0,0,0, -1,-1,-1);
    // r projection (fp16 2-pass)
    hgemm<128,1,2,bf16><<<dim3((KLEN+127)/128, UU/128, 1), 256, SMEM4(128,2)>>>(
        (const bf16*)relh, (const bf16*)rell, (const bf16*)WrH, nullptr,
        nullptr, rh, rl, nullptr, nullptr, br, nullptr, nullptr,
        KLEN, UU, UU, UU, UU, UU, 1, 0,0,0,0,0,0, -1,-1,-1);
    // scores (bf16 3-pass, batched over b,h), dead-tile skips
    {
        dim3 grid(SS / 128, (KLEN + 127) / 128, BB * HH);
        hgemm<128,0,3,bf16><<<grid, 256, SMEM4(128,3)>>>(qch, qcl, kvh, kvl, ac,
            (bf16*)nullptr, (bf16*)nullptr, (bf16*)nullptr, (bf16*)nullptr,
            nullptr, nullptr, nullptr,
            SS, KLEN, DD, UU, 2*UU, KLEN, HH,
            (long long)SS*UU, 64,
            (long long)KLEN*2*UU, 64,
            (long long)HH*SS*KLEN, (long long)SS*KLEN,
            MEMLEN + 127, -1, -1);
        hgemm<128,0,3,bf16><<<grid, 256, SMEM4(128,3)>>>(qrh, qrl, rh, rl, ar,
            (bf16*)nullptr, (bf16*)nullptr, (bf16*)nullptr, (bf16*)nullptr,
            nullptr, nullptr, nullptr,
            SS, KLEN, DD, UU, UU, KLEN, HH,
            (long long)SS*UU, 64,
            0, 64,
            (long long)HH*SS*KLEN, (long long)SS*KLEN,
            -1, SS - 255, -1);
    }
    // fused rel-shift + mask + softmax -> split P (bf16)
    {
        dim3 grid(SS, BB * HH);
        attn_softmax<<<grid, 256>>>(ac, ar, ph, pl);
    }
    // V^T per head
    {
        dim3 grid(KLEN / 32, DD / 32, BB * HH);
        transpose_v<<<grid, tb>>>(kvh, kvl, vth, vtl);
    }
    // ctx = P @ V^T (bf16 3-pass, K clamp), fp16 split output
    {
        dim3 grid(SS / 128, 1, BB * HH);
        hgemm<64,1,3,__half><<<grid, 256, SMEM4(64,3)>>>(ph, pl, vth, vtl, nullptr,
            ctxh, ctxl, (__half*)nullptr, (__half*)nullptr,
            nullptr, nullptr, nullptr,
            SS, DD, KLEN, KLEN, KLEN, UU, HH,
            (long long)HH*SS*KLEN, (long long)SS*KLEN,
            (long long)HH*DD*KLEN, (long long)DD*KLEN,
            (long long)SS*UU, 64,
            -1, -1, MEMLEN + 128);
    }
    // attention out projection + LN1 (fp16 2-pass)
    hgemm<128,0,2,__half><<<dim3(M_TOK/128, UU/128, 1), 256, SMEM4(128,2)>>>(
        (const bf16*)ctxh, (const bf16*)ctxl, (const bf16*)WoH, nullptr,
        tmp, (__half*)nullptr, (__half*)nullptr, (__half*)nullptr, (__half*)nullptr,
        bo, nullptr, nullptr,
        M_TOK, UU, UU, UU, UU, UU, 1, 0,0,0,0,0,0, -1,-1,-1);
    add_ln<<<M_TOK, 256>>>(x, tmp, ln1_g, ln1_b, h1, h1hh, h1lh);
    // FF (fp16 2-pass)
    hgemm<128,2,2,__half><<<dim3(M_TOK/128, FFD/128, 1), 256, SMEM4(128,2)>>>(
        (const bf16*)h1hh, (const bf16*)h1lh, (const bf16*)W1H, nullptr,
        nullptr, ffhh, fflh, (__half*)nullptr, (__half*)nullptr, b1, nullptr, nullptr,
        M_TOK, FFD, UU, UU, UU, FFD, 1, 0,0,0,0,0,0, -1,-1,-1);
    hgemm<128,0,2,__half><<<dim3(M_TOK/128, UU/128, 1), 256, SMEM4(128,2)>>>(
        (const bf16*)ffhh, (const bf16*)fflh, (const bf16*)W2H, nullptr,
        tmp, (__half*)nullptr, (__half*)nullptr, (__half*)nullptr, (__half*)nullptr,
        b2, nullptr, nullptr,
        M_TOK, UU, FFD, FFD, FFD, UU, 1, 0,0,0,0,0,0, -1,-1,-1);
    add_ln<<<M_TOK, 256>>>(h1, tmp, ln2_g, ln2_b, nullptr, h2hh, h2lh);
    // logits (fp16 2-pass) + softmax
    hgemm<128,0,2,__half><<<dim3(M_TOK/128, NT/128, 1), 256, SMEM4(128,2)>>>(
        (const bf16*)h2hh, (const bf16*)h2lh, (const bf16*)WoutH, nullptr,
        out, (__half*)nullptr, (__half*)nullptr, (__half*)nullptr, (__half*)nullptr,
        bout, nullptr, nullptr,
        M_TOK, NT, UU, UU, UU, NT, 1, 0,0,0,0,0,0, -1,-1,-1);
    softmax_rows<<<M_TOK, 512>>>(out, NT);
}

// round 14
// speedup vs baseline: 1.6488x; 1.2066x over previous
#include <cuda_runtime.h>
#include <cuda_bf16.h>
#include <cuda_fp16.h>
#include <math.h>
#include <stdint.h>

// ---------------- problem constants ----------------
#define BB 2
#define SS 1024
#define UU 1024
#define HH 16
#define DD 64
#define NT 32000
#define MEMLEN 576
#define FFD 4096
#define KLEN 1600   // MEM + S
#define VOCAB 1024

typedef __nv_bfloat16 bf16;

// ---------------- scratch (device globals; no allocation allowed) ----------------
__device__ float g_ac  [(size_t)BB*HH*SS*KLEN];
__device__ float g_ar  [(size_t)BB*HH*SS*KLEN];
__device__ float g_x   [(size_t)BB*SS*UU];
__device__ float g_tmp [(size_t)BB*SS*UU];
__device__ float g_h1  [(size_t)BB*SS*UU];

// fp16 A-side splits
__device__ __half g_xh   [(size_t)BB*SS*UU],   g_xl   [(size_t)BB*SS*UU];
__device__ __half g_fullh[(size_t)BB*KLEN*UU], g_fulll[(size_t)BB*KLEN*UU];
__device__ __half g_relh [(size_t)KLEN*UU],    g_rell [(size_t)KLEN*UU];
__device__ __half g_ctxh [(size_t)BB*SS*UU],   g_ctxl [(size_t)BB*SS*UU];
__device__ __half g_h1hh [(size_t)BB*SS*UU],   g_h1lh [(size_t)BB*SS*UU];
__device__ __half g_ffhh [(size_t)BB*SS*FFD],  g_fflh [(size_t)BB*SS*FFD];
__device__ __half g_h2hh [(size_t)BB*SS*UU],   g_h2lh [(size_t)BB*SS*UU];
// bf16 splits (attention internal path)
__device__ bf16 g_qch  [(size_t)BB*SS*UU],   g_qcl  [(size_t)BB*SS*UU];
__device__ bf16 g_qrh  [(size_t)BB*SS*UU],   g_qrl  [(size_t)BB*SS*UU];
__device__ bf16 g_kvh  [(size_t)BB*KLEN*2*UU], g_kvl [(size_t)BB*KLEN*2*UU];
__device__ bf16 g_rh   [(size_t)KLEN*UU],    g_rl   [(size_t)KLEN*UU];
__device__ bf16 g_ph   [(size_t)BB*HH*SS*KLEN], g_pl [(size_t)BB*HH*SS*KLEN];
__device__ bf16 g_vth  [(size_t)BB*HH*DD*KLEN], g_vtl[(size_t)BB*HH*DD*KLEN];
// single-fp16 transposed weights [N,K]
__device__ __half g_WqH [(size_t)UU*UU];
__device__ __half g_WkvH[(size_t)2*UU*UU];
__device__ __half g_WrH [(size_t)UU*UU];
__device__ __half g_WoH [(size_t)UU*UU];
__device__ __half g_W1H [(size_t)FFD*UU];
__device__ __half g_W2H [(size_t)UU*FFD];
__device__ __half g_WoutH[(size_t)NT*UU];

// ---------------- helpers ----------------
__device__ __forceinline__ uint32_t smem_u32(const void* p) {
    uint32_t a;
    asm("{ .reg .u64 t; cvta.to.shared.u64 t, %1; cvt.u32.u64 %0, t; }" : "=r"(a) : "l"(p));
    return a;
}
__device__ __forceinline__ void split_to(float v, bf16& h, bf16& l) {
    h = __float2bfloat16(v);
    l = __float2bfloat16(v - __bfloat162float(h));
}
__device__ __forceinline__ void split_to(float v, __half& h, __half& l) {
    h = __float2half(v);
    l = __float2half(v - __half2float(h));
}
template<typename T>
__device__ __forceinline__ uint32_t pack2(T a, T b) {
    unsigned short x = *(unsigned short*)&a, y = *(unsigned short*)&b;
    return (uint32_t)x | ((uint32_t)y << 16);
}
__device__ __forceinline__ void cp16(uint32_t dst, const void* src) {
    asm volatile("cp.async.cg.shared.global [%0], [%1], 16;" :: "r"(dst), "l"(src));
}
__device__ __forceinline__ void ldx4(uint32_t* r, uint32_t addr) {
    asm volatile("ldmatrix.sync.aligned.m8n8.x4.shared.b16 {%0,%1,%2,%3}, [%4];"
                 : "=r"(r[0]), "=r"(r[1]), "=r"(r[2]), "=r"(r[3]) : "r"(addr));
}
__device__ __forceinline__ void mma_bf(float* c, const uint32_t* a, const uint32_t* b) {
    asm volatile("mma.sync.aligned.m16n8k16.row.col.f32.bf16.bf16.f32 "
                 "{%0,%1,%2,%3}, {%4,%5,%6,%7}, {%8,%9}, {%0,%1,%2,%3};"
                 : "+f"(c[0]), "+f"(c[1]), "+f"(c[2]), "+f"(c[3])
                 : "r"(a[0]), "r"(a[1]), "r"(a[2]), "r"(a[3]), "r"(b[0]), "r"(b[1]));
}
__device__ __forceinline__ void mma_fp(float* c, const uint32_t* a, const uint32_t* b) {
    asm volatile("mma.sync.aligned.m16n8k16.row.col.f32.f16.f16.f32 "
                 "{%0,%1,%2,%3}, {%4,%5,%6,%7}, {%8,%9}, {%0,%1,%2,%3};"
                 : "+f"(c[0]), "+f"(c[1]), "+f"(c[2]), "+f"(c[3])
                 : "r"(a[0]), "r"(a[1]), "r"(a[2]), "r"(a[3]), "r"(b[0]), "r"(b[1]));
}

// shared epilogue writer
template<int OUT, typename ET>
__device__ __forceinline__ void epi_store(
    float v0, float v1, float v2, float v3,
    int gm0, int gn, int M, int ldc, long long cbase,
    float* C, ET* Ch, ET* Cl, ET* Dh, ET* Dl,
    const float* bias2, const float* bias3)
{
    if (OUT == 0) {
        if (gm0 < M) {
            float2 w; w.x = v0; w.y = v1;
            *(float2*)(C + cbase + (long long)gm0 * ldc + gn) = w;
        }
        if (gm0 + 8 < M) {
            float2 w; w.x = v2; w.y = v3;
            *(float2*)(C + cbase + (long long)(gm0 + 8) * ldc + gn) = w;
        }
    } else if (OUT == 3) {
        float2 b2 = *(const float2*)(bias2 + gn);
        float2 b3 = *(const float2*)(bias3 + gn);
        ET h0, l0, h1, l1;
        if (gm0 < M) {
            long long o = cbase + (long long)gm0 * ldc + gn;
            split_to(v0 + b2.x, h0, l0); split_to(v1 + b2.y, h1, l1);
            *(uint32_t*)(Ch + o) = pack2(h0, h1); *(uint32_t*)(Cl + o) = pack2(l0, l1);
            split_to(v0 + b3.x, h0, l0); split_to(v1 + b3.y, h1, l1);
            *(uint32_t*)(Dh + o) = pack2(h0, h1); *(uint32_t*)(Dl + o) = pack2(l0, l1);
        }
        if (gm0 + 8 < M) {
            long long o = cbase + (long long)(gm0 + 8) * ldc + gn;
            split_to(v2 + b2.x, h0, l0); split_to(v3 + b2.y, h1, l1);
            *(uint32_t*)(Ch + o) = pack2(h0, h1); *(uint32_t*)(Cl + o) = pack2(l0, l1);
            split_to(v2 + b3.x, h0, l0); split_to(v3 + b3.y, h1, l1);
            *(uint32_t*)(Dh + o) = pack2(h0, h1); *(uint32_t*)(Dl + o) = pack2(l0, l1);
        }
    } else {
        if (OUT == 2) {
            v0 = fmaxf(v0, 0.f); v1 = fmaxf(v1, 0.f);
            v2 = fmaxf(v2, 0.f); v3 = fmaxf(v3, 0.f);
        }
        ET h0, l0, h1, l1;
        if (gm0 < M) {
            long long o = cbase + (long long)gm0 * ldc + gn;
            split_to(v0, h0, l0); split_to(v1, h1, l1);
            *(uint32_t*)(Ch + o) = pack2(h0, h1); *(uint32_t*)(Cl + o) = pack2(l0, l1);
        }
        if (gm0 + 8 < M) {
            long long o = cbase + (long long)(gm0 + 8) * ldc + gn;
            split_to(v2, h0, l0); split_to(v3, h1, l1);
            *(uint32_t*)(Ch + o) = pack2(h0, h1); *(uint32_t*)(Cl + o) = pack2(l0, l1);
        }
    }
}

// ---------------- generalized HMMA split GEMM (R8 mainloop) ----------------
// PASS=3 (bf16): C = (Ah+Al) @ (Bh+Bl)^T via hh + hl + lh  (A,B bf16 hi/lo).
// PASS=2 (fp16): C = (Ah+Al) @ Bh^T via hh + lh            (A fp16 hi/lo, B single fp16).
// PASS=1 (fp16): C = Ah @ Bh^T                             (A,B single fp16).
// 4-stage cp.async pipeline, ONE barrier per K16 chunk (best measured config).
// maskA/maskB: dead-tile skips. kclamp: effective K = min(K, m0+kclamp).
// OUT: 0 = fp32 C (+bias); 1 = split ET; 2 = relu + split ET; 3 = dual-bias split ET.
// Element pointers declared bf16; for PASS<=2 they carry fp16 bits (MMA decides type).
template<int BN, int OUT, int PASS, typename ET>
__global__ __launch_bounds__(256)
void hgemm(const bf16* __restrict__ Ah, const bf16* __restrict__ Al,
           const bf16* __restrict__ Bh, const bf16* __restrict__ Bl,
           float* __restrict__ C, ET* __restrict__ Ch, ET* __restrict__ Cl,
           ET* __restrict__ Dh, ET* __restrict__ Dl,
           const float* __restrict__ bias,
           const float* __restrict__ bias2, const float* __restrict__ bias3,
           int M, int N, int K, int lda, int ldb, int ldc, int Z2,
           long long sA1, long long sA2, long long sB1, long long sB2,
           long long sC1, long long sC2,
           int maskA, int maskB, int kclamp)
{
    constexpr int BSTR = BN * 32;
    constexpr int ACNT = (PASS == 1) ? 1 : 2;
    constexpr int STAGE = ACNT * 4096 + (PASS == 3 ? 2 : 1) * BSTR;
    constexpr int ABASE = ACNT * 4096;
    constexpr int MT = (BN == 128) ? 4 : 2;
    extern __shared__ __align__(128) char sm[];
    const uint32_t smb = smem_u32(sm);
    const int tid = threadIdx.x, wid = tid >> 5, lane = tid & 31;
    const int m0 = blockIdx.x * 128, n0 = blockIdx.y * BN;
    if (maskA >= 0 && n0 > m0 + maskA) return;
    if (maskB >= 0 && m0 + n0 < maskB) return;
    const int Keff = (kclamp >= 0) ? min(K, m0 + kclamp) : K;

    const int m_w = (BN == 128) ? (wid & 1) * 64 : (wid & 3) * 32;
    const int n_w = (BN == 128) ? (wid >> 1) * 32 : (wid >> 2) * 32;

    const int z = blockIdx.z;
    const int z1 = z / Z2, z2 = z - z1 * Z2;
    Ah += z1 * sA1 + z2 * sA2;
    if (PASS != 1) Al += z1 * sA1 + z2 * sA2;
    Bh += z1 * sB1 + z2 * sB2;
    if (PASS == 3) Bl += z1 * sB1 + z2 * sB2;
    const long long cbase = z1 * sC1 + z2 * sC2;

    const int lr = tid >> 1, lc = tid & 1;
    const uint32_t so = (uint32_t)(lr * 32 + ((lc ^ ((lr >> 2) & 1)) << 4));
    const int ga = min(m0 + lr, M - 1);
    const long long aoff = (long long)ga * lda + lc * 8;
    const bool bdo = (BN == 128) || (tid < 128);
    const int gb = min(n0 + lr, N - 1);
    const long long boff = (long long)gb * ldb + lc * 8;

    float acc[MT][4][4];
    #pragma unroll
    for (int i = 0; i < MT; i++)
        #pragma unroll
        for (int j = 0; j < 4; j++)
            #pragma unroll
            for (int k = 0; k < 4; k++) acc[i][j][k] = 0.f;

    const int NC = Keff / 16;

    // prologue: stages 0,1,2
    #pragma unroll
    for (int pc = 0; pc < 3; pc++) {
        const uint32_t st = smb + pc * STAGE;
        cp16(st + so, Ah + aoff + pc * 16);
        if (PASS != 1) cp16(st + 4096 + so, Al + aoff + pc * 16);
        if (bdo) {
            cp16(st + ABASE + so, Bh + boff + pc * 16);
            if (PASS == 3) cp16(st + ABASE + BSTR + so, Bl + boff + pc * 16);
        }
        asm volatile("cp.async.commit_group;");
    }

    const int rr = lane & 15, ccq = lane >> 4;
    const int rbq = (lane & 7) | ((lane & 16) >> 1);
    const int cbq = (lane >> 3) & 1;

    for (int c = 0; c < NC; c++) {
        asm volatile("cp.async.wait_group 2;");
        __syncthreads();
        if (c + 3 < NC) {
            const uint32_t st = smb + ((c + 3) & 3) * STAGE;
            const long long k0 = (long long)(c + 3) * 16;
            cp16(st + so, Ah + aoff + k0);
            if (PASS != 1) cp16(st + 4096 + so, Al + aoff + k0);
            if (bdo) {
                cp16(st + ABASE + so, Bh + boff + k0);
                if (PASS == 3) cp16(st + ABASE + BSTR + so, Bl + boff + k0);
            }
        }
        asm volatile("cp.async.commit_group;");

        const uint32_t st = smb + (c & 3) * STAGE;
        uint32_t ah[MT][4], al[MT][4], bh[2][4], bl[2][4];
        #pragma unroll
        for (int mt = 0; mt < MT; mt++) {
            int R = m_w + mt * 16 + rr;
            uint32_t ad = st + R * 32 + ((ccq ^ ((R >> 2) & 1)) << 4);
            ldx4(ah[mt], ad);
            if (PASS != 1) ldx4(al[mt], ad + 4096);
        }
        #pragma unroll
        for (int np = 0; np < 2; np++) {
            int Nr = n_w + np * 16 + rbq;
            uint32_t bd = st + ABASE + Nr * 32 + ((cbq ^ ((Nr >> 2) & 1)) << 4);
            ldx4(bh[np], bd);
            if (PASS == 3) ldx4(bl[np], bd + BSTR);
        }
        #pragma unroll
        for (int mt = 0; mt < MT; mt++)
            #pragma unroll
            for (int nt = 0; nt < 4; nt++) {
                const uint32_t* bhp = &bh[nt >> 1][(nt & 1) * 2];
                if (PASS == 3) {
                    const uint32_t* blp = &bl[nt >> 1][(nt & 1) * 2];
                    mma_bf(acc[mt][nt], ah[mt], bhp);
                    mma_bf(acc[mt][nt], ah[mt], blp);
                    mma_bf(acc[mt][nt], al[mt], bhp);
                } else if (PASS == 2) {
                    mma_fp(acc[mt][nt], ah[mt], bhp);
                    mma_fp(acc[mt][nt], al[mt], bhp);
                } else {
                    mma_fp(acc[mt][nt], ah[mt], bhp);
                }
            }
    }

    // ---- epilogue ----
    #pragma unroll
    for (int mt = 0; mt < MT; mt++) {
        int gm0 = m0 + m_w + mt * 16 + (lane >> 2);
        #pragma unroll
        for (int nt = 0; nt < 4; nt++) {
            int gn = n0 + n_w + nt * 8 + (lane & 3) * 2;
            if (gn >= N) continue;
            float bx = 0.f, by = 0.f;
            if (bias) { float2 bv = *(const float2*)(bias + gn); bx = bv.x; by = bv.y; }
            epi_store<OUT, ET>(acc[mt][nt][0] + bx, acc[mt][nt][1] + by,
                               acc[mt][nt][2] + bx, acc[mt][nt][3] + by,
                               gm0, gn, M, ldc, cbase, C, Ch, Cl, Dh, Dl, bias2, bias3);
        }
    }
}

// ---------------- reductions ----------------
__device__ __forceinline__ float block_reduce_sum(float v) {
    __shared__ float sm[16];
    __syncthreads();
    #pragma unroll
    for (int o = 16; o > 0; o >>= 1) v += __shfl_xor_sync(0xffffffffu, v, o);
    if ((threadIdx.x & 31) == 0) sm[threadIdx.x >> 5] = v;
    __syncthreads();
    if (threadIdx.x < 32) {
        float x = (threadIdx.x < (blockDim.x >> 5)) ? sm[threadIdx.x] : 0.f;
        #pragma unroll
        for (int o = 8; o > 0; o >>= 1) x += __shfl_xor_sync(0xffffffffu, x, o);
        if (threadIdx.x == 0) sm[0] = x;
    }
    __syncthreads();
    return sm[0];
}
__device__ __forceinline__ float block_reduce_max(float v) {
    __shared__ float sm[16];
    __syncthreads();
    #pragma unroll
    for (int o = 16; o > 0; o >>= 1) v = fmaxf(v, __shfl_xor_sync(0xffffffffu, v, o));
    if ((threadIdx.x & 31) == 0) sm[threadIdx.x >> 5] = v;
    __syncthreads();
    if (threadIdx.x < 32) {
        float x = (threadIdx.x < (blockDim.x >> 5)) ? sm[threadIdx.x] : -3.4e38f;
        #pragma unroll
        for (int o = 8; o > 0; o >>= 1) x = fmaxf(x, __shfl_xor_sync(0xffffffffu, x, o));
        if (threadIdx.x == 0) sm[0] = x;
    }
    __syncthreads();
    return sm[0];
}

// ---------------- small kernels ----------------
__global__ void build_full(const int* __restrict__ tokens,
                           const float* __restrict__ memory,
                           const float* __restrict__ embed,
                           float* __restrict__ x,
                           __half* __restrict__ xh, __half* __restrict__ xl,
                           __half* __restrict__ fullh, __half* __restrict__ fulll)
{
    long long idx = (long long)blockIdx.x * 256 + threadIdx.x;
    const long long tot = (long long)BB * KLEN * UU;
    if (idx >= tot) return;
    int u = (int)(idx % UU);
    long long t = idx / UU;
    int j = (int)(t % KLEN);
    int b = (int)(t / KLEN);
    float v;
    if (j < MEMLEN) {
        v = memory[((long long)b * MEMLEN + j) * UU + u];
    } else {
        int s = j - MEMLEN;
        int tok = tokens[b * SS + s];
        v = embed[(long long)tok * UU + u] * 32.0f;  // sqrt(1024)
        long long xo = ((long long)b * SS + s) * UU + u;
        x[xo] = v;
        __half h, l; split_to(v, h, l);
        xh[xo] = h; xl[xo] = l;
    }
    __half h, l; split_to(v, h, l);
    fullh[idx] = h; fulll[idx] = l;
}

__global__ void pos_embed(__half* __restrict__ relh, __half* __restrict__ rell)
{
    long long idx = (long long)blockIdx.x * 256 + threadIdx.x;
    if (idx >= (long long)KLEN * UU) return;
    int u = (int)(idx % UU);
    int jj = (int)(idx / UU);
    float pos = (float)(KLEN - 1 - jj);
    int i2 = (u < UU / 2) ? u : (u - UU / 2);
    float expo = ((float)(2 * i2)) / (float)UU;
    float invf = expf(-expo * 9.210340371976184f);  // ln(10000)
    float ang = pos * invf;
    float v = (u < UU / 2) ? sinf(ang) : cosf(ang);
    __half h, l; split_to(v, h, l);
    relh[idx] = h; rell[idx] = l;
}

// transpose: W[K,N] fp32 -> single fp16 [N,K]
__global__ void split_T_h(const float* __restrict__ W, __half* __restrict__ hi,
                          int K, int N)
{
    __shared__ float t[32][33];
    int n0 = blockIdx.x * 32, k0 = blockIdx.y * 32;
    #pragma unroll
    for (int i = 0; i < 32; i += 8)
        t[threadIdx.y + i][threadIdx.x] =
            W[(long long)(k0 + threadIdx.y + i) * N + n0 + threadIdx.x];
    __syncthreads();
    #pragma unroll
    for (int i = 0; i < 32; i += 8) {
        float v = t[threadIdx.x][threadIdx.y + i];
        long long o = (long long)(n0 + threadIdx.y + i) * K + k0 + threadIdx.x;
        hi[o] = __float2half(v);
    }
}

// V^T per head (bf16): vt[(b*H+h), d, j] = kv[b, j, U + h*64 + d]
__global__ void transpose_v(const bf16* __restrict__ kvh, const bf16* __restrict__ kvl,
                            bf16* __restrict__ vth, bf16* __restrict__ vtl)
{
    __shared__ bf16 th[32][33], tl[32][33];
    int z = blockIdx.z;
    int b = z / HH, h = z % HH;
    int j0 = blockIdx.x * 32, d0 = blockIdx.y * 32;
    int tx = threadIdx.x, ty = threadIdx.y;
    #pragma unroll
    for (int i = 0; i < 32; i += 8) {
        long long src = ((long long)b * KLEN + j0 + ty + i) * (2 * UU) + UU + h * 64 + d0 + tx;
        th[ty + i][tx] = kvh[src];
        tl[ty + i][tx] = kvl[src];
    }
    __syncthreads();
    #pragma unroll
    for (int i = 0; i < 32; i += 8) {
        long long dst = ((long long)z * DD + d0 + ty + i) * KLEN + j0 + tx;
        vth[dst] = th[tx][ty + i];
        vtl[dst] = tl[tx][ty + i];
    }
}

// mask + rel-shift + softmax; writes P as split bf16 (zero tail)
__global__ __launch_bounds__(256)
void attn_softmax(const float* __restrict__ ac, const float* __restrict__ ar,
                  bf16* __restrict__ ph, bf16* __restrict__ pl)
{
    int i = blockIdx.x;
    long long z = blockIdx.y;
    const float* arow = ac + (z * SS + i) * (long long)KLEN;
    const float* rrow = ar + (z * SS + i) * (long long)KLEN;
    bf16* phr = ph + (z * SS + i) * (long long)KLEN;
    bf16* plr = pl + (z * SS + i) * (long long)KLEN;
    int lim = i + MEMLEN;
    int shift = SS - 1 - i;
    int tid = threadIdx.x;

    float vals[7];
    int cnt = 0;
    float lmax = -3.4e38f;
    for (int j = tid; j <= lim; j += 256) {
        float v = (arow[j] + rrow[j + shift]) * 0.125f;
        vals[cnt++] = v;
        lmax = fmaxf(lmax, v);
    }
    float m = block_reduce_max(lmax);
    float lsum = 0.f;
    for (int t = 0; t < cnt; t++) {
        float e = expf(vals[t] - m);
        vals[t] = e;
        lsum += e;
    }
    float s = block_reduce_sum(lsum);
    float inv = 1.f / s;
    cnt = 0;
    for (int j = tid; j <= lim; j += 256) {
        float p = vals[cnt++] * inv;
        bf16 h, l; split_to(p, h, l);
        phr[j] = h; plr[j] = l;
    }
    bf16 z0 = __float2bfloat16(0.f);
    for (int j = lim + 1 + tid; j < KLEN; j += 256) { phr[j] = z0; plr[j] = z0; }
}

// add + LayerNorm; emits fp32 (optional) plus fp16 split pair
__global__ __launch_bounds__(256)
void add_ln(const float* __restrict__ a, const float* __restrict__ b,
            const float* __restrict__ g, const float* __restrict__ beta,
            float* __restrict__ out, __half* __restrict__ oh, __half* __restrict__ ol)
{
    long long row = blockIdx.x;
    const float* pa = a + row * UU;
    const float* pb = b + row * UU;
    int tid = threadIdx.x;
    float vals[4];
    float s = 0.f, ss = 0.f;
    #pragma unroll
    for (int t = 0; t < 4; t++) {
        int idx = tid * 4 + t;
        float v = pa[idx] + pb[idx];
        vals[t] = v;
        s += v;
        ss += v * v;
    }
    s = block_reduce_sum(s);
    ss = block_reduce_sum(ss);
    float mean = s * (1.f / UU);
    float var = fmaxf(ss * (1.f / UU) - mean * mean, 0.f);
    float rstd = rsqrtf(var + 1e-5f);
    #pragma unroll
    for (int t = 0; t < 4; t++) {
        int idx = tid * 4 + t;
        float v = (vals[t] - mean) * rstd * g[idx] + beta[idx];
        if (out) out[row * UU + idx] = v;
        __half h, l; split_to(v, h, l);
        oh[row * UU + idx] = h; ol[row * UU + idx] = l;
    }
}

// online-softmax over vocab rows, in place
__global__ __launch_bounds__(512)
void softmax_rows(float* __restrict__ x, int N)
{
    __shared__ float smm[16], sms[16];
    long long row = blockIdx.x;
    float* p = x + row * (long long)N;
    int tid = threadIdx.x;
    float m = -3.4e38f, s = 0.f;
    for (int j = tid; j < N; j += 512) {
        float v = p[j];
        if (v > m) { s = s * expf(m - v) + 1.f; m = v; }
        else       { s += expf(v - m); }
    }
    #pragma unroll
    for (int o = 16; o > 0; o >>= 1) {
        float m2 = __shfl_xor_sync(0xffffffffu, m, o);
        float s2 = __shfl_xor_sync(0xffffffffu, s, o);
        float M = fmaxf(m, m2);
        s = s * expf(m - M) + s2 * expf(m2 - M);
        m = M;
    }
    if ((tid & 31) == 0) { smm[tid >> 5] = m; sms[tid >> 5] = s; }
    __syncthreads();
    if (tid < 32) {
        float mm = (tid < 16) ? smm[tid] : -3.4e38f;
        float ssv = (tid < 16) ? sms[tid] : 0.f;
        #pragma unroll
        for (int o = 8; o > 0; o >>= 1) {
            float m2 = __shfl_xor_sync(0xffffffffu, mm, o);
            float s2 = __shfl_xor_sync(0xffffffffu, ssv, o);
            float M = fmaxf(mm, m2);
            ssv = ssv * expf(mm - M) + s2 * expf(m2 - M);
            mm = M;
        }
        if (tid == 0) { smm[0] = mm; sms[0] = ssv; }
    }
    __syncthreads();
    float M = smm[0];
    float inv = 1.f / sms[0];
    for (int j = tid; j < N; j += 512) p[j] = expf(p[j] - M) * inv;
}

// ---------------- host ----------------
#define SMEM4(BN, PASS) (4 * (((PASS) == 1 ? 1 : 2) * 4096 + ((PASS) == 3 ? 2 : 1) * (BN) * 32))

extern "C" void kernel_launch(void* const* d_in, const int* in_sizes, int n_in,
                              void* d_out, int out_size)
{
    const int*   tokens  = (const int*)  d_in[0];
    const float* memory  = (const float*)d_in[1];
    const float* embed   = (const float*)d_in[2];
    const float* Wq      = (const float*)d_in[3];
    const float* Wkv     = (const float*)d_in[4];
    const float* Wr      = (const float*)d_in[5];
    const float* Wo      = (const float*)d_in[6];
    const float* bq      = (const float*)d_in[7];
    const float* bkv     = (const float*)d_in[8];
    const float* br      = (const float*)d_in[9];
    const float* bo      = (const float*)d_in[10];
    const float* bias_c  = (const float*)d_in[11];
    const float* bias_r  = (const float*)d_in[12];
    const float* ln1_g   = (const float*)d_in[13];
    const float* ln1_b   = (const float*)d_in[14];
    const float* W1      = (const float*)d_in[15];
    const float* b1      = (const float*)d_in[16];
    const float* W2      = (const float*)d_in[17];
    const float* b2      = (const float*)d_in[18];
    const float* ln2_g   = (const float*)d_in[19];
    const float* ln2_b   = (const float*)d_in[20];
    const float* Wout    = (const float*)d_in[21];
    const float* bout    = (const float*)d_in[22];
    float* out = (float*)d_out;

    static bool s_attr = false;
    if (!s_attr) {
        cudaFuncSetAttribute(hgemm<128,0,3,bf16>,   cudaFuncAttributeMaxDynamicSharedMemorySize, SMEM4(128,3));
        cudaFuncSetAttribute(hgemm<64,1,3,__half>,  cudaFuncAttributeMaxDynamicSharedMemorySize, SMEM4(64,3));
        cudaFuncSetAttribute(hgemm<128,0,2,__half>, cudaFuncAttributeMaxDynamicSharedMemorySize, SMEM4(128,2));
        cudaFuncSetAttribute(hgemm<128,1,2,bf16>,   cudaFuncAttributeMaxDynamicSharedMemorySize, SMEM4(128,2));
        cudaFuncSetAttribute(hgemm<128,2,2,__half>, cudaFuncAttributeMaxDynamicSharedMemorySize, SMEM4(128,2));
        cudaFuncSetAttribute(hgemm<128,3,2,bf16>,   cudaFuncAttributeMaxDynamicSharedMemorySize, SMEM4(128,2));
        cudaFuncSetAttribute(hgemm<128,0,1,__half>, cudaFuncAttributeMaxDynamicSharedMemorySize, SMEM4(128,1));
        s_attr = true;
    }

    float *x, *ac, *ar, *tmp, *h1;
    cudaGetSymbolAddress((void**)&x,   g_x);
    cudaGetSymbolAddress((void**)&ac,  g_ac);
    cudaGetSymbolAddress((void**)&ar,  g_ar);
    cudaGetSymbolAddress((void**)&tmp, g_tmp);
    cudaGetSymbolAddress((void**)&h1,  g_h1);

    __half *xh,*xl,*fullh,*fulll,*relh,*rell,*ctxh,*ctxl,*h1hh,*h1lh,*ffhh,*fflh,*h2hh,*h2lh;
    bf16 *qch,*qcl,*qrh,*qrl,*kvh,*kvl,*rh,*rl,*ph,*pl,*vth,*vtl;
    __half *WqH,*WkvH,*WrH,*WoH,*W1H,*W2H,*WoutH;
    cudaGetSymbolAddress((void**)&xh, g_xh);       cudaGetSymbolAddress((void**)&xl, g_xl);
    cudaGetSymbolAddress((void**)&fullh, g_fullh); cudaGetSymbolAddress((void**)&fulll, g_fulll);
    cudaGetSymbolAddress((void**)&relh, g_relh);   cudaGetSymbolAddress((void**)&rell, g_rell);
    cudaGetSymbolAddress((void**)&ctxh, g_ctxh);   cudaGetSymbolAddress((void**)&ctxl, g_ctxl);
    cudaGetSymbolAddress((void**)&h1hh, g_h1hh);   cudaGetSymbolAddress((void**)&h1lh, g_h1lh);
    cudaGetSymbolAddress((void**)&ffhh, g_ffhh);   cudaGetSymbolAddress((void**)&fflh, g_fflh);
    cudaGetSymbolAddress((void**)&h2hh, g_h2hh);   cudaGetSymbolAddress((void**)&h2lh, g_h2lh);
    cudaGetSymbolAddress((void**)&qch, g_qch);     cudaGetSymbolAddress((void**)&qcl, g_qcl);
    cudaGetSymbolAddress((void**)&qrh, g_qrh);     cudaGetSymbolAddress((void**)&qrl, g_qrl);
    cudaGetSymbolAddress((void**)&kvh, g_kvh);     cudaGetSymbolAddress((void**)&kvl, g_kvl);
    cudaGetSymbolAddress((void**)&rh, g_rh);       cudaGetSymbolAddress((void**)&rl, g_rl);
    cudaGetSymbolAddress((void**)&ph, g_ph);       cudaGetSymbolAddress((void**)&pl, g_pl);
    cudaGetSymbolAddress((void**)&vth, g_vth);     cudaGetSymbolAddress((void**)&vtl, g_vtl);
    cudaGetSymbolAddress((void**)&WqH, g_WqH);     cudaGetSymbolAddress((void**)&WkvH, g_WkvH);
    cudaGetSymbolAddress((void**)&WrH, g_WrH);     cudaGetSymbolAddress((void**)&WoH, g_WoH);
    cudaGetSymbolAddress((void**)&W1H, g_W1H);     cudaGetSymbolAddress((void**)&W2H, g_W2H);
    cudaGetSymbolAddress((void**)&WoutH, g_WoutH);

    const int M_TOK = BB * SS;      // 2048
    const int M_FULL = BB * KLEN;   // 3200
    dim3 tb(32, 8);

    // 1) embedding + concat + fp16 splits
    {
        long long tot = (long long)BB * KLEN * UU;
        build_full<<<(unsigned)((tot + 255) / 256), 256>>>(tokens, memory, embed,
                                                           x, xh, xl, fullh, fulll);
    }
    // 2) Wkv -> fp16
    split_T_h<<<dim3(2*UU/32, UU/32), tb>>>(Wkv, WkvH, UU, 2*UU);
    // 3) positional embedding
    {
        long long tot = (long long)KLEN * UU;
        pos_embed<<<(unsigned)((tot + 255) / 256), 256>>>(relh, rell);
    }
    // 4) kv projection (fp16 2-pass)  <-- ncu capture target (4th launch)
    hgemm<128,1,2,bf16><<<dim3(M_FULL/128, 2*UU/128, 1), 256, SMEM4(128,2)>>>(
        (const bf16*)fullh, (const bf16*)fulll, (const bf16*)WkvH, nullptr,
        nullptr, kvh, kvl, nullptr, nullptr, bkv, nullptr, nullptr,
        M_FULL, 2*UU, UU, UU, UU, 2*UU, 1, 0,0,0,0,0,0, -1,-1,-1);
    // remaining weight conversions
    split_T_h<<<dim3(UU/32,  UU/32),  tb>>>(Wq,   WqH,   UU,  UU);
    split_T_h<<<dim3(UU/32,  UU/32),  tb>>>(Wr,   WrH,   UU,  UU);
    split_T_h<<<dim3(UU/32,  UU/32),  tb>>>(Wo,   WoH,   UU,  UU);
    split_T_h<<<dim3(FFD/32, UU/32),  tb>>>(W1,   W1H,   UU,  FFD);
    split_T_h<<<dim3(UU/32,  FFD/32), tb>>>(W2,   W2H,   FFD, UU);
    split_T_h<<<dim3(NT/32,  UU/32),  tb>>>(Wout, WoutH, UU,  NT);
    // q projection fused with (q+u)/(q+v) bf16 splits (fp16 2-pass)
    hgemm<128,3,2,bf16><<<dim3(M_TOK/128, UU/128, 1), 256, SMEM4(128,2)>>>(
        (const bf16*)xh, (const bf16*)xl, (const bf16*)WqH, nullptr,
        nullptr, qch, qcl, qrh, qrl, bq, bias_c, bias_r,
        M_TOK, UU, UU, UU, UU, UU, 1, 0,0,0,0,0,0, -1,-1,-1);
    // r projection (fp16 2-pass)
    hgemm<128,1,2,bf16><<<dim3((KLEN+127)/128, UU/128, 1), 256, SMEM4(128,2)>>>(
        (const bf16*)relh, (const bf16*)rell, (const bf16*)WrH, nullptr,
        nullptr, rh, rl, nullptr, nullptr, br, nullptr, nullptr,
        KLEN, UU, UU, UU, UU, UU, 1, 0,0,0,0,0,0, -1,-1,-1);
    // scores (bf16 3-pass, batched over b,h), dead-tile skips
    {
        dim3 grid(SS / 128, (KLEN + 127) / 128, BB * HH);
        hgemm<128,0,3,bf16><<<grid, 256, SMEM4(128,3)>>>(qch, qcl, kvh, kvl, ac,
            (bf16*)nullptr, (bf16*)nullptr, (bf16*)nullptr, (bf16*)nullptr,
            nullptr, nullptr, nullptr,
            SS, KLEN, DD, UU, 2*UU, KLEN, HH,
            (long long)SS*UU, 64,
            (long long)KLEN*2*UU, 64,
            (long long)HH*SS*KLEN, (long long)SS*KLEN,
            MEMLEN + 127, -1, -1);
        hgemm<128,0,3,bf16><<<grid, 256, SMEM4(128,3)>>>(qrh, qrl, rh, rl, ar,
            (bf16*)nullptr, (bf16*)nullptr, (bf16*)nullptr, (bf16*)nullptr,
            nullptr, nullptr, nullptr,
            SS, KLEN, DD, UU, UU, KLEN, HH,
            (long long)SS*UU, 64,
            0, 64,
            (long long)HH*SS*KLEN, (long long)SS*KLEN,
            -1, SS - 255, -1);
    }
    // fused rel-shift + mask + softmax -> split P (bf16)
    {
        dim3 grid(SS, BB * HH);
        attn_softmax<<<grid, 256>>>(ac, ar, ph, pl);
    }
    // V^T per head
    {
        dim3 grid(KLEN / 32, DD / 32, BB * HH);
        transpose_v<<<grid, tb>>>(kvh, kvl, vth, vtl);
    }
    // ctx = P @ V^T (bf16 3-pass, K clamp), fp16 split output
    {
        dim3 grid(SS / 128, 1, BB * HH);
        hgemm<64,1,3,__half><<<grid, 256, SMEM4(64,3)>>>(ph, pl, vth, vtl, nullptr,
            ctxh, ctxl, (__half*)nullptr, (__half*)nullptr,
            nullptr, nullptr, nullptr,
            SS, DD, KLEN, KLEN, KLEN, UU, HH,
            (long long)HH*SS*KLEN, (long long)SS*KLEN,
            (long long)HH*DD*KLEN, (long long)DD*KLEN,
            (long long)SS*UU, 64,
            -1, -1, MEMLEN + 128);
    }
    // attention out projection + LN1 (fp16 2-pass)
    hgemm<128,0,2,__half><<<dim3(M_TOK/128, UU/128, 1), 256, SMEM4(128,2)>>>(
        (const bf16*)ctxh, (const bf16*)ctxl, (const bf16*)WoH, nullptr,
        tmp, (__half*)nullptr, (__half*)nullptr, (__half*)nullptr, (__half*)nullptr,
        bo, nullptr, nullptr,
        M_TOK, UU, UU, UU, UU, UU, 1, 0,0,0,0,0,0, -1,-1,-1);
    add_ln<<<M_TOK, 256>>>(x, tmp, ln1_g, ln1_b, h1, h1hh, h1lh);
    // FF (fp16 2-pass)
    hgemm<128,2,2,__half><<<dim3(M_TOK/128, FFD/128, 1), 256, SMEM4(128,2)>>>(
        (const bf16*)h1hh, (const bf16*)h1lh, (const bf16*)W1H, nullptr,
        nullptr, ffhh, fflh, (__half*)nullptr, (__half*)nullptr, b1, nullptr, nullptr,
        M_TOK, FFD, UU, UU, UU, FFD, 1, 0,0,0,0,0,0, -1,-1,-1);
    hgemm<128,0,2,__half><<<dim3(M_TOK/128, UU/128, 1), 256, SMEM4(128,2)>>>(
        (const bf16*)ffhh, (const bf16*)fflh, (const bf16*)W2H, nullptr,
        tmp, (__half*)nullptr, (__half*)nullptr, (__half*)nullptr, (__half*)nullptr,
        b2, nullptr, nullptr,
        M_TOK, UU, FFD, FFD, FFD, UU, 1, 0,0,0,0,0,0, -1,-1,-1);
    add_ln<<<M_TOK, 256>>>(h1, tmp, ln2_g, ln2_b, nullptr, h2hh, h2lh);
    // logits (fp16 SINGLE-pass: A = h2 single fp16, B = Wout single fp16) + softmax
    hgemm<128,0,1,__half><<<dim3(M_TOK/128, NT/128, 1), 256, SMEM4(128,1)>>>(
        (const bf16*)h2hh, nullptr, (const bf16*)WoutH, nullptr,
        out, (__half*)nullptr, (__half*)nullptr, (__half*)nullptr, (__half*)nullptr,
        bout, nullptr, nullptr,
        M_TOK, NT, UU, UU, UU, NT, 1, 0,0,0,0,0,0, -1,-1,-1);
    softmax_rows<<<M_TOK, 512>>>(out, NT);
}

// round 15
// speedup vs baseline: 1.7716x; 1.0745x over previous
#include <cuda_runtime.h>
#include <cuda_bf16.h>
#include <cuda_fp16.h>
#include <math.h>
#include <stdint.h>

// ---------------- problem constants ----------------
#define BB 2
#define SS 1024
#define UU 1024
#define HH 16
#define DD 64
#define NT 32000
#define MEMLEN 576
#define FFD 4096
#define KLEN 1600   // MEM + S
#define VOCAB 1024

typedef __nv_bfloat16 bf16;

// ---------------- scratch (device globals; no allocation allowed) ----------------
__device__ float g_ac  [(size_t)BB*HH*SS*KLEN];
__device__ float g_ar  [(size_t)BB*HH*SS*KLEN];
__device__ float g_x   [(size_t)BB*SS*UU];
__device__ float g_tmp [(size_t)BB*SS*UU];
__device__ float g_h1  [(size_t)BB*SS*UU];

// fp16 activations
__device__ __half g_xh   [(size_t)BB*SS*UU],   g_xl   [(size_t)BB*SS*UU];
__device__ __half g_fullh[(size_t)BB*KLEN*UU], g_fulll[(size_t)BB*KLEN*UU];
__device__ __half g_relh [(size_t)KLEN*UU],    g_rell [(size_t)KLEN*UU];
__device__ __half g_ctxh [(size_t)BB*SS*UU],   g_ctxl [(size_t)BB*SS*UU];
__device__ __half g_h1hh [(size_t)BB*SS*UU],   g_h1lh [(size_t)BB*SS*UU];
__device__ __half g_ffhh [(size_t)BB*SS*FFD],  g_fflh [(size_t)BB*SS*FFD];
__device__ __half g_h2hh [(size_t)BB*SS*UU],   g_h2lh [(size_t)BB*SS*UU];
// single fp16 attention operands
__device__ __half g_qc   [(size_t)BB*SS*UU];
__device__ __half g_qr   [(size_t)BB*SS*UU];
__device__ __half g_kv   [(size_t)BB*KLEN*2*UU];
__device__ __half g_r    [(size_t)KLEN*UU];
__device__ __half g_p    [(size_t)BB*HH*SS*KLEN];
__device__ __half g_vt   [(size_t)BB*HH*DD*KLEN];
// single-fp16 transposed weights [N,K]
__device__ __half g_WqH [(size_t)UU*UU];
__device__ __half g_WkvH[(size_t)2*UU*UU];
__device__ __half g_WrH [(size_t)UU*UU];
__device__ __half g_WoH [(size_t)UU*UU];
__device__ __half g_W1H [(size_t)FFD*UU];
__device__ __half g_W2H [(size_t)UU*FFD];
__device__ __half g_WoutH[(size_t)NT*UU];

// ---------------- helpers ----------------
__device__ __forceinline__ uint32_t smem_u32(const void* p) {
    uint32_t a;
    asm("{ .reg .u64 t; cvta.to.shared.u64 t, %1; cvt.u32.u64 %0, t; }" : "=r"(a) : "l"(p));
    return a;
}
__device__ __forceinline__ void split_to(float v, bf16& h, bf16& l) {
    h = __float2bfloat16(v);
    l = __float2bfloat16(v - __bfloat162float(h));
}
__device__ __forceinline__ void split_to(float v, __half& h, __half& l) {
    h = __float2half(v);
    l = __float2half(v - __half2float(h));
}
__device__ __forceinline__ void cvt1(float v, __half& h) { h = __float2half(v); }
__device__ __forceinline__ void cvt1(float v, bf16& h)   { h = __float2bfloat16(v); }
template<typename T>
__device__ __forceinline__ uint32_t pack2(T a, T b) {
    unsigned short x = *(unsigned short*)&a, y = *(unsigned short*)&b;
    return (uint32_t)x | ((uint32_t)y << 16);
}
__device__ __forceinline__ void cp16(uint32_t dst, const void* src) {
    asm volatile("cp.async.cg.shared.global [%0], [%1], 16;" :: "r"(dst), "l"(src));
}
__device__ __forceinline__ void ldx4(uint32_t* r, uint32_t addr) {
    asm volatile("ldmatrix.sync.aligned.m8n8.x4.shared.b16 {%0,%1,%2,%3}, [%4];"
                 : "=r"(r[0]), "=r"(r[1]), "=r"(r[2]), "=r"(r[3]) : "r"(addr));
}
__device__ __forceinline__ void mma_bf(float* c, const uint32_t* a, const uint32_t* b) {
    asm volatile("mma.sync.aligned.m16n8k16.row.col.f32.bf16.bf16.f32 "
                 "{%0,%1,%2,%3}, {%4,%5,%6,%7}, {%8,%9}, {%0,%1,%2,%3};"
                 : "+f"(c[0]), "+f"(c[1]), "+f"(c[2]), "+f"(c[3])
                 : "r"(a[0]), "r"(a[1]), "r"(a[2]), "r"(a[3]), "r"(b[0]), "r"(b[1]));
}
__device__ __forceinline__ void mma_fp(float* c, const uint32_t* a, const uint32_t* b) {
    asm volatile("mma.sync.aligned.m16n8k16.row.col.f32.f16.f16.f32 "
                 "{%0,%1,%2,%3}, {%4,%5,%6,%7}, {%8,%9}, {%0,%1,%2,%3};"
                 : "+f"(c[0]), "+f"(c[1]), "+f"(c[2]), "+f"(c[3])
                 : "r"(a[0]), "r"(a[1]), "r"(a[2]), "r"(a[3]), "r"(b[0]), "r"(b[1]));
}

// shared epilogue writer
// OUT: 0 fp32+bias; 1 split ET (Ch/Cl); 2 relu+split; 3 dual-bias split (C/D);
//      4 dual-bias SINGLE ET (Ch=v+b2, Dh=v+b3); 5 SINGLE ET (Ch).
template<int OUT, typename ET>
__device__ __forceinline__ void epi_store(
    float v0, float v1, float v2, float v3,
    int gm0, int gn, int M, int ldc, long long cbase,
    float* C, ET* Ch, ET* Cl, ET* Dh, ET* Dl,
    const float* bias2, const float* bias3)
{
    if (OUT == 0) {
        if (gm0 < M) {
            float2 w; w.x = v0; w.y = v1;
            *(float2*)(C + cbase + (long long)gm0 * ldc + gn) = w;
        }
        if (gm0 + 8 < M) {
            float2 w; w.x = v2; w.y = v3;
            *(float2*)(C + cbase + (long long)(gm0 + 8) * ldc + gn) = w;
        }
    } else if (OUT == 3 || OUT == 4) {
        float2 b2 = *(const float2*)(bias2 + gn);
        float2 b3 = *(const float2*)(bias3 + gn);
        ET h0, l0, h1, l1;
        if (gm0 < M) {
            long long o = cbase + (long long)gm0 * ldc + gn;
            if (OUT == 3) {
                split_to(v0 + b2.x, h0, l0); split_to(v1 + b2.y, h1, l1);
                *(uint32_t*)(Ch + o) = pack2(h0, h1); *(uint32_t*)(Cl + o) = pack2(l0, l1);
                split_to(v0 + b3.x, h0, l0); split_to(v1 + b3.y, h1, l1);
                *(uint32_t*)(Dh + o) = pack2(h0, h1); *(uint32_t*)(Dl + o) = pack2(l0, l1);
            } else {
                cvt1(v0 + b2.x, h0); cvt1(v1 + b2.y, h1);
                *(uint32_t*)(Ch + o) = pack2(h0, h1);
                cvt1(v0 + b3.x, h0); cvt1(v1 + b3.y, h1);
                *(uint32_t*)(Dh + o) = pack2(h0, h1);
            }
        }
        if (gm0 + 8 < M) {
            long long o = cbase + (long long)(gm0 + 8) * ldc + gn;
            if (OUT == 3) {
                split_to(v2 + b2.x, h0, l0); split_to(v3 + b2.y, h1, l1);
                *(uint32_t*)(Ch + o) = pack2(h0, h1); *(uint32_t*)(Cl + o) = pack2(l0, l1);
                split_to(v2 + b3.x, h0, l0); split_to(v3 + b3.y, h1, l1);
                *(uint32_t*)(Dh + o) = pack2(h0, h1); *(uint32_t*)(Dl + o) = pack2(l0, l1);
            } else {
                cvt1(v2 + b2.x, h0); cvt1(v3 + b2.y, h1);
                *(uint32_t*)(Ch + o) = pack2(h0, h1);
                cvt1(v2 + b3.x, h0); cvt1(v3 + b3.y, h1);
                *(uint32_t*)(Dh + o) = pack2(h0, h1);
            }
        }
    } else if (OUT == 5) {
        ET h0, h1;
        if (gm0 < M) {
            long long o = cbase + (long long)gm0 * ldc + gn;
            cvt1(v0, h0); cvt1(v1, h1);
            *(uint32_t*)(Ch + o) = pack2(h0, h1);
        }
        if (gm0 + 8 < M) {
            long long o = cbase + (long long)(gm0 + 8) * ldc + gn;
            cvt1(v2, h0); cvt1(v3, h1);
            *(uint32_t*)(Ch + o) = pack2(h0, h1);
        }
    } else {
        if (OUT == 2) {
            v0 = fmaxf(v0, 0.f); v1 = fmaxf(v1, 0.f);
            v2 = fmaxf(v2, 0.f); v3 = fmaxf(v3, 0.f);
        }
        ET h0, l0, h1, l1;
        if (gm0 < M) {
            long long o = cbase + (long long)gm0 * ldc + gn;
            split_to(v0, h0, l0); split_to(v1, h1, l1);
            *(uint32_t*)(Ch + o) = pack2(h0, h1); *(uint32_t*)(Cl + o) = pack2(l0, l1);
        }
        if (gm0 + 8 < M) {
            long long o = cbase + (long long)(gm0 + 8) * ldc + gn;
            split_to(v2, h0, l0); split_to(v3, h1, l1);
            *(uint32_t*)(Ch + o) = pack2(h0, h1); *(uint32_t*)(Cl + o) = pack2(l0, l1);
        }
    }
}

// ---------------- generalized HMMA split GEMM (R8 mainloop) ----------------
// PASS=3 (bf16): hh + hl + lh. PASS=2 (fp16): hh + lh (B single). PASS=1 (fp16): hh.
// 4-stage cp.async pipeline, ONE barrier per K16 chunk.
// maskA/maskB: dead-tile skips. kclamp: effective K = min(K, m0+kclamp).
template<int BN, int OUT, int PASS, typename ET>
__global__ __launch_bounds__(256)
void hgemm(const bf16* __restrict__ Ah, const bf16* __restrict__ Al,
           const bf16* __restrict__ Bh, const bf16* __restrict__ Bl,
           float* __restrict__ C, ET* __restrict__ Ch, ET* __restrict__ Cl,
           ET* __restrict__ Dh, ET* __restrict__ Dl,
           const float* __restrict__ bias,
           const float* __restrict__ bias2, const float* __restrict__ bias3,
           int M, int N, int K, int lda, int ldb, int ldc, int Z2,
           long long sA1, long long sA2, long long sB1, long long sB2,
           long long sC1, long long sC2,
           int maskA, int maskB, int kclamp)
{
    constexpr int BSTR = BN * 32;
    constexpr int ACNT = (PASS == 1) ? 1 : 2;
    constexpr int STAGE = ACNT * 4096 + (PASS == 3 ? 2 : 1) * BSTR;
    constexpr int ABASE = ACNT * 4096;
    constexpr int MT = (BN == 128) ? 4 : 2;
    extern __shared__ __align__(128) char sm[];
    const uint32_t smb = smem_u32(sm);
    const int tid = threadIdx.x, wid = tid >> 5, lane = tid & 31;
    const int m0 = blockIdx.x * 128, n0 = blockIdx.y * BN;
    if (maskA >= 0 && n0 > m0 + maskA) return;
    if (maskB >= 0 && m0 + n0 < maskB) return;
    const int Keff = (kclamp >= 0) ? min(K, m0 + kclamp) : K;

    const int m_w = (BN == 128) ? (wid & 1) * 64 : (wid & 3) * 32;
    const int n_w = (BN == 128) ? (wid >> 1) * 32 : (wid >> 2) * 32;

    const int z = blockIdx.z;
    const int z1 = z / Z2, z2 = z - z1 * Z2;
    Ah += z1 * sA1 + z2 * sA2;
    if (PASS != 1) Al += z1 * sA1 + z2 * sA2;
    Bh += z1 * sB1 + z2 * sB2;
    if (PASS == 3) Bl += z1 * sB1 + z2 * sB2;
    const long long cbase = z1 * sC1 + z2 * sC2;

    const int lr = tid >> 1, lc = tid & 1;
    const uint32_t so = (uint32_t)(lr * 32 + ((lc ^ ((lr >> 2) & 1)) << 4));
    const int ga = min(m0 + lr, M - 1);
    const long long aoff = (long long)ga * lda + lc * 8;
    const bool bdo = (BN == 128) || (tid < 128);
    const int gb = min(n0 + lr, N - 1);
    const long long boff = (long long)gb * ldb + lc * 8;

    float acc[MT][4][4];
    #pragma unroll
    for (int i = 0; i < MT; i++)
        #pragma unroll
        for (int j = 0; j < 4; j++)
            #pragma unroll
            for (int k = 0; k < 4; k++) acc[i][j][k] = 0.f;

    const int NC = Keff / 16;

    // prologue: stages 0,1,2
    #pragma unroll
    for (int pc = 0; pc < 3; pc++) {
        const uint32_t st = smb + pc * STAGE;
        cp16(st + so, Ah + aoff + pc * 16);
        if (PASS != 1) cp16(st + 4096 + so, Al + aoff + pc * 16);
        if (bdo) {
            cp16(st + ABASE + so, Bh + boff + pc * 16);
            if (PASS == 3) cp16(st + ABASE + BSTR + so, Bl + boff + pc * 16);
        }
        asm volatile("cp.async.commit_group;");
    }

    const int rr = lane & 15, ccq = lane >> 4;
    const int rbq = (lane & 7) | ((lane & 16) >> 1);
    const int cbq = (lane >> 3) & 1;

    for (int c = 0; c < NC; c++) {
        asm volatile("cp.async.wait_group 2;");
        __syncthreads();
        if (c + 3 < NC) {
            const uint32_t st = smb + ((c + 3) & 3) * STAGE;
            const long long k0 = (long long)(c + 3) * 16;
            cp16(st + so, Ah + aoff + k0);
            if (PASS != 1) cp16(st + 4096 + so, Al + aoff + k0);
            if (bdo) {
                cp16(st + ABASE + so, Bh + boff + k0);
                if (PASS == 3) cp16(st + ABASE + BSTR + so, Bl + boff + k0);
            }
        }
        asm volatile("cp.async.commit_group;");

        const uint32_t st = smb + (c & 3) * STAGE;
        uint32_t ah[MT][4], al[MT][4], bh[2][4], bl[2][4];
        #pragma unroll
        for (int mt = 0; mt < MT; mt++) {
            int R = m_w + mt * 16 + rr;
            uint32_t ad = st + R * 32 + ((ccq ^ ((R >> 2) & 1)) << 4);
            ldx4(ah[mt], ad);
            if (PASS != 1) ldx4(al[mt], ad + 4096);
        }
        #pragma unroll
        for (int np = 0; np < 2; np++) {
            int Nr = n_w + np * 16 + rbq;
            uint32_t bd = st + ABASE + Nr * 32 + ((cbq ^ ((Nr >> 2) & 1)) << 4);
            ldx4(bh[np], bd);
            if (PASS == 3) ldx4(bl[np], bd + BSTR);
        }
        #pragma unroll
        for (int mt = 0; mt < MT; mt++)
            #pragma unroll
            for (int nt = 0; nt < 4; nt++) {
                const uint32_t* bhp = &bh[nt >> 1][(nt & 1) * 2];
                if (PASS == 3) {
                    const uint32_t* blp = &bl[nt >> 1][(nt & 1) * 2];
                    mma_bf(acc[mt][nt], ah[mt], bhp);
                    mma_bf(acc[mt][nt], ah[mt], blp);
                    mma_bf(acc[mt][nt], al[mt], bhp);
                } else if (PASS == 2) {
                    mma_fp(acc[mt][nt], ah[mt], bhp);
                    mma_fp(acc[mt][nt], al[mt], bhp);
                } else {
                    mma_fp(acc[mt][nt], ah[mt], bhp);
                }
            }
    }

    // ---- epilogue ----
    #pragma unroll
    for (int mt = 0; mt < MT; mt++) {
        int gm0 = m0 + m_w + mt * 16 + (lane >> 2);
        #pragma unroll
        for (int nt = 0; nt < 4; nt++) {
            int gn = n0 + n_w + nt * 8 + (lane & 3) * 2;
            if (gn >= N) continue;
            float bx = 0.f, by = 0.f;
            if (bias) { float2 bv = *(const float2*)(bias + gn); bx = bv.x; by = bv.y; }
            epi_store<OUT, ET>(acc[mt][nt][0] + bx, acc[mt][nt][1] + by,
                               acc[mt][nt][2] + bx, acc[mt][nt][3] + by,
                               gm0, gn, M, ldc, cbase, C, Ch, Cl, Dh, Dl, bias2, bias3);
        }
    }
}

// ---------------- reductions ----------------
__device__ __forceinline__ float block_reduce_sum(float v) {
    __shared__ float sm[16];
    __syncthreads();
    #pragma unroll
    for (int o = 16; o > 0; o >>= 1) v += __shfl_xor_sync(0xffffffffu, v, o);
    if ((threadIdx.x & 31) == 0) sm[threadIdx.x >> 5] = v;
    __syncthreads();
    if (threadIdx.x < 32) {
        float x = (threadIdx.x < (blockDim.x >> 5)) ? sm[threadIdx.x] : 0.f;
        #pragma unroll
        for (int o = 8; o > 0; o >>= 1) x += __shfl_xor_sync(0xffffffffu, x, o);
        if (threadIdx.x == 0) sm[0] = x;
    }
    __syncthreads();
    return sm[0];
}
__device__ __forceinline__ float block_reduce_max(float v) {
    __shared__ float sm[16];
    __syncthreads();
    #pragma unroll
    for (int o = 16; o > 0; o >>= 1) v = fmaxf(v, __shfl_xor_sync(0xffffffffu, v, o));
    if ((threadIdx.x & 31) == 0) sm[threadIdx.x >> 5] = v;
    __syncthreads();
    if (threadIdx.x < 32) {
        float x = (threadIdx.x < (blockDim.x >> 5)) ? sm[threadIdx.x] : -3.4e38f;
        #pragma unroll
        for (int o = 8; o > 0; o >>= 1) x = fmaxf(x, __shfl_xor_sync(0xffffffffu, x, o));
        if (threadIdx.x == 0) sm[0] = x;
    }
    __syncthreads();
    return sm[0];
}

// ---------------- small kernels ----------------
__global__ void build_full(const int* __restrict__ tokens,
                           const float* __restrict__ memory,
                           const float* __restrict__ embed,
                           float* __restrict__ x,
                           __half* __restrict__ xh, __half* __restrict__ xl,
                           __half* __restrict__ fullh, __half* __restrict__ fulll)
{
    long long idx = (long long)blockIdx.x * 256 + threadIdx.x;
    const long long tot = (long long)BB * KLEN * UU;
    if (idx >= tot) return;
    int u = (int)(idx % UU);
    long long t = idx / UU;
    int j = (int)(t % KLEN);
    int b = (int)(t / KLEN);
    float v;
    if (j < MEMLEN) {
        v = memory[((long long)b * MEMLEN + j) * UU + u];
    } else {
        int s = j - MEMLEN;
        int tok = tokens[b * SS + s];
        v = embed[(long long)tok * UU + u] * 32.0f;  // sqrt(1024)
        long long xo = ((long long)b * SS + s) * UU + u;
        x[xo] = v;
        __half h, l; split_to(v, h, l);
        xh[xo] = h; xl[xo] = l;
    }
    __half h, l; split_to(v, h, l);
    fullh[idx] = h; fulll[idx] = l;
}

__global__ void pos_embed(__half* __restrict__ relh, __half* __restrict__ rell)
{
    long long idx = (long long)blockIdx.x * 256 + threadIdx.x;
    if (idx >= (long long)KLEN * UU) return;
    int u = (int)(idx % UU);
    int jj = (int)(idx / UU);
    float pos = (float)(KLEN - 1 - jj);
    int i2 = (u < UU / 2) ? u : (u - UU / 2);
    float expo = ((float)(2 * i2)) / (float)UU;
    float invf = expf(-expo * 9.210340371976184f);  // ln(10000)
    float ang = pos * invf;
    float v = (u < UU / 2) ? sinf(ang) : cosf(ang);
    __half h, l; split_to(v, h, l);
    relh[idx] = h; rell[idx] = l;
}

// transpose: W[K,N] fp32 -> single fp16 [N,K]
__global__ void split_T_h(const float* __restrict__ W, __half* __restrict__ hi,
                          int K, int N)
{
    __shared__ float t[32][33];
    int n0 = blockIdx.x * 32, k0 = blockIdx.y * 32;
    #pragma unroll
    for (int i = 0; i < 32; i += 8)
        t[threadIdx.y + i][threadIdx.x] =
            W[(long long)(k0 + threadIdx.y + i) * N + n0 + threadIdx.x];
    __syncthreads();
    #pragma unroll
    for (int i = 0; i < 32; i += 8) {
        float v = t[threadIdx.x][threadIdx.y + i];
        long long o = (long long)(n0 + threadIdx.y + i) * K + k0 + threadIdx.x;
        hi[o] = __float2half(v);
    }
}

// V^T per head (single fp16): vt[(b*H+h), d, j] = kv[b, j, U + h*64 + d]
__global__ void transpose_v(const __half* __restrict__ kv, __half* __restrict__ vt)
{
    __shared__ __half th[32][33];
    int z = blockIdx.z;
    int b = z / HH, h = z % HH;
    int j0 = blockIdx.x * 32, d0 = blockIdx.y * 32;
    int tx = threadIdx.x, ty = threadIdx.y;
    #pragma unroll
    for (int i = 0; i < 32; i += 8) {
        long long src = ((long long)b * KLEN + j0 + ty + i) * (2 * UU) + UU + h * 64 + d0 + tx;
        th[ty + i][tx] = kv[src];
    }
    __syncthreads();
    #pragma unroll
    for (int i = 0; i < 32; i += 8) {
        long long dst = ((long long)z * DD + d0 + ty + i) * KLEN + j0 + tx;
        vt[dst] = th[tx][ty + i];
    }
}

// mask + rel-shift + softmax; writes P as single fp16 (zero tail)
__global__ __launch_bounds__(256)
void attn_softmax(const float* __restrict__ ac, const float* __restrict__ ar,
                  __half* __restrict__ p)
{
    int i = blockIdx.x;
    long long z = blockIdx.y;
    const float* arow = ac + (z * SS + i) * (long long)KLEN;
    const float* rrow = ar + (z * SS + i) * (long long)KLEN;
    __half* pr = p + (z * SS + i) * (long long)KLEN;
    int lim = i + MEMLEN;
    int shift = SS - 1 - i;
    int tid = threadIdx.x;

    float vals[7];
    int cnt = 0;
    float lmax = -3.4e38f;
    for (int j = tid; j <= lim; j += 256) {
        float v = (arow[j] + rrow[j + shift]) * 0.125f;
        vals[cnt++] = v;
        lmax = fmaxf(lmax, v);
    }
    float m = block_reduce_max(lmax);
    float lsum = 0.f;
    for (int t = 0; t < cnt; t++) {
        float e = expf(vals[t] - m);
        vals[t] = e;
        lsum += e;
    }
    float s = block_reduce_sum(lsum);
    float inv = 1.f / s;
    cnt = 0;
    for (int j = tid; j <= lim; j += 256) {
        pr[j] = __float2half(vals[cnt++] * inv);
    }
    __half z0 = __float2half(0.f);
    for (int j = lim + 1 + tid; j < KLEN; j += 256) pr[j] = z0;
}

// add + LayerNorm; emits fp32 (optional) plus fp16 split pair
__global__ __launch_bounds__(256)
void add_ln(const float* __restrict__ a, const float* __restrict__ b,
            const float* __restrict__ g, const float* __restrict__ beta,
            float* __restrict__ out, __half* __restrict__ oh, __half* __restrict__ ol)
{
    long long row = blockIdx.x;
    const float* pa = a + row * UU;
    const float* pb = b + row * UU;
    int tid = threadIdx.x;
    float vals[4];
    float s = 0.f, ss = 0.f;
    #pragma unroll
    for (int t = 0; t < 4; t++) {
        int idx = tid * 4 + t;
        float v = pa[idx] + pb[idx];
        vals[t] = v;
        s += v;
        ss += v * v;
    }
    s = block_reduce_sum(s);
    ss = block_reduce_sum(ss);
    float mean = s * (1.f / UU);
    float var = fmaxf(ss * (1.f / UU) - mean * mean, 0.f);
    float rstd = rsqrtf(var + 1e-5f);
    #pragma unroll
    for (int t = 0; t < 4; t++) {
        int idx = tid * 4 + t;
        float v = (vals[t] - mean) * rstd * g[idx] + beta[idx];
        if (out) out[row * UU + idx] = v;
        __half h, l; split_to(v, h, l);
        oh[row * UU + idx] = h; ol[row * UU + idx] = l;
    }
}

// online-softmax over vocab rows, in place
__global__ __launch_bounds__(512)
void softmax_rows(float* __restrict__ x, int N)
{
    __shared__ float smm[16], sms[16];
    long long row = blockIdx.x;
    float* p = x + row * (long long)N;
    int tid = threadIdx.x;
    float m = -3.4e38f, s = 0.f;
    for (int j = tid; j < N; j += 512) {
        float v = p[j];
        if (v > m) { s = s * expf(m - v) + 1.f; m = v; }
        else       { s += expf(v - m); }
    }
    #pragma unroll
    for (int o = 16; o > 0; o >>= 1) {
        float m2 = __shfl_xor_sync(0xffffffffu, m, o);
        float s2 = __shfl_xor_sync(0xffffffffu, s, o);
        float M = fmaxf(m, m2);
        s = s * expf(m - M) + s2 * expf(m2 - M);
        m = M;
    }
    if ((tid & 31) == 0) { smm[tid >> 5] = m; sms[tid >> 5] = s; }
    __syncthreads();
    if (tid < 32) {
        float mm = (tid < 16) ? smm[tid] : -3.4e38f;
        float ssv = (tid < 16) ? sms[tid] : 0.f;
        #pragma unroll
        for (int o = 8; o > 0; o >>= 1) {
            float m2 = __shfl_xor_sync(0xffffffffu, mm, o);
            float s2 = __shfl_xor_sync(0xffffffffu, ssv, o);
            float M = fmaxf(mm, m2);
            ssv = ssv * expf(mm - M) + s2 * expf(m2 - M);
            mm = M;
        }
        if (tid == 0) { smm[0] = mm; sms[0] = ssv; }
    }
    __syncthreads();
    float M = smm[0];
    float inv = 1.f / sms[0];
    for (int j = tid; j < N; j += 512) p[j] = expf(p[j] - M) * inv;
}

// ---------------- host ----------------
#define SMEM4(BN, PASS) (4 * (((PASS) == 1 ? 1 : 2) * 4096 + ((PASS) == 3 ? 2 : 1) * (BN) * 32))

extern "C" void kernel_launch(void* const* d_in, const int* in_sizes, int n_in,
                              void* d_out, int out_size)
{
    const int*   tokens  = (const int*)  d_in[0];
    const float* memory  = (const float*)d_in[1];
    const float* embed   = (const float*)d_in[2];
    const float* Wq      = (const float*)d_in[3];
    const float* Wkv     = (const float*)d_in[4];
    const float* Wr      = (const float*)d_in[5];
    const float* Wo      = (const float*)d_in[6];
    const float* bq      = (const float*)d_in[7];
    const float* bkv     = (const float*)d_in[8];
    const float* br      = (const float*)d_in[9];
    const float* bo      = (const float*)d_in[10];
    const float* bias_c  = (const float*)d_in[11];
    const float* bias_r  = (const float*)d_in[12];
    const float* ln1_g   = (const float*)d_in[13];
    const float* ln1_b   = (const float*)d_in[14];
    const float* W1      = (const float*)d_in[15];
    const float* b1      = (const float*)d_in[16];
    const float* W2      = (const float*)d_in[17];
    const float* b2      = (const float*)d_in[18];
    const float* ln2_g   = (const float*)d_in[19];
    const float* ln2_b   = (const float*)d_in[20];
    const float* Wout    = (const float*)d_in[21];
    const float* bout    = (const float*)d_in[22];
    float* out = (float*)d_out;

    static bool s_attr = false;
    if (!s_attr) {
        cudaFuncSetAttribute(hgemm<128,0,2,__half>, cudaFuncAttributeMaxDynamicSharedMemorySize, SMEM4(128,2));
        cudaFuncSetAttribute(hgemm<128,2,2,__half>, cudaFuncAttributeMaxDynamicSharedMemorySize, SMEM4(128,2));
        cudaFuncSetAttribute(hgemm<128,4,2,__half>, cudaFuncAttributeMaxDynamicSharedMemorySize, SMEM4(128,2));
        cudaFuncSetAttribute(hgemm<128,5,2,__half>, cudaFuncAttributeMaxDynamicSharedMemorySize, SMEM4(128,2));
        cudaFuncSetAttribute(hgemm<128,0,1,__half>, cudaFuncAttributeMaxDynamicSharedMemorySize, SMEM4(128,1));
        cudaFuncSetAttribute(hgemm<64,1,1,__half>,  cudaFuncAttributeMaxDynamicSharedMemorySize, SMEM4(64,1));
        s_attr = true;
    }

    float *x, *ac, *ar, *tmp, *h1;
    cudaGetSymbolAddress((void**)&x,   g_x);
    cudaGetSymbolAddress((void**)&ac,  g_ac);
    cudaGetSymbolAddress((void**)&ar,  g_ar);
    cudaGetSymbolAddress((void**)&tmp, g_tmp);
    cudaGetSymbolAddress((void**)&h1,  g_h1);

    __half *xh,*xl,*fullh,*fulll,*relh,*rell,*ctxh,*ctxl,*h1hh,*h1lh,*ffhh,*fflh,*h2hh,*h2lh;
    __half *qc,*qr,*kv,*r,*p,*vt;
    __half *WqH,*WkvH,*WrH,*WoH,*W1H,*W2H,*WoutH;
    cudaGetSymbolAddress((void**)&xh, g_xh);       cudaGetSymbolAddress((void**)&xl, g_xl);
    cudaGetSymbolAddress((void**)&fullh, g_fullh); cudaGetSymbolAddress((void**)&fulll, g_fulll);
    cudaGetSymbolAddress((void**)&relh, g_relh);   cudaGetSymbolAddress((void**)&rell, g_rell);
    cudaGetSymbolAddress((void**)&ctxh, g_ctxh);   cudaGetSymbolAddress((void**)&ctxl, g_ctxl);
    cudaGetSymbolAddress((void**)&h1hh, g_h1hh);   cudaGetSymbolAddress((void**)&h1lh, g_h1lh);
    cudaGetSymbolAddress((void**)&ffhh, g_ffhh);   cudaGetSymbolAddress((void**)&fflh, g_fflh);
    cudaGetSymbolAddress((void**)&h2hh, g_h2hh);   cudaGetSymbolAddress((void**)&h2lh, g_h2lh);
    cudaGetSymbolAddress((void**)&qc, g_qc);       cudaGetSymbolAddress((void**)&qr, g_qr);
    cudaGetSymbolAddress((void**)&kv, g_kv);       cudaGetSymbolAddress((void**)&r, g_r);
    cudaGetSymbolAddress((void**)&p, g_p);         cudaGetSymbolAddress((void**)&vt, g_vt);
    cudaGetSymbolAddress((void**)&WqH, g_WqH);     cudaGetSymbolAddress((void**)&WkvH, g_WkvH);
    cudaGetSymbolAddress((void**)&WrH, g_WrH);     cudaGetSymbolAddress((void**)&WoH, g_WoH);
    cudaGetSymbolAddress((void**)&W1H, g_W1H);     cudaGetSymbolAddress((void**)&W2H, g_W2H);
    cudaGetSymbolAddress((void**)&WoutH, g_WoutH);

    const int M_TOK = BB * SS;      // 2048
    const int M_FULL = BB * KLEN;   // 3200
    dim3 tb(32, 8);

    // 1) embedding + concat + fp16 splits
    {
        long long tot = (long long)BB * KLEN * UU;
        build_full<<<(unsigned)((tot + 255) / 256), 256>>>(tokens, memory, embed,
                                                           x, xh, xl, fullh, fulll);
    }
    // 2) Wkv -> fp16
    split_T_h<<<dim3(2*UU/32, UU/32), tb>>>(Wkv, WkvH, UU, 2*UU);
    // 3) positional embedding
    {
        long long tot = (long long)KLEN * UU;
        pos_embed<<<(unsigned)((tot + 255) / 256), 256>>>(relh, rell);
    }
    // 4) kv projection (fp16 2-pass, single fp16 out)  <-- ncu capture target
    hgemm<128,5,2,__half><<<dim3(M_FULL/128, 2*UU/128, 1), 256, SMEM4(128,2)>>>(
        (const bf16*)fullh, (const bf16*)fulll, (const bf16*)WkvH, nullptr,
        nullptr, kv, nullptr, nullptr, nullptr, bkv, nullptr, nullptr,
        M_FULL, 2*UU, UU, UU, UU, 2*UU, 1, 0,0,0,0,0,0, -1,-1,-1);
    // remaining weight conversions
    split_T_h<<<dim3(UU/32,  UU/32),  tb>>>(Wq,   WqH,   UU,  UU);
    split_T_h<<<dim3(UU/32,  UU/32),  tb>>>(Wr,   WrH,   UU,  UU);
    split_T_h<<<dim3(UU/32,  UU/32),  tb>>>(Wo,   WoH,   UU,  UU);
    split_T_h<<<dim3(FFD/32, UU/32),  tb>>>(W1,   W1H,   UU,  FFD);
    split_T_h<<<dim3(UU/32,  FFD/32), tb>>>(W2,   W2H,   FFD, UU);
    split_T_h<<<dim3(NT/32,  UU/32),  tb>>>(Wout, WoutH, UU,  NT);
    // q projection fused with (q+u)/(q+v) single-fp16 outputs
    hgemm<128,4,2,__half><<<dim3(M_TOK/128, UU/128, 1), 256, SMEM4(128,2)>>>(
        (const bf16*)xh, (const bf16*)xl, (const bf16*)WqH, nullptr,
        nullptr, qc, nullptr, qr, nullptr, bq, bias_c, bias_r,
        M_TOK, UU, UU, UU, UU, UU, 1, 0,0,0,0,0,0, -1,-1,-1);
    // r projection (single fp16 out)
    hgemm<128,5,2,__half><<<dim3((KLEN+127)/128, UU/128, 1), 256, SMEM4(128,2)>>>(
        (const bf16*)relh, (const bf16*)rell, (const bf16*)WrH, nullptr,
        nullptr, r, nullptr, nullptr, nullptr, br, nullptr, nullptr,
        KLEN, UU, UU, UU, UU, UU, 1, 0,0,0,0,0,0, -1,-1,-1);
    // scores (fp16 SINGLE-pass, batched over b,h), dead-tile skips
    {
        dim3 grid(SS / 128, (KLEN + 127) / 128, BB * HH);
        hgemm<128,0,1,__half><<<grid, 256, SMEM4(128,1)>>>(
            (const bf16*)qc, nullptr, (const bf16*)kv, nullptr, ac,
            (__half*)nullptr, (__half*)nullptr, (__half*)nullptr, (__half*)nullptr,
            nullptr, nullptr, nullptr,
            SS, KLEN, DD, UU, 2*UU, KLEN, HH,
            (long long)SS*UU, 64,
            (long long)KLEN*2*UU, 64,
            (long long)HH*SS*KLEN, (long long)SS*KLEN,
            MEMLEN + 127, -1, -1);
        hgemm<128,0,1,__half><<<grid, 256, SMEM4(128,1)>>>(
            (const bf16*)qr, nullptr, (const bf16*)r, nullptr, ar,
            (__half*)nullptr, (__half*)nullptr, (__half*)nullptr, (__half*)nullptr,
            nullptr, nullptr, nullptr,
            SS, KLEN, DD, UU, UU, KLEN, HH,
            (long long)SS*UU, 64,
            0, 64,
            (long long)HH*SS*KLEN, (long long)SS*KLEN,
            -1, SS - 255, -1);
    }
    // fused rel-shift + mask + softmax -> single-fp16 P
    {
        dim3 grid(SS, BB * HH);
        attn_softmax<<<grid, 256>>>(ac, ar, p);
    }
    // V^T per head (single fp16)
    {
        dim3 grid(KLEN / 32, DD / 32, BB * HH);
        transpose_v<<<grid, tb>>>(kv, vt);
    }
    // ctx = P @ V^T (fp16 SINGLE-pass, K clamp), fp16 split output for Wo
    {
        dim3 grid(SS / 128, 1, BB * HH);
        hgemm<64,1,1,__half><<<grid, 256, SMEM4(64,1)>>>(
            (const bf16*)p, nullptr, (const bf16*)vt, nullptr, nullptr,
            ctxh, ctxl, (__half*)nullptr, (__half*)nullptr,
            nullptr, nullptr, nullptr,
            SS, DD, KLEN, KLEN, KLEN, UU, HH,
            (long long)HH*SS*KLEN, (long long)SS*KLEN,
            (long long)HH*DD*KLEN, (long long)DD*KLEN,
            (long long)SS*UU, 64,
            -1, -1, MEMLEN + 128);
    }
    // attention out projection + LN1 (fp16 2-pass)
    hgemm<128,0,2,__half><<<dim3(M_TOK/128, UU/128, 1), 256, SMEM4(128,2)>>>(
        (const bf16*)ctxh, (const bf16*)ctxl, (const bf16*)WoH, nullptr,
        tmp, (__half*)nullptr, (__half*)nullptr, (__half*)nullptr, (__half*)nullptr,
        bo, nullptr, nullptr,
        M_TOK, UU, UU, UU, UU, UU, 1, 0,0,0,0,0,0, -1,-1,-1);
    add_ln<<<M_TOK, 256>>>(x, tmp, ln1_g, ln1_b, h1, h1hh, h1lh);
    // FF (fp16 2-pass)
    hgemm<128,2,2,__half><<<dim3(M_TOK/128, FFD/128, 1), 256, SMEM4(128,2)>>>(
        (const bf16*)h1hh, (const bf16*)h1lh, (const bf16*)W1H, nullptr,
        nullptr, ffhh, fflh, (__half*)nullptr, (__half*)nullptr, b1, nullptr, nullptr,
        M_TOK, FFD, UU, UU, UU, FFD, 1, 0,0,0,0,0,0, -1,-1,-1);
    hgemm<128,0,2,__half><<<dim3(M_TOK/128, UU/128, 1), 256, SMEM4(128,2)>>>(
        (const bf16*)ffhh, (const bf16*)fflh, (const bf16*)W2H, nullptr,
        tmp, (__half*)nullptr, (__half*)nullptr, (__half*)nullptr, (__half*)nullptr,
        b2, nullptr, nullptr,
        M_TOK, UU, FFD, FFD, FFD, UU, 1, 0,0,0,0,0,0, -1,-1,-1);
    add_ln<<<M_TOK, 256>>>(h1, tmp, ln2_g, ln2_b, nullptr, h2hh, h2lh);
    // logits (fp16 single-pass) + softmax
    hgemm<128,0,1,__half><<<dim3(M_TOK/128, NT/128, 1), 256, SMEM4(128,1)>>>(
        (const bf16*)h2hh, nullptr, (const bf16*)WoutH, nullptr,
        out, (__half*)nullptr, (__half*)nullptr, (__half*)nullptr, (__half*)nullptr,
        bout, nullptr, nullptr,
        M_TOK, NT, UU, UU, UU, NT, 1, 0,0,0,0,0,0, -1,-1,-1);
    softmax_rows<<<M_TOK, 512>>>(out, NT);
}

// round 16
// speedup vs baseline: 2.0695x; 1.1682x over previous
#include <cuda_runtime.h>
#include <cuda_bf16.h>
#include <cuda_fp16.h>
#include <math.h>
#include <stdint.h>

// ---------------- problem constants ----------------
#define BB 2
#define SS 1024
#define UU 1024
#define HH 16
#define DD 64
#define NT 32000
#define MEMLEN 576
#define FFD 4096
#define KLEN 1600   // MEM + S
#define VOCAB 1024

// ---------------- scratch (device globals; no allocation allowed) ----------------
__device__ float g_ac  [(size_t)BB*HH*SS*KLEN];
__device__ float g_ar  [(size_t)BB*HH*SS*KLEN];
__device__ float g_x   [(size_t)BB*SS*UU];
__device__ float g_tmp [(size_t)BB*SS*UU];
__device__ float g_h1  [(size_t)BB*SS*UU];

// single fp16 activations
__device__ __half g_xh   [(size_t)BB*SS*UU];
__device__ __half g_fullh[(size_t)BB*KLEN*UU];
__device__ __half g_relh [(size_t)KLEN*UU];
__device__ __half g_ctx  [(size_t)BB*SS*UU];
__device__ __half g_h1h  [(size_t)BB*SS*UU];
__device__ __half g_ffh  [(size_t)BB*SS*FFD];
__device__ __half g_h2h  [(size_t)BB*SS*UU];
__device__ __half g_qc   [(size_t)BB*SS*UU];
__device__ __half g_qr   [(size_t)BB*SS*UU];
__device__ __half g_kv   [(size_t)BB*KLEN*2*UU];
__device__ __half g_r    [(size_t)KLEN*UU];
__device__ __half g_p    [(size_t)BB*HH*SS*KLEN];
__device__ __half g_vt   [(size_t)BB*HH*DD*KLEN];
// single-fp16 transposed weights [N,K]
__device__ __half g_WqH [(size_t)UU*UU];
__device__ __half g_WkvH[(size_t)2*UU*UU];
__device__ __half g_WrH [(size_t)UU*UU];
__device__ __half g_WoH [(size_t)UU*UU];
__device__ __half g_W1H [(size_t)FFD*UU];
__device__ __half g_W2H [(size_t)UU*FFD];
__device__ __half g_WoutH[(size_t)NT*UU];

// ---------------- helpers ----------------
__device__ __forceinline__ uint32_t smem_u32(const void* p) {
    uint32_t a;
    asm("{ .reg .u64 t; cvta.to.shared.u64 t, %1; cvt.u32.u64 %0, t; }" : "=r"(a) : "l"(p));
    return a;
}
__device__ __forceinline__ uint32_t pack2h(__half a, __half b) {
    unsigned short x = *(unsigned short*)&a, y = *(unsigned short*)&b;
    return (uint32_t)x | ((uint32_t)y << 16);
}
__device__ __forceinline__ void cp16(uint32_t dst, const void* src) {
    asm volatile("cp.async.cg.shared.global [%0], [%1], 16;" :: "r"(dst), "l"(src));
}
__device__ __forceinline__ void ldx4(uint32_t* r, uint32_t addr) {
    asm volatile("ldmatrix.sync.aligned.m8n8.x4.shared.b16 {%0,%1,%2,%3}, [%4];"
                 : "=r"(r[0]), "=r"(r[1]), "=r"(r[2]), "=r"(r[3]) : "r"(addr));
}
__device__ __forceinline__ void mma_fp(float* c, const uint32_t* a, const uint32_t* b) {
    asm volatile("mma.sync.aligned.m16n8k16.row.col.f32.f16.f16.f32 "
                 "{%0,%1,%2,%3}, {%4,%5,%6,%7}, {%8,%9}, {%0,%1,%2,%3};"
                 : "+f"(c[0]), "+f"(c[1]), "+f"(c[2]), "+f"(c[3])
                 : "r"(a[0]), "r"(a[1]), "r"(a[2]), "r"(a[3]), "r"(b[0]), "r"(b[1]));
}

// epilogue writer
// OUT: 0 fp32 C (+bias); 4 dual-bias single (Ch=v+b2, Dh=v+b3); 5 single fp16 (+bias);
//      6 relu + single fp16 (+bias).
template<int OUT>
__device__ __forceinline__ void epi_store(
    float v0, float v1, float v2, float v3,
    int gm0, int gn, int M, int ldc, long long cbase,
    float* C, __half* Ch, __half* Dh,
    const float* bias2, const float* bias3)
{
    if (OUT == 0) {
        if (gm0 < M) {
            float2 w; w.x = v0; w.y = v1;
            *(float2*)(C + cbase + (long long)gm0 * ldc + gn) = w;
        }
        if (gm0 + 8 < M) {
            float2 w; w.x = v2; w.y = v3;
            *(float2*)(C + cbase + (long long)(gm0 + 8) * ldc + gn) = w;
        }
    } else if (OUT == 4) {
        float2 b2 = *(const float2*)(bias2 + gn);
        float2 b3 = *(const float2*)(bias3 + gn);
        if (gm0 < M) {
            long long o = cbase + (long long)gm0 * ldc + gn;
            *(uint32_t*)(Ch + o) = pack2h(__float2half(v0 + b2.x), __float2half(v1 + b2.y));
            *(uint32_t*)(Dh + o) = pack2h(__float2half(v0 + b3.x), __float2half(v1 + b3.y));
        }
        if (gm0 + 8 < M) {
            long long o = cbase + (long long)(gm0 + 8) * ldc + gn;
            *(uint32_t*)(Ch + o) = pack2h(__float2half(v2 + b2.x), __float2half(v3 + b2.y));
            *(uint32_t*)(Dh + o) = pack2h(__float2half(v2 + b3.x), __float2half(v3 + b3.y));
        }
    } else {
        if (OUT == 6) {
            v0 = fmaxf(v0, 0.f); v1 = fmaxf(v1, 0.f);
            v2 = fmaxf(v2, 0.f); v3 = fmaxf(v3, 0.f);
        }
        if (gm0 < M) {
            long long o = cbase + (long long)gm0 * ldc + gn;
            *(uint32_t*)(Ch + o) = pack2h(__float2half(v0), __float2half(v1));
        }
        if (gm0 + 8 < M) {
            long long o = cbase + (long long)(gm0 + 8) * ldc + gn;
            *(uint32_t*)(Ch + o) = pack2h(__float2half(v2), __float2half(v3));
        }
    }
}

// ---------------- single-pass fp16 HMMA GEMM (R8 mainloop) ----------------
// C[M,N] = A[M,K] @ B[N,K]^T (+bias), fp32 accum, fp16 operands.
// 4-stage cp.async pipeline, ONE barrier per K16 chunk.
// maskA/maskB: dead-tile skips. kclamp: effective K = min(K, m0+kclamp).
template<int BN, int OUT>
__global__ __launch_bounds__(256)
void hgemm(const __half* __restrict__ A, const __half* __restrict__ B,
           float* __restrict__ C, __half* __restrict__ Ch, __half* __restrict__ Dh,
           const float* __restrict__ bias,
           const float* __restrict__ bias2, const float* __restrict__ bias3,
           int M, int N, int K, int lda, int ldb, int ldc, int Z2,
           long long sA1, long long sA2, long long sB1, long long sB2,
           long long sC1, long long sC2,
           int maskA, int maskB, int kclamp)
{
    constexpr int BSTR = BN * 32;
    constexpr int STAGE = 4096 + BSTR;
    constexpr int MT = (BN == 128) ? 4 : 2;
    extern __shared__ __align__(128) char sm[];
    const uint32_t smb = smem_u32(sm);
    const int tid = threadIdx.x, wid = tid >> 5, lane = tid & 31;
    const int m0 = blockIdx.x * 128, n0 = blockIdx.y * BN;
    if (maskA >= 0 && n0 > m0 + maskA) return;
    if (maskB >= 0 && m0 + n0 < maskB) return;
    const int Keff = (kclamp >= 0) ? min(K, m0 + kclamp) : K;

    const int m_w = (BN == 128) ? (wid & 1) * 64 : (wid & 3) * 32;
    const int n_w = (BN == 128) ? (wid >> 1) * 32 : (wid >> 2) * 32;

    const int z = blockIdx.z;
    const int z1 = z / Z2, z2 = z - z1 * Z2;
    A += z1 * sA1 + z2 * sA2;
    B += z1 * sB1 + z2 * sB2;
    const long long cbase = z1 * sC1 + z2 * sC2;

    const int lr = tid >> 1, lc = tid & 1;
    const uint32_t so = (uint32_t)(lr * 32 + ((lc ^ ((lr >> 2) & 1)) << 4));
    const int ga = min(m0 + lr, M - 1);
    const long long aoff = (long long)ga * lda + lc * 8;
    const bool bdo = (BN == 128) || (tid < 128);
    const int gb = min(n0 + lr, N - 1);
    const long long boff = (long long)gb * ldb + lc * 8;

    float acc[MT][4][4];
    #pragma unroll
    for (int i = 0; i < MT; i++)
        #pragma unroll
        for (int j = 0; j < 4; j++)
            #pragma unroll
            for (int k = 0; k < 4; k++) acc[i][j][k] = 0.f;

    const int NC = Keff / 16;

    // prologue: stages 0,1,2
    #pragma unroll
    for (int pc = 0; pc < 3; pc++) {
        const uint32_t st = smb + pc * STAGE;
        cp16(st + so, A + aoff + pc * 16);
        if (bdo) cp16(st + 4096 + so, B + boff + pc * 16);
        asm volatile("cp.async.commit_group;");
    }

    const int rr = lane & 15, ccq = lane >> 4;
    const int rbq = (lane & 7) | ((lane & 16) >> 1);
    const int cbq = (lane >> 3) & 1;

    for (int c = 0; c < NC; c++) {
        asm volatile("cp.async.wait_group 2;");
        __syncthreads();
        if (c + 3 < NC) {
            const uint32_t st = smb + ((c + 3) & 3) * STAGE;
            const long long k0 = (long long)(c + 3) * 16;
            cp16(st + so, A + aoff + k0);
            if (bdo) cp16(st + 4096 + so, B + boff + k0);
        }
        asm volatile("cp.async.commit_group;");

        const uint32_t st = smb + (c & 3) * STAGE;
        uint32_t ah[MT][4], bh[2][4];
        #pragma unroll
        for (int mt = 0; mt < MT; mt++) {
            int R = m_w + mt * 16 + rr;
            uint32_t ad = st + R * 32 + ((ccq ^ ((R >> 2) & 1)) << 4);
            ldx4(ah[mt], ad);
        }
        #pragma unroll
        for (int np = 0; np < 2; np++) {
            int Nr = n_w + np * 16 + rbq;
            uint32_t bd = st + 4096 + Nr * 32 + ((cbq ^ ((Nr >> 2) & 1)) << 4);
            ldx4(bh[np], bd);
        }
        #pragma unroll
        for (int mt = 0; mt < MT; mt++)
            #pragma unroll
            for (int nt = 0; nt < 4; nt++)
                mma_fp(acc[mt][nt], ah[mt], &bh[nt >> 1][(nt & 1) * 2]);
    }

    // ---- epilogue ----
    #pragma unroll
    for (int mt = 0; mt < MT; mt++) {
        int gm0 = m0 + m_w + mt * 16 + (lane >> 2);
        #pragma unroll
        for (int nt = 0; nt < 4; nt++) {
            int gn = n0 + n_w + nt * 8 + (lane & 3) * 2;
            if (gn >= N) continue;
            float bx = 0.f, by = 0.f;
            if (bias) { float2 bv = *(const float2*)(bias + gn); bx = bv.x; by = bv.y; }
            epi_store<OUT>(acc[mt][nt][0] + bx, acc[mt][nt][1] + by,
                           acc[mt][nt][2] + bx, acc[mt][nt][3] + by,
                           gm0, gn, M, ldc, cbase, C, Ch, Dh, bias2, bias3);
        }
    }
}

// ---------------- reductions ----------------
__device__ __forceinline__ float block_reduce_sum(float v) {
    __shared__ float sm[16];
    __syncthreads();
    #pragma unroll
    for (int o = 16; o > 0; o >>= 1) v += __shfl_xor_sync(0xffffffffu, v, o);
    if ((threadIdx.x & 31) == 0) sm[threadIdx.x >> 5] = v;
    __syncthreads();
    if (threadIdx.x < 32) {
        float x = (threadIdx.x < (blockDim.x >> 5)) ? sm[threadIdx.x] : 0.f;
        #pragma unroll
        for (int o = 8; o > 0; o >>= 1) x += __shfl_xor_sync(0xffffffffu, x, o);
        if (threadIdx.x == 0) sm[0] = x;
    }
    __syncthreads();
    return sm[0];
}
__device__ __forceinline__ float block_reduce_max(float v) {
    __shared__ float sm[16];
    __syncthreads();
    #pragma unroll
    for (int o = 16; o > 0; o >>= 1) v = fmaxf(v, __shfl_xor_sync(0xffffffffu, v, o));
    if ((threadIdx.x & 31) == 0) sm[threadIdx.x >> 5] = v;
    __syncthreads();
    if (threadIdx.x < 32) {
        float x = (threadIdx.x < (blockDim.x >> 5)) ? sm[threadIdx.x] : -3.4e38f;
        #pragma unroll
        for (int o = 8; o > 0; o >>= 1) x = fmaxf(x, __shfl_xor_sync(0xffffffffu, x, o));
        if (threadIdx.x == 0) sm[0] = x;
    }
    __syncthreads();
    return sm[0];
}

// ---------------- small kernels ----------------
__global__ void build_full(const int* __restrict__ tokens,
                           const float* __restrict__ memory,
                           const float* __restrict__ embed,
                           float* __restrict__ x,
                           __half* __restrict__ xh, __half* __restrict__ fullh)
{
    long long idx = (long long)blockIdx.x * 256 + threadIdx.x;
    const long long tot = (long long)BB * KLEN * UU;
    if (idx >= tot) return;
    int u = (int)(idx % UU);
    long long t = idx / UU;
    int j = (int)(t % KLEN);
    int b = (int)(t / KLEN);
    float v;
    if (j < MEMLEN) {
        v = memory[((long long)b * MEMLEN + j) * UU + u];
    } else {
        int s = j - MEMLEN;
        int tok = tokens[b * SS + s];
        v = embed[(long long)tok * UU + u] * 32.0f;  // sqrt(1024)
        long long xo = ((long long)b * SS + s) * UU + u;
        x[xo] = v;
        xh[xo] = __float2half(v);
    }
    fullh[idx] = __float2half(v);
}

__global__ void pos_embed(__half* __restrict__ relh)
{
    long long idx = (long long)blockIdx.x * 256 + threadIdx.x;
    if (idx >= (long long)KLEN * UU) return;
    int u = (int)(idx % UU);
    int jj = (int)(idx / UU);
    float pos = (float)(KLEN - 1 - jj);
    int i2 = (u < UU / 2) ? u : (u - UU / 2);
    float expo = ((float)(2 * i2)) / (float)UU;
    float invf = expf(-expo * 9.210340371976184f);  // ln(10000)
    float ang = pos * invf;
    relh[idx] = __float2half((u < UU / 2) ? sinf(ang) : cosf(ang));
}

// transpose: W[K,N] fp32 -> single fp16 [N,K]
__global__ void split_T_h(const float* __restrict__ W, __half* __restrict__ hi,
                          int K, int N)
{
    __shared__ float t[32][33];
    int n0 = blockIdx.x * 32, k0 = blockIdx.y * 32;
    #pragma unroll
    for (int i = 0; i < 32; i += 8)
        t[threadIdx.y + i][threadIdx.x] =
            W[(long long)(k0 + threadIdx.y + i) * N + n0 + threadIdx.x];
    __syncthreads();
    #pragma unroll
    for (int i = 0; i < 32; i += 8) {
        float v = t[threadIdx.x][threadIdx.y + i];
        long long o = (long long)(n0 + threadIdx.y + i) * K + k0 + threadIdx.x;
        hi[o] = __float2half(v);
    }
}

// V^T per head (single fp16): vt[(b*H+h), d, j] = kv[b, j, U + h*64 + d]
__global__ void transpose_v(const __half* __restrict__ kv, __half* __restrict__ vt)
{
    __shared__ __half th[32][33];
    int z = blockIdx.z;
    int b = z / HH, h = z % HH;
    int j0 = blockIdx.x * 32, d0 = blockIdx.y * 32;
    int tx = threadIdx.x, ty = threadIdx.y;
    #pragma unroll
    for (int i = 0; i < 32; i += 8) {
        long long src = ((long long)b * KLEN + j0 + ty + i) * (2 * UU) + UU + h * 64 + d0 + tx;
        th[ty + i][tx] = kv[src];
    }
    __syncthreads();
    #pragma unroll
    for (int i = 0; i < 32; i += 8) {
        long long dst = ((long long)z * DD + d0 + ty + i) * KLEN + j0 + tx;
        vt[dst] = th[tx][ty + i];
    }
}

// mask + rel-shift + softmax; writes P as single fp16 (zero tail)
__global__ __launch_bounds__(256)
void attn_softmax(const float* __restrict__ ac, const float* __restrict__ ar,
                  __half* __restrict__ p)
{
    int i = blockIdx.x;
    long long z = blockIdx.y;
    const float* arow = ac + (z * SS + i) * (long long)KLEN;
    const float* rrow = ar + (z * SS + i) * (long long)KLEN;
    __half* pr = p + (z * SS + i) * (long long)KLEN;
    int lim = i + MEMLEN;
    int shift = SS - 1 - i;
    int tid = threadIdx.x;

    float vals[7];
    int cnt = 0;
    float lmax = -3.4e38f;
    for (int j = tid; j <= lim; j += 256) {
        float v = (arow[j] + rrow[j + shift]) * 0.125f;
        vals[cnt++] = v;
        lmax = fmaxf(lmax, v);
    }
    float m = block_reduce_max(lmax);
    float lsum = 0.f;
    for (int t = 0; t < cnt; t++) {
        float e = expf(vals[t] - m);
        vals[t] = e;
        lsum += e;
    }
    float s = block_reduce_sum(lsum);
    float inv = 1.f / s;
    cnt = 0;
    for (int j = tid; j <= lim; j += 256) {
        pr[j] = __float2half(vals[cnt++] * inv);
    }
    __half z0 = __float2half(0.f);
    for (int j = lim + 1 + tid; j < KLEN; j += 256) pr[j] = z0;
}

// add + LayerNorm; emits fp32 (optional) plus single fp16
__global__ __launch_bounds__(256)
void add_ln(const float* __restrict__ a, const float* __restrict__ b,
            const float* __restrict__ g, const float* __restrict__ beta,
            float* __restrict__ out, __half* __restrict__ oh)
{
    long long row = blockIdx.x;
    const float* pa = a + row * UU;
    const float* pb = b + row * UU;
    int tid = threadIdx.x;
    float vals[4];
    float s = 0.f, ss = 0.f;
    #pragma unroll
    for (int t = 0; t < 4; t++) {
        int idx = tid * 4 + t;
        float v = pa[idx] + pb[idx];
        vals[t] = v;
        s += v;
        ss += v * v;
    }
    s = block_reduce_sum(s);
    ss = block_reduce_sum(ss);
    float mean = s * (1.f / UU);
    float var = fmaxf(ss * (1.f / UU) - mean * mean, 0.f);
    float rstd = rsqrtf(var + 1e-5f);
    #pragma unroll
    for (int t = 0; t < 4; t++) {
        int idx = tid * 4 + t;
        float v = (vals[t] - mean) * rstd * g[idx] + beta[idx];
        if (out) out[row * UU + idx] = v;
        oh[row * UU + idx] = __float2half(v);
    }
}

// online-softmax over vocab rows, in place
__global__ __launch_bounds__(512)
void softmax_rows(float* __restrict__ x, int N)
{
    __shared__ float smm[16], sms[16];
    long long row = blockIdx.x;
    float* p = x + row * (long long)N;
    int tid = threadIdx.x;
    float m = -3.4e38f, s = 0.f;
    for (int j = tid; j < N; j += 512) {
        float v = p[j];
        if (v > m) { s = s * expf(m - v) + 1.f; m = v; }
        else       { s += expf(v - m); }
    }
    #pragma unroll
    for (int o = 16; o > 0; o >>= 1) {
        float m2 = __shfl_xor_sync(0xffffffffu, m, o);
        float s2 = __shfl_xor_sync(0xffffffffu, s, o);
        float M = fmaxf(m, m2);
        s = s * expf(m - M) + s2 * expf(m2 - M);
        m = M;
    }
    if ((tid & 31) == 0) { smm[tid >> 5] = m; sms[tid >> 5] = s; }
    __syncthreads();
    if (tid < 32) {
        float mm = (tid < 16) ? smm[tid] : -3.4e38f;
        float ssv = (tid < 16) ? sms[tid] : 0.f;
        #pragma unroll
        for (int o = 8; o > 0; o >>= 1) {
            float m2 = __shfl_xor_sync(0xffffffffu, mm, o);
            float s2 = __shfl_xor_sync(0xffffffffu, ssv, o);
            float M = fmaxf(mm, m2);
            ssv = ssv * expf(mm - M) + s2 * expf(m2 - M);
            mm = M;
        }
        if (tid == 0) { smm[0] = mm; sms[0] = ssv; }
    }
    __syncthreads();
    float M = smm[0];
    float inv = 1.f / sms[0];
    for (int j = tid; j < N; j += 512) p[j] = expf(p[j] - M) * inv;
}

// ---------------- host ----------------
#define SMEM1(BN) (4 * (4096 + (BN) * 32))

extern "C" void kernel_launch(void* const* d_in, const int* in_sizes, int n_in,
                              void* d_out, int out_size)
{
    const int*   tokens  = (const int*)  d_in[0];
    const float* memory  = (const float*)d_in[1];
    const float* embed   = (const float*)d_in[2];
    const float* Wq      = (const float*)d_in[3];
    const float* Wkv     = (const float*)d_in[4];
    const float* Wr      = (const float*)d_in[5];
    const float* Wo      = (const float*)d_in[6];
    const float* bq      = (const float*)d_in[7];
    const float* bkv     = (const float*)d_in[8];
    const float* br      = (const float*)d_in[9];
    const float* bo      = (const float*)d_in[10];
    const float* bias_c  = (const float*)d_in[11];
    const float* bias_r  = (const float*)d_in[12];
    const float* ln1_g   = (const float*)d_in[13];
    const float* ln1_b   = (const float*)d_in[14];
    const float* W1      = (const float*)d_in[15];
    const float* b1      = (const float*)d_in[16];
    const float* W2      = (const float*)d_in[17];
    const float* b2      = (const float*)d_in[18];
    const float* ln2_g   = (const float*)d_in[19];
    const float* ln2_b   = (const float*)d_in[20];
    const float* Wout    = (const float*)d_in[21];
    const float* bout    = (const float*)d_in[22];
    float* out = (float*)d_out;

    static bool s_attr = false;
    if (!s_attr) {
        cudaFuncSetAttribute(hgemm<128,0>, cudaFuncAttributeMaxDynamicSharedMemorySize, SMEM1(128));
        cudaFuncSetAttribute(hgemm<128,4>, cudaFuncAttributeMaxDynamicSharedMemorySize, SMEM1(128));
        cudaFuncSetAttribute(hgemm<128,5>, cudaFuncAttributeMaxDynamicSharedMemorySize, SMEM1(128));
        cudaFuncSetAttribute(hgemm<128,6>, cudaFuncAttributeMaxDynamicSharedMemorySize, SMEM1(128));
        cudaFuncSetAttribute(hgemm<64,5>,  cudaFuncAttributeMaxDynamicSharedMemorySize, SMEM1(64));
        s_attr = true;
    }

    float *x, *ac, *ar, *tmp, *h1;
    cudaGetSymbolAddress((void**)&x,   g_x);
    cudaGetSymbolAddress((void**)&ac,  g_ac);
    cudaGetSymbolAddress((void**)&ar,  g_ar);
    cudaGetSymbolAddress((void**)&tmp, g_tmp);
    cudaGetSymbolAddress((void**)&h1,  g_h1);

    __half *xh,*fullh,*relh,*ctx,*h1h,*ffh,*h2h,*qc,*qr,*kv,*r,*p,*vt;
    __half *WqH,*WkvH,*WrH,*WoH,*W1H,*W2H,*WoutH;
    cudaGetSymbolAddress((void**)&xh, g_xh);
    cudaGetSymbolAddress((void**)&fullh, g_fullh);
    cudaGetSymbolAddress((void**)&relh, g_relh);
    cudaGetSymbolAddress((void**)&ctx, g_ctx);
    cudaGetSymbolAddress((void**)&h1h, g_h1h);
    cudaGetSymbolAddress((void**)&ffh, g_ffh);
    cudaGetSymbolAddress((void**)&h2h, g_h2h);
    cudaGetSymbolAddress((void**)&qc, g_qc);       cudaGetSymbolAddress((void**)&qr, g_qr);
    cudaGetSymbolAddress((void**)&kv, g_kv);       cudaGetSymbolAddress((void**)&r, g_r);
    cudaGetSymbolAddress((void**)&p, g_p);         cudaGetSymbolAddress((void**)&vt, g_vt);
    cudaGetSymbolAddress((void**)&WqH, g_WqH);     cudaGetSymbolAddress((void**)&WkvH, g_WkvH);
    cudaGetSymbolAddress((void**)&WrH, g_WrH);     cudaGetSymbolAddress((void**)&WoH, g_WoH);
    cudaGetSymbolAddress((void**)&W1H, g_W1H);     cudaGetSymbolAddress((void**)&W2H, g_W2H);
    cudaGetSymbolAddress((void**)&WoutH, g_WoutH);

    const int M_TOK = BB * SS;      // 2048
    const int M_FULL = BB * KLEN;   // 3200
    dim3 tb(32, 8);

    // 1) embedding + concat + fp16
    {
        long long tot = (long long)BB * KLEN * UU;
        build_full<<<(unsigned)((tot + 255) / 256), 256>>>(tokens, memory, embed,
                                                           x, xh, fullh);
    }
    // 2) Wkv -> fp16
    split_T_h<<<dim3(2*UU/32, UU/32), tb>>>(Wkv, WkvH, UU, 2*UU);
    // 3) positional embedding
    {
        long long tot = (long long)KLEN * UU;
        pos_embed<<<(unsigned)((tot + 255) / 256), 256>>>(relh);
    }
    // 4) kv projection (fp16 single-pass)  <-- ncu capture target
    hgemm<128,5><<<dim3(M_FULL/128, 2*UU/128, 1), 256, SMEM1(128)>>>(
        fullh, WkvH, nullptr, kv, nullptr, bkv, nullptr, nullptr,
        M_FULL, 2*UU, UU, UU, UU, 2*UU, 1, 0,0,0,0,0,0, -1,-1,-1);
    // remaining weight conversions
    split_T_h<<<dim3(UU/32,  UU/32),  tb>>>(Wq,   WqH,   UU,  UU);
    split_T_h<<<dim3(UU/32,  UU/32),  tb>>>(Wr,   WrH,   UU,  UU);
    split_T_h<<<dim3(UU/32,  UU/32),  tb>>>(Wo,   WoH,   UU,  UU);
    split_T_h<<<dim3(FFD/32, UU/32),  tb>>>(W1,   W1H,   UU,  FFD);
    split_T_h<<<dim3(UU/32,  FFD/32), tb>>>(W2,   W2H,   FFD, UU);
    split_T_h<<<dim3(NT/32,  UU/32),  tb>>>(Wout, WoutH, UU,  NT);
    // q projection fused with (q+u)/(q+v) single-fp16 outputs
    hgemm<128,4><<<dim3(M_TOK/128, UU/128, 1), 256, SMEM1(128)>>>(
        xh, WqH, nullptr, qc, qr, bq, bias_c, bias_r,
        M_TOK, UU, UU, UU, UU, UU, 1, 0,0,0,0,0,0, -1,-1,-1);
    // r projection (single fp16 out)
    hgemm<128,5><<<dim3((KLEN+127)/128, UU/128, 1), 256, SMEM1(128)>>>(
        relh, WrH, nullptr, r, nullptr, br, nullptr, nullptr,
        KLEN, UU, UU, UU, UU, UU, 1, 0,0,0,0,0,0, -1,-1,-1);
    // scores (fp16 single-pass, batched over b,h), dead-tile skips
    {
        dim3 grid(SS / 128, (KLEN + 127) / 128, BB * HH);
        hgemm<128,0><<<grid, 256, SMEM1(128)>>>(
            qc, kv, ac, nullptr, nullptr, nullptr, nullptr, nullptr,
            SS, KLEN, DD, UU, 2*UU, KLEN, HH,
            (long long)SS*UU, 64,
            (long long)KLEN*2*UU, 64,
            (long long)HH*SS*KLEN, (long long)SS*KLEN,
            MEMLEN + 127, -1, -1);
        hgemm<128,0><<<grid, 256, SMEM1(128)>>>(
            qr, r, ar, nullptr, nullptr, nullptr, nullptr, nullptr,
            SS, KLEN, DD, UU, UU, KLEN, HH,
            (long long)SS*UU, 64,
            0, 64,
            (long long)HH*SS*KLEN, (long long)SS*KLEN,
            -1, SS - 255, -1);
    }
    // fused rel-shift + mask + softmax -> single-fp16 P
    {
        dim3 grid(SS, BB * HH);
        attn_softmax<<<grid, 256>>>(ac, ar, p);
    }
    // V^T per head (single fp16)
    {
        dim3 grid(KLEN / 32, DD / 32, BB * HH);
        transpose_v<<<grid, tb>>>(kv, vt);
    }
    // ctx = P @ V^T (fp16 single-pass, K clamp), single fp16 output
    {
        dim3 grid(SS / 128, 1, BB * HH);
        hgemm<64,5><<<grid, 256, SMEM1(64)>>>(
            p, vt, nullptr, ctx, nullptr, nullptr, nullptr, nullptr,
            SS, DD, KLEN, KLEN, KLEN, UU, HH,
            (long long)HH*SS*KLEN, (long long)SS*KLEN,
            (long long)HH*DD*KLEN, (long long)DD*KLEN,
            (long long)SS*UU, 64,
            -1, -1, MEMLEN + 128);
    }
    // attention out projection + LN1
    hgemm<128,0><<<dim3(M_TOK/128, UU/128, 1), 256, SMEM1(128)>>>(
        ctx, WoH, tmp, nullptr, nullptr, bo, nullptr, nullptr,
        M_TOK, UU, UU, UU, UU, UU, 1, 0,0,0,0,0,0, -1,-1,-1);
    add_ln<<<M_TOK, 256>>>(x, tmp, ln1_g, ln1_b, h1, h1h);
    // FF (fp16 single-pass)
    hgemm<128,6><<<dim3(M_TOK/128, FFD/128, 1), 256, SMEM1(128)>>>(
        h1h, W1H, nullptr, ffh, nullptr, b1, nullptr, nullptr,
        M_TOK, FFD, UU, UU, UU, FFD, 1, 0,0,0,0,0,0, -1,-1,-1);
    hgemm<128,0><<<dim3(M_TOK/128, UU/128, 1), 256, SMEM1(128)>>>(
        ffh, W2H, tmp, nullptr, nullptr, b2, nullptr, nullptr,
        M_TOK, UU, FFD, FFD, FFD, UU, 1, 0,0,0,0,0,0, -1,-1,-1);
    add_ln<<<M_TOK, 256>>>(h1, tmp, ln2_g, ln2_b, nullptr, h2h);
    // logits (fp16 single-pass) + softmax
    hgemm<128,0><<<dim3(M_TOK/128, NT/128, 1), 256, SMEM1(128)>>>(
        h2h, WoutH, out, nullptr, nullptr, bout, nullptr, nullptr,
        M_TOK, NT, UU, UU, UU, NT, 1, 0,0,0,0,0,0, -1,-1,-1);
    softmax_rows<<<M_TOK, 512>>>(out, NT);
}

// round 17
// speedup vs baseline: 2.1300x; 1.0292x over previous
#include <cuda_runtime.h>
#include <cuda_bf16.h>
#include <cuda_fp16.h>
#include <math.h>
#include <stdint.h>

// ---------------- problem constants ----------------
#define BB 2
#define SS 1024
#define UU 1024
#define HH 16
#define DD 64
#define NT 32000
#define MEMLEN 576
#define FFD 4096
#define KLEN 1600   // MEM + S
#define VOCAB 1024

// ---------------- scratch (device globals; no allocation allowed) ----------------
__device__ float g_x   [(size_t)BB*SS*UU];
__device__ float g_tmp [(size_t)BB*SS*UU];
__device__ float g_h1  [(size_t)BB*SS*UU];

// fp16 score / logits buffers
__device__ __half g_ac  [(size_t)BB*HH*SS*KLEN];
__device__ __half g_ar  [(size_t)BB*HH*SS*KLEN];
__device__ __half g_lg  [(size_t)BB*SS*NT];

// single fp16 activations
__device__ __half g_xh   [(size_t)BB*SS*UU];
__device__ __half g_fullh[(size_t)BB*KLEN*UU];
__device__ __half g_relh [(size_t)KLEN*UU];
__device__ __half g_ctx  [(size_t)BB*SS*UU];
__device__ __half g_h1h  [(size_t)BB*SS*UU];
__device__ __half g_ffh  [(size_t)BB*SS*FFD];
__device__ __half g_h2h  [(size_t)BB*SS*UU];
__device__ __half g_qc   [(size_t)BB*SS*UU];
__device__ __half g_qr   [(size_t)BB*SS*UU];
__device__ __half g_kv   [(size_t)BB*KLEN*2*UU];
__device__ __half g_r    [(size_t)KLEN*UU];
__device__ __half g_p    [(size_t)BB*HH*SS*KLEN];
__device__ __half g_vt   [(size_t)BB*HH*DD*KLEN];
// single-fp16 transposed weights [N,K]
__device__ __half g_WqH [(size_t)UU*UU];
__device__ __half g_WkvH[(size_t)2*UU*UU];
__device__ __half g_WrH [(size_t)UU*UU];
__device__ __half g_WoH [(size_t)UU*UU];
__device__ __half g_W1H [(size_t)FFD*UU];
__device__ __half g_W2H [(size_t)UU*FFD];
__device__ __half g_WoutH[(size_t)NT*UU];

// ---------------- helpers ----------------
__device__ __forceinline__ uint32_t smem_u32(const void* p) {
    uint32_t a;
    asm("{ .reg .u64 t; cvta.to.shared.u64 t, %1; cvt.u32.u64 %0, t; }" : "=r"(a) : "l"(p));
    return a;
}
__device__ __forceinline__ uint32_t pack2h(__half a, __half b) {
    unsigned short x = *(unsigned short*)&a, y = *(unsigned short*)&b;
    return (uint32_t)x | ((uint32_t)y << 16);
}
__device__ __forceinline__ void cp16(uint32_t dst, const void* src) {
    asm volatile("cp.async.cg.shared.global [%0], [%1], 16;" :: "r"(dst), "l"(src));
}
__device__ __forceinline__ void ldx4(uint32_t* r, uint32_t addr) {
    asm volatile("ldmatrix.sync.aligned.m8n8.x4.shared.b16 {%0,%1,%2,%3}, [%4];"
                 : "=r"(r[0]), "=r"(r[1]), "=r"(r[2]), "=r"(r[3]) : "r"(addr));
}
__device__ __forceinline__ void mma_fp(float* c, const uint32_t* a, const uint32_t* b) {
    asm volatile("mma.sync.aligned.m16n8k16.row.col.f32.f16.f16.f32 "
                 "{%0,%1,%2,%3}, {%4,%5,%6,%7}, {%8,%9}, {%0,%1,%2,%3};"
                 : "+f"(c[0]), "+f"(c[1]), "+f"(c[2]), "+f"(c[3])
                 : "r"(a[0]), "r"(a[1]), "r"(a[2]), "r"(a[3]), "r"(b[0]), "r"(b[1]));
}

// epilogue writer
// OUT: 0 fp32 C (+bias); 4 dual-bias single (Ch=v+b2, Dh=v+b3); 5 single fp16 (+bias);
//      6 relu + single fp16 (+bias).
template<int OUT>
__device__ __forceinline__ void epi_store(
    float v0, float v1, float v2, float v3,
    int gm0, int gn, int M, int ldc, long long cbase,
    float* C, __half* Ch, __half* Dh,
    const float* bias2, const float* bias3)
{
    if (OUT == 0) {
        if (gm0 < M) {
            float2 w; w.x = v0; w.y = v1;
            *(float2*)(C + cbase + (long long)gm0 * ldc + gn) = w;
        }
        if (gm0 + 8 < M) {
            float2 w; w.x = v2; w.y = v3;
            *(float2*)(C + cbase + (long long)(gm0 + 8) * ldc + gn) = w;
        }
    } else if (OUT == 4) {
        float2 b2 = *(const float2*)(bias2 + gn);
        float2 b3 = *(const float2*)(bias3 + gn);
        if (gm0 < M) {
            long long o = cbase + (long long)gm0 * ldc + gn;
            *(uint32_t*)(Ch + o) = pack2h(__float2half(v0 + b2.x), __float2half(v1 + b2.y));
            *(uint32_t*)(Dh + o) = pack2h(__float2half(v0 + b3.x), __float2half(v1 + b3.y));
        }
        if (gm0 + 8 < M) {
            long long o = cbase + (long long)(gm0 + 8) * ldc + gn;
            *(uint32_t*)(Ch + o) = pack2h(__float2half(v2 + b2.x), __float2half(v3 + b2.y));
            *(uint32_t*)(Dh + o) = pack2h(__float2half(v2 + b3.x), __float2half(v3 + b3.y));
        }
    } else {
        if (OUT == 6) {
            v0 = fmaxf(v0, 0.f); v1 = fmaxf(v1, 0.f);
            v2 = fmaxf(v2, 0.f); v3 = fmaxf(v3, 0.f);
        }
        if (gm0 < M) {
            long long o = cbase + (long long)gm0 * ldc + gn;
            *(uint32_t*)(Ch + o) = pack2h(__float2half(v0), __float2half(v1));
        }
        if (gm0 + 8 < M) {
            long long o = cbase + (long long)(gm0 + 8) * ldc + gn;
            *(uint32_t*)(Ch + o) = pack2h(__float2half(v2), __float2half(v3));
        }
    }
}

// ---------------- single-pass fp16 HMMA GEMM (R8 mainloop) ----------------
// C[M,N] = A[M,K] @ B[N,K]^T (+bias), fp32 accum, fp16 operands.
// 4-stage cp.async pipeline, ONE barrier per K16 chunk.
// maskA/maskB: dead-tile skips. kclamp: effective K = min(K, m0+kclamp).
template<int BN, int OUT>
__global__ __launch_bounds__(256)
void hgemm(const __half* __restrict__ A, const __half* __restrict__ B,
           float* __restrict__ C, __half* __restrict__ Ch, __half* __restrict__ Dh,
           const float* __restrict__ bias,
           const float* __restrict__ bias2, const float* __restrict__ bias3,
           int M, int N, int K, int lda, int ldb, int ldc, int Z2,
           long long sA1, long long sA2, long long sB1, long long sB2,
           long long sC1, long long sC2,
           int maskA, int maskB, int kclamp)
{
    constexpr int BSTR = BN * 32;
    constexpr int STAGE = 4096 + BSTR;
    constexpr int MT = (BN == 128) ? 4 : 2;
    extern __shared__ __align__(128) char sm[];
    const uint32_t smb = smem_u32(sm);
    const int tid = threadIdx.x, wid = tid >> 5, lane = tid & 31;
    const int m0 = blockIdx.x * 128, n0 = blockIdx.y * BN;
    if (maskA >= 0 && n0 > m0 + maskA) return;
    if (maskB >= 0 && m0 + n0 < maskB) return;
    const int Keff = (kclamp >= 0) ? min(K, m0 + kclamp) : K;

    const int m_w = (BN == 128) ? (wid & 1) * 64 : (wid & 3) * 32;
    const int n_w = (BN == 128) ? (wid >> 1) * 32 : (wid >> 2) * 32;

    const int z = blockIdx.z;
    const int z1 = z / Z2, z2 = z - z1 * Z2;
    A += z1 * sA1 + z2 * sA2;
    B += z1 * sB1 + z2 * sB2;
    const long long cbase = z1 * sC1 + z2 * sC2;

    const int lr = tid >> 1, lc = tid & 1;
    const uint32_t so = (uint32_t)(lr * 32 + ((lc ^ ((lr >> 2) & 1)) << 4));
    const int ga = min(m0 + lr, M - 1);
    const long long aoff = (long long)ga * lda + lc * 8;
    const bool bdo = (BN == 128) || (tid < 128);
    const int gb = min(n0 + lr, N - 1);
    const long long boff = (long long)gb * ldb + lc * 8;

    float acc[MT][4][4];
    #pragma unroll
    for (int i = 0; i < MT; i++)
        #pragma unroll
        for (int j = 0; j < 4; j++)
            #pragma unroll
            for (int k = 0; k < 4; k++) acc[i][j][k] = 0.f;

    const int NC = Keff / 16;

    // prologue: stages 0,1,2
    #pragma unroll
    for (int pc = 0; pc < 3; pc++) {
        const uint32_t st = smb + pc * STAGE;
        cp16(st + so, A + aoff + pc * 16);
        if (bdo) cp16(st + 4096 + so, B + boff + pc * 16);
        asm volatile("cp.async.commit_group;");
    }

    const int rr = lane & 15, ccq = lane >> 4;
    const int rbq = (lane & 7) | ((lane & 16) >> 1);
    const int cbq = (lane >> 3) & 1;

    for (int c = 0; c < NC; c++) {
        asm volatile("cp.async.wait_group 2;");
        __syncthreads();
        if (c + 3 < NC) {
            const uint32_t st = smb + ((c + 3) & 3) * STAGE;
            const long long k0 = (long long)(c + 3) * 16;
            cp16(st + so, A + aoff + k0);
            if (bdo) cp16(st + 4096 + so, B + boff + k0);
        }
        asm volatile("cp.async.commit_group;");

        const uint32_t st = smb + (c & 3) * STAGE;
        uint32_t ah[MT][4], bh[2][4];
        #pragma unroll
        for (int mt = 0; mt < MT; mt++) {
            int R = m_w + mt * 16 + rr;
            uint32_t ad = st + R * 32 + ((ccq ^ ((R >> 2) & 1)) << 4);
            ldx4(ah[mt], ad);
        }
        #pragma unroll
        for (int np = 0; np < 2; np++) {
            int Nr = n_w + np * 16 + rbq;
            uint32_t bd = st + 4096 + Nr * 32 + ((cbq ^ ((Nr >> 2) & 1)) << 4);
            ldx4(bh[np], bd);
        }
        #pragma unroll
        for (int mt = 0; mt < MT; mt++)
            #pragma unroll
            for (int nt = 0; nt < 4; nt++)
                mma_fp(acc[mt][nt], ah[mt], &bh[nt >> 1][(nt & 1) * 2]);
    }

    // ---- epilogue ----
    #pragma unroll
    for (int mt = 0; mt < MT; mt++) {
        int gm0 = m0 + m_w + mt * 16 + (lane >> 2);
        #pragma unroll
        for (int nt = 0; nt < 4; nt++) {
            int gn = n0 + n_w + nt * 8 + (lane & 3) * 2;
            if (gn >= N) continue;
            float bx = 0.f, by = 0.f;
            if (bias) { float2 bv = *(const float2*)(bias + gn); bx = bv.x; by = bv.y; }
            epi_store<OUT>(acc[mt][nt][0] + bx, acc[mt][nt][1] + by,
                           acc[mt][nt][2] + bx, acc[mt][nt][3] + by,
                           gm0, gn, M, ldc, cbase, C, Ch, Dh, bias2, bias3);
        }
    }
}

// ---------------- reductions ----------------
__device__ __forceinline__ float block_reduce_sum(float v) {
    __shared__ float sm[16];
    __syncthreads();
    #pragma unroll
    for (int o = 16; o > 0; o >>= 1) v += __shfl_xor_sync(0xffffffffu, v, o);
    if ((threadIdx.x & 31) == 0) sm[threadIdx.x >> 5] = v;
    __syncthreads();
    if (threadIdx.x < 32) {
        float x = (threadIdx.x < (blockDim.x >> 5)) ? sm[threadIdx.x] : 0.f;
        #pragma unroll
        for (int o = 8; o > 0; o >>= 1) x += __shfl_xor_sync(0xffffffffu, x, o);
        if (threadIdx.x == 0) sm[0] = x;
    }
    __syncthreads();
    return sm[0];
}
__device__ __forceinline__ float block_reduce_max(float v) {
    __shared__ float sm[16];
    __syncthreads();
    #pragma unroll
    for (int o = 16; o > 0; o >>= 1) v = fmaxf(v, __shfl_xor_sync(0xffffffffu, v, o));
    if ((threadIdx.x & 31) == 0) sm[threadIdx.x >> 5] = v;
    __syncthreads();
    if (threadIdx.x < 32) {
        float x = (threadIdx.x < (blockDim.x >> 5)) ? sm[threadIdx.x] : -3.4e38f;
        #pragma unroll
        for (int o = 8; o > 0; o >>= 1) x = fmaxf(x, __shfl_xor_sync(0xffffffffu, x, o));
        if (threadIdx.x == 0) sm[0] = x;
    }
    __syncthreads();
    return sm[0];
}

// ---------------- small kernels ----------------
__global__ void build_full(const int* __restrict__ tokens,
                           const float* __restrict__ memory,
                           const float* __restrict__ embed,
                           float* __restrict__ x,
                           __half* __restrict__ xh, __half* __restrict__ fullh)
{
    long long idx = (long long)blockIdx.x * 256 + threadIdx.x;
    const long long tot = (long long)BB * KLEN * UU;
    if (idx >= tot) return;
    int u = (int)(idx % UU);
    long long t = idx / UU;
    int j = (int)(t % KLEN);
    int b = (int)(t / KLEN);
    float v;
    if (j < MEMLEN) {
        v = memory[((long long)b * MEMLEN + j) * UU + u];
    } else {
        int s = j - MEMLEN;
        int tok = tokens[b * SS + s];
        v = embed[(long long)tok * UU + u] * 32.0f;  // sqrt(1024)
        long long xo = ((long long)b * SS + s) * UU + u;
        x[xo] = v;
        xh[xo] = __float2half(v);
    }
    fullh[idx] = __float2half(v);
}

__global__ void pos_embed(__half* __restrict__ relh)
{
    long long idx = (long long)blockIdx.x * 256 + threadIdx.x;
    if (idx >= (long long)KLEN * UU) return;
    int u = (int)(idx % UU);
    int jj = (int)(idx / UU);
    float pos = (float)(KLEN - 1 - jj);
    int i2 = (u < UU / 2) ? u : (u - UU / 2);
    float expo = ((float)(2 * i2)) / (float)UU;
    float invf = expf(-expo * 9.210340371976184f);  // ln(10000)
    float ang = pos * invf;
    relh[idx] = __float2half((u < UU / 2) ? sinf(ang) : cosf(ang));
}

// transpose: W[K,N] fp32 -> single fp16 [N,K]
__global__ void split_T_h(const float* __restrict__ W, __half* __restrict__ hi,
                          int K, int N)
{
    __shared__ float t[32][33];
    int n0 = blockIdx.x * 32, k0 = blockIdx.y * 32;
    #pragma unroll
    for (int i = 0; i < 32; i += 8)
        t[threadIdx.y + i][threadIdx.x] =
            W[(long long)(k0 + threadIdx.y + i) * N + n0 + threadIdx.x];
    __syncthreads();
    #pragma unroll
    for (int i = 0; i < 32; i += 8) {
        float v = t[threadIdx.x][threadIdx.y + i];
        long long o = (long long)(n0 + threadIdx.y + i) * K + k0 + threadIdx.x;
        hi[o] = __float2half(v);
    }
}

// V^T per head (single fp16): vt[(b*H+h), d, j] = kv[b, j, U + h*64 + d]
__global__ void transpose_v(const __half* __restrict__ kv, __half* __restrict__ vt)
{
    __shared__ __half th[32][33];
    int z = blockIdx.z;
    int b = z / HH, h = z % HH;
    int j0 = blockIdx.x * 32, d0 = blockIdx.y * 32;
    int tx = threadIdx.x, ty = threadIdx.y;
    #pragma unroll
    for (int i = 0; i < 32; i += 8) {
        long long src = ((long long)b * KLEN + j0 + ty + i) * (2 * UU) + UU + h * 64 + d0 + tx;
        th[ty + i][tx] = kv[src];
    }
    __syncthreads();
    #pragma unroll
    for (int i = 0; i < 32; i += 8) {
        long long dst = ((long long)z * DD + d0 + ty + i) * KLEN + j0 + tx;
        vt[dst] = th[tx][ty + i];
    }
}

// mask + rel-shift + softmax over fp16 scores; writes P as single fp16 (zero tail)
__global__ __launch_bounds__(256)
void attn_softmax(const __half* __restrict__ ac, const __half* __restrict__ ar,
                  __half* __restrict__ p)
{
    int i = blockIdx.x;
    long long z = blockIdx.y;
    const __half* arow = ac + (z * SS + i) * (long long)KLEN;
    const __half* rrow = ar + (z * SS + i) * (long long)KLEN;
    __half* pr = p + (z * SS + i) * (long long)KLEN;
    int lim = i + MEMLEN;
    int shift = SS - 1 - i;
    int tid = threadIdx.x;

    float vals[7];
    int cnt = 0;
    float lmax = -3.4e38f;
    for (int j = tid; j <= lim; j += 256) {
        float v = (__half2float(arow[j]) + __half2float(rrow[j + shift])) * 0.125f;
        vals[cnt++] = v;
        lmax = fmaxf(lmax, v);
    }
    float m = block_reduce_max(lmax);
    float lsum = 0.f;
    for (int t = 0; t < cnt; t++) {
        float e = expf(vals[t] - m);
        vals[t] = e;
        lsum += e;
    }
    float s = block_reduce_sum(lsum);
    float inv = 1.f / s;
    cnt = 0;
    for (int j = tid; j <= lim; j += 256) {
        pr[j] = __float2half(vals[cnt++] * inv);
    }
    __half z0 = __float2half(0.f);
    for (int j = lim + 1 + tid; j < KLEN; j += 256) pr[j] = z0;
}

// add + LayerNorm; emits fp32 (optional) plus single fp16
__global__ __launch_bounds__(256)
void add_ln(const float* __restrict__ a, const float* __restrict__ b,
            const float* __restrict__ g, const float* __restrict__ beta,
            float* __restrict__ out, __half* __restrict__ oh)
{
    long long row = blockIdx.x;
    const float* pa = a + row * UU;
    const float* pb = b + row * UU;
    int tid = threadIdx.x;
    float vals[4];
    float s = 0.f, ss = 0.f;
    #pragma unroll
    for (int t = 0; t < 4; t++) {
        int idx = tid * 4 + t;
        float v = pa[idx] + pb[idx];
        vals[t] = v;
        s += v;
        ss += v * v;
    }
    s = block_reduce_sum(s);
    ss = block_reduce_sum(ss);
    float mean = s * (1.f / UU);
    float var = fmaxf(ss * (1.f / UU) - mean * mean, 0.f);
    float rstd = rsqrtf(var + 1e-5f);
    #pragma unroll
    for (int t = 0; t < 4; t++) {
        int idx = tid * 4 + t;
        float v = (vals[t] - mean) * rstd * g[idx] + beta[idx];
        if (out) out[row * UU + idx] = v;
        oh[row * UU + idx] = __float2half(v);
    }
}

// online-softmax over fp16 logit rows -> fp32 probs
__global__ __launch_bounds__(512)
void softmax_rows_h(const __half* __restrict__ lg, float* __restrict__ out, int N)
{
    __shared__ float smm[16], sms[16];
    long long row = blockIdx.x;
    const __half* p = lg + row * (long long)N;
    float* q = out + row * (long long)N;
    int tid = threadIdx.x;
    float m = -3.4e38f, s = 0.f;
    for (int j = tid; j < N; j += 512) {
        float v = __half2float(p[j]);
        if (v > m) { s = s * expf(m - v) + 1.f; m = v; }
        else       { s += expf(v - m); }
    }
    #pragma unroll
    for (int o = 16; o > 0; o >>= 1) {
        float m2 = __shfl_xor_sync(0xffffffffu, m, o);
        float s2 = __shfl_xor_sync(0xffffffffu, s, o);
        float M = fmaxf(m, m2);
        s = s * expf(m - M) + s2 * expf(m2 - M);
        m = M;
    }
    if ((tid & 31) == 0) { smm[tid >> 5] = m; sms[tid >> 5] = s; }
    __syncthreads();
    if (tid < 32) {
        float mm = (tid < 16) ? smm[tid] : -3.4e38f;
        float ssv = (tid < 16) ? sms[tid] : 0.f;
        #pragma unroll
        for (int o = 8; o > 0; o >>= 1) {
            float m2 = __shfl_xor_sync(0xffffffffu, mm, o);
            float s2 = __shfl_xor_sync(0xffffffffu, ssv, o);
            float M = fmaxf(mm, m2);
            ssv = ssv * expf(mm - M) + s2 * expf(m2 - M);
            mm = M;
        }
        if (tid == 0) { smm[0] = mm; sms[0] = ssv; }
    }
    __syncthreads();
    float M = smm[0];
    float inv = 1.f / sms[0];
    for (int j = tid; j < N; j += 512)
        q[j] = expf(__half2float(p[j]) - M) * inv;
}

// ---------------- host ----------------
#define SMEM1(BN) (4 * (4096 + (BN) * 32))

extern "C" void kernel_launch(void* const* d_in, const int* in_sizes, int n_in,
                              void* d_out, int out_size)
{
    const int*   tokens  = (const int*)  d_in[0];
    const float* memory  = (const float*)d_in[1];
    const float* embed   = (const float*)d_in[2];
    const float* Wq      = (const float*)d_in[3];
    const float* Wkv     = (const float*)d_in[4];
    const float* Wr      = (const float*)d_in[5];
    const float* Wo      = (const float*)d_in[6];
    const float* bq      = (const float*)d_in[7];
    const float* bkv     = (const float*)d_in[8];
    const float* br      = (const float*)d_in[9];
    const float* bo      = (const float*)d_in[10];
    const float* bias_c  = (const float*)d_in[11];
    const float* bias_r  = (const float*)d_in[12];
    const float* ln1_g   = (const float*)d_in[13];
    const float* ln1_b   = (const float*)d_in[14];
    const float* W1      = (const float*)d_in[15];
    const float* b1      = (const float*)d_in[16];
    const float* W2      = (const float*)d_in[17];
    const float* b2      = (const float*)d_in[18];
    const float* ln2_g   = (const float*)d_in[19];
    const float* ln2_b   = (const float*)d_in[20];
    const float* Wout    = (const float*)d_in[21];
    const float* bout    = (const float*)d_in[22];
    float* out = (float*)d_out;

    static bool s_attr = false;
    if (!s_attr) {
        cudaFuncSetAttribute(hgemm<128,0>, cudaFuncAttributeMaxDynamicSharedMemorySize, SMEM1(128));
        cudaFuncSetAttribute(hgemm<128,4>, cudaFuncAttributeMaxDynamicSharedMemorySize, SMEM1(128));
        cudaFuncSetAttribute(hgemm<128,5>, cudaFuncAttributeMaxDynamicSharedMemorySize, SMEM1(128));
        cudaFuncSetAttribute(hgemm<128,6>, cudaFuncAttributeMaxDynamicSharedMemorySize, SMEM1(128));
        cudaFuncSetAttribute(hgemm<64,5>,  cudaFuncAttributeMaxDynamicSharedMemorySize, SMEM1(64));
        s_attr = true;
    }

    float *x, *tmp, *h1;
    cudaGetSymbolAddress((void**)&x,   g_x);
    cudaGetSymbolAddress((void**)&tmp, g_tmp);
    cudaGetSymbolAddress((void**)&h1,  g_h1);

    __half *ac,*ar,*lg;
    __half *xh,*fullh,*relh,*ctx,*h1h,*ffh,*h2h,*qc,*qr,*kv,*r,*p,*vt;
    __half *WqH,*WkvH,*WrH,*WoH,*W1H,*W2H,*WoutH;
    cudaGetSymbolAddress((void**)&ac, g_ac);
    cudaGetSymbolAddress((void**)&ar, g_ar);
    cudaGetSymbolAddress((void**)&lg, g_lg);
    cudaGetSymbolAddress((void**)&xh, g_xh);
    cudaGetSymbolAddress((void**)&fullh, g_fullh);
    cudaGetSymbolAddress((void**)&relh, g_relh);
    cudaGetSymbolAddress((void**)&ctx, g_ctx);
    cudaGetSymbolAddress((void**)&h1h, g_h1h);
    cudaGetSymbolAddress((void**)&ffh, g_ffh);
    cudaGetSymbolAddress((void**)&h2h, g_h2h);
    cudaGetSymbolAddress((void**)&qc, g_qc);       cudaGetSymbolAddress((void**)&qr, g_qr);
    cudaGetSymbolAddress((void**)&kv, g_kv);       cudaGetSymbolAddress((void**)&r, g_r);
    cudaGetSymbolAddress((void**)&p, g_p);         cudaGetSymbolAddress((void**)&vt, g_vt);
    cudaGetSymbolAddress((void**)&WqH, g_WqH);     cudaGetSymbolAddress((void**)&WkvH, g_WkvH);
    cudaGetSymbolAddress((void**)&WrH, g_WrH);     cudaGetSymbolAddress((void**)&WoH, g_WoH);
    cudaGetSymbolAddress((void**)&W1H, g_W1H);     cudaGetSymbolAddress((void**)&W2H, g_W2H);
    cudaGetSymbolAddress((void**)&WoutH, g_WoutH);

    const int M_TOK = BB * SS;      // 2048
    const int M_FULL = BB * KLEN;   // 3200
    dim3 tb(32, 8);

    // 1) embedding + concat + fp16
    {
        long long tot = (long long)BB * KLEN * UU;
        build_full<<<(unsigned)((tot + 255) / 256), 256>>>(tokens, memory, embed,
                                                           x, xh, fullh);
    }
    // 2) Wkv -> fp16
    split_T_h<<<dim3(2*UU/32, UU/32), tb>>>(Wkv, WkvH, UU, 2*UU);
    // 3) positional embedding
    {
        long long tot = (long long)KLEN * UU;
        pos_embed<<<(unsigned)((tot + 255) / 256), 256>>>(relh);
    }
    // 4) kv projection (fp16 single-pass)  <-- ncu capture target
    hgemm<128,5><<<dim3(M_FULL/128, 2*UU/128, 1), 256, SMEM1(128)>>>(
        fullh, WkvH, nullptr, kv, nullptr, bkv, nullptr, nullptr,
        M_FULL, 2*UU, UU, UU, UU, 2*UU, 1, 0,0,0,0,0,0, -1,-1,-1);
    // remaining weight conversions
    split_T_h<<<dim3(UU/32,  UU/32),  tb>>>(Wq,   WqH,   UU,  UU);
    split_T_h<<<dim3(UU/32,  UU/32),  tb>>>(Wr,   WrH,   UU,  UU);
    split_T_h<<<dim3(UU/32,  UU/32),  tb>>>(Wo,   WoH,   UU,  UU);
    split_T_h<<<dim3(FFD/32, UU/32),  tb>>>(W1,   W1H,   UU,  FFD);
    split_T_h<<<dim3(UU/32,  FFD/32), tb>>>(W2,   W2H,   FFD, UU);
    split_T_h<<<dim3(NT/32,  UU/32),  tb>>>(Wout, WoutH, UU,  NT);
    // q projection fused with (q+u)/(q+v) single-fp16 outputs
    hgemm<128,4><<<dim3(M_TOK/128, UU/128, 1), 256, SMEM1(128)>>>(
        xh, WqH, nullptr, qc, qr, bq, bias_c, bias_r,
        M_TOK, UU, UU, UU, UU, UU, 1, 0,0,0,0,0,0, -1,-1,-1);
    // r projection (single fp16 out)
    hgemm<128,5><<<dim3((KLEN+127)/128, UU/128, 1), 256, SMEM1(128)>>>(
        relh, WrH, nullptr, r, nullptr, br, nullptr, nullptr,
        KLEN, UU, UU, UU, UU, UU, 1, 0,0,0,0,0,0, -1,-1,-1);
    // scores (fp16 single-pass, fp16 outputs, batched over b,h), dead-tile skips
    {
        dim3 grid(SS / 128, (KLEN + 127) / 128, BB * HH);
        hgemm<128,5><<<grid, 256, SMEM1(128)>>>(
            qc, kv, nullptr, ac, nullptr, nullptr, nullptr, nullptr,
            SS, KLEN, DD, UU, 2*UU, KLEN, HH,
            (long long)SS*UU, 64,
            (long long)KLEN*2*UU, 64,
            (long long)HH*SS*KLEN, (long long)SS*KLEN,
            MEMLEN + 127, -1, -1);
        hgemm<128,5><<<grid, 256, SMEM1(128)>>>(
            qr, r, nullptr, ar, nullptr, nullptr, nullptr, nullptr,
            SS, KLEN, DD, UU, UU, KLEN, HH,
            (long long)SS*UU, 64,
            0, 64,
            (long long)HH*SS*KLEN, (long long)SS*KLEN,
            -1, SS - 255, -1);
    }
    // fused rel-shift + mask + softmax -> single-fp16 P
    {
        dim3 grid(SS, BB * HH);
        attn_softmax<<<grid, 256>>>(ac, ar, p);
    }
    // V^T per head (single fp16)
    {
        dim3 grid(KLEN / 32, DD / 32, BB * HH);
        transpose_v<<<grid, tb>>>(kv, vt);
    }
    // ctx = P @ V^T (fp16 single-pass, K clamp), single fp16 output
    {
        dim3 grid(SS / 128, 1, BB * HH);
        hgemm<64,5><<<grid, 256, SMEM1(64)>>>(
            p, vt, nullptr, ctx, nullptr, nullptr, nullptr, nullptr,
            SS, DD, KLEN, KLEN, KLEN, UU, HH,
            (long long)HH*SS*KLEN, (long long)SS*KLEN,
            (long long)HH*DD*KLEN, (long long)DD*KLEN,
            (long long)SS*UU, 64,
            -1, -1, MEMLEN + 128);
    }
    // attention out projection + LN1
    hgemm<128,0><<<dim3(M_TOK/128, UU/128, 1), 256, SMEM1(128)>>>(
        ctx, WoH, tmp, nullptr, nullptr, bo, nullptr, nullptr,
        M_TOK, UU, UU, UU, UU, UU, 1, 0,0,0,0,0,0, -1,-1,-1);
    add_ln<<<M_TOK, 256>>>(x, tmp, ln1_g, ln1_b, h1, h1h);
    // FF (fp16 single-pass)
    hgemm<128,6><<<dim3(M_TOK/128, FFD/128, 1), 256, SMEM1(128)>>>(
        h1h, W1H, nullptr, ffh, nullptr, b1, nullptr, nullptr,
        M_TOK, FFD, UU, UU, UU, FFD, 1, 0,0,0,0,0,0, -1,-1,-1);
    hgemm<128,0><<<dim3(M_TOK/128, UU/128, 1), 256, SMEM1(128)>>>(
        ffh, W2H, tmp, nullptr, nullptr, b2, nullptr, nullptr,
        M_TOK, UU, FFD, FFD, FFD, UU, 1, 0,0,0,0,0,0, -1,-1,-1);
    add_ln<<<M_TOK, 256>>>(h1, tmp, ln2_g, ln2_b, nullptr, h2h);
    // logits (fp16 single-pass, fp16 output) + softmax -> fp32 probs
    hgemm<128,5><<<dim3(M_TOK/128, NT/128, 1), 256, SMEM1(128)>>>(
        h2h, WoutH, nullptr, lg, nullptr, bout, nullptr, nullptr,
        M_TOK, NT, UU, UU, UU, NT, 1, 0,0,0,0,0,0, -1,-1,-1);
    softmax_rows_h<<<M_TOK, 512>>>(lg, out, NT);
}